// round 5
// baseline (speedup 1.0000x reference)
#include <cuda_runtime.h>
#include <cuda_bf16.h>
#include <cstdint>

// ---------------------------------------------------------------------------
// GQA: B=2, T=2048, C=1024, H=16 q-heads, KVH=4 kv-heads, D=64, causal, RoPE
// All GEMM operands pre-split to bf16 hi/lo in gmem; bf16x3 MMA everywhere.
// ---------------------------------------------------------------------------

__device__ __align__(16) __nv_bfloat16 g_xh[4194304], g_xl[4194304];
__device__ __align__(16) __nv_bfloat16 g_wqkvh[1572864], g_wqkvl[1572864];
__device__ __align__(16) __nv_bfloat16 g_woh[1048576], g_wol[1048576];
__device__ __align__(16) __nv_bfloat16 g_qh[4194304], g_ql[4194304];
__device__ __align__(16) __nv_bfloat16 g_kh[1048576], g_kl[1048576];
__device__ __align__(16) __nv_bfloat16 g_vh[1048576], g_vl[1048576];
__device__ __align__(16) __nv_bfloat16 g_yh[4194304], g_yl[4194304];

// ---------------------------------------------------------------------------
// helpers
// ---------------------------------------------------------------------------
__device__ __forceinline__ uint32_t smem_u32(const void* p) {
    return (uint32_t)__cvta_generic_to_shared(p);
}
__device__ __forceinline__ void ldmx4(uint32_t* r, uint32_t addr) {
    asm volatile("ldmatrix.sync.aligned.m8n8.x4.shared.b16 {%0,%1,%2,%3}, [%4];"
        : "=r"(r[0]), "=r"(r[1]), "=r"(r[2]), "=r"(r[3]) : "r"(addr));
}
__device__ __forceinline__ void ldmx4t(uint32_t* r, uint32_t addr) {
    asm volatile("ldmatrix.sync.aligned.m8n8.x4.trans.shared.b16 {%0,%1,%2,%3}, [%4];"
        : "=r"(r[0]), "=r"(r[1]), "=r"(r[2]), "=r"(r[3]) : "r"(addr));
}
__device__ __forceinline__ void mma_bf16(float* c, const uint32_t* a, const uint32_t* b) {
    asm volatile(
        "mma.sync.aligned.m16n8k16.row.col.f32.bf16.bf16.f32 "
        "{%0,%1,%2,%3}, {%4,%5,%6,%7}, {%8,%9}, {%0,%1,%2,%3};\n"
        : "+f"(c[0]), "+f"(c[1]), "+f"(c[2]), "+f"(c[3])
        : "r"(a[0]), "r"(a[1]), "r"(a[2]), "r"(a[3]), "r"(b[0]), "r"(b[1]));
}
__device__ __forceinline__ float ex2(float x) {
    float r;
    asm("ex2.approx.f32 %0, %1;" : "=f"(r) : "f"(x));
    return r;
}
__device__ __forceinline__ void pack_hl(float x, float y, uint32_t& h, uint32_t& l) {
    __nv_bfloat162 hb, lb;
    __nv_bfloat16 hx = __float2bfloat16(x);
    hb.x = hx; lb.x = __float2bfloat16(x - __bfloat162float(hx));
    __nv_bfloat16 hy = __float2bfloat16(y);
    hb.y = hy; lb.y = __float2bfloat16(y - __bfloat162float(hy));
    h = *(uint32_t*)&hb; l = *(uint32_t*)&lb;
}
__device__ __forceinline__ void store_hl(__nv_bfloat16* H, __nv_bfloat16* L,
                                         int idx, float a, float b) {
    uint32_t h, l; pack_hl(a, b, h, l);
    *(uint32_t*)(H + idx) = h;
    *(uint32_t*)(L + idx) = l;
}
__device__ __forceinline__ void cpa16(uint32_t dst, const void* src) {
    asm volatile("cp.async.cg.shared.global [%0], [%1], 16;\n" :: "r"(dst), "l"(src));
}

#define SOFTMAX_SCALE (0.125f * 1.44269504088896f)  // 1/sqrt(64) * log2(e)

// ---------------------------------------------------------------------------
// Conversion kernels: fp32 -> bf16 hi/lo (one-shot, memory-bound)
// ---------------------------------------------------------------------------
__global__ void cvt_x(const float* __restrict__ src) {
    int i = blockIdx.x * blockDim.x + threadIdx.x;        // < 1048576
    float4 v = ((const float4*)src)[i];
    uint32_t h0, l0, h1, l1;
    pack_hl(v.x, v.y, h0, l0);
    pack_hl(v.z, v.w, h1, l1);
    uint2 hv; hv.x = h0; hv.y = h1;
    uint2 lv; lv.x = l0; lv.y = l1;
    ((uint2*)g_xh)[i] = hv; ((uint2*)g_xl)[i] = lv;
}
__global__ void cvt_wo(const float* __restrict__ src) {
    int i = blockIdx.x * blockDim.x + threadIdx.x;        // < 262144
    float4 v = ((const float4*)src)[i];
    uint32_t h0, l0, h1, l1;
    pack_hl(v.x, v.y, h0, l0);
    pack_hl(v.z, v.w, h1, l1);
    uint2 hv; hv.x = h0; hv.y = h1;
    uint2 lv; lv.x = l0; lv.y = l1;
    ((uint2*)g_woh)[i] = hv; ((uint2*)g_wol)[i] = lv;
}
__global__ void cvt_qkvw(const float* __restrict__ Wq,
                         const float* __restrict__ Wk,
                         const float* __restrict__ Wv) {
    int i = blockIdx.x * blockDim.x + threadIdx.x;        // < 393216
    int k = i / 384;
    int n = (i % 384) * 4;
    float4 v;
    if (n < 1024)      v = *(const float4*)(Wq + k * 1024 + n);
    else if (n < 1280) v = *(const float4*)(Wk + k * 256 + n - 1024);
    else               v = *(const float4*)(Wv + k * 256 + n - 1280);
    uint32_t h0, l0, h1, l1;
    pack_hl(v.x, v.y, h0, l0);
    pack_hl(v.z, v.w, h1, l1);
    uint2 hv; hv.x = h0; hv.y = h1;
    uint2 lv; lv.x = l0; lv.y = l1;
    int o = k * 1536 + n;
    *(uint2*)(g_wqkvh + o) = hv; *(uint2*)(g_wqkvl + o) = lv;
}

// ---------------------------------------------------------------------------
// bf16x3 GEMM, pre-split operands, cp.async double-buffered.
// Tile 128x128, BK=32, 8 warps (4x2), 2x8 m16n8k16 frags per warp, x3 MMAs.
// smem buffer (halves): Ah[128*40] Al[128*40] Bh[32*136] Bl[32*136] = 18944
// -> 37888 B per stage, 2 stages = 75776 B dynamic.
// MODE 0: A=g_x, B=g_wqkv (ldn=1536); epilogue RoPE(+scale) -> g_{q,k,v}{h,l}
// MODE 1: A=g_y,  B=g_wo  (ldn=1024); epilogue fp32 -> Cout
// ---------------------------------------------------------------------------
template<int MODE>
__global__ void __launch_bounds__(256, 1) gemm_bf16(
    const float* __restrict__ cosb,
    const float* __restrict__ sinb,
    float* __restrict__ Cout)
{
    extern __shared__ __align__(16) __nv_bfloat16 sm[];
    const uint32_t sbase = smem_u32(sm);
    const int ldn = (MODE == 0) ? 1536 : 1024;

    const __nv_bfloat16* Ah = (MODE == 0) ? g_xh : g_yh;
    const __nv_bfloat16* Al = (MODE == 0) ? g_xl : g_yl;
    const __nv_bfloat16* Bh = (MODE == 0) ? g_wqkvh : g_woh;
    const __nv_bfloat16* Bl = (MODE == 0) ? g_wqkvl : g_wol;

    const int tid  = threadIdx.x;
    const int lane = tid & 31;
    const int warp = tid >> 5;
    const int wm   = warp >> 1;
    const int wn   = warp & 1;
    const int brow = blockIdx.y * 128;
    const int bcol = blockIdx.x * 128;
    const int t4   = lane & 3;

    float c[2][8][4];
    #pragma unroll
    for (int mt = 0; mt < 2; mt++)
        #pragma unroll
        for (int nt = 0; nt < 8; nt++)
            #pragma unroll
            for (int i = 0; i < 4; i++) c[mt][nt][i] = 0.f;

    auto stage = [&](int kb, int buf) {
        uint32_t base = sbase + (uint32_t)buf * 37888u;
        #pragma unroll
        for (int i = 0; i < 2; i++) {
            int u   = tid + i * 256;
            int ar  = u >> 2, ac8 = (u & 3) << 3;
            cpa16(base + (uint32_t)(ar * 40 + ac8) * 2u,
                  Ah + (brow + ar) * 1024 + kb + ac8);
            cpa16(base + (uint32_t)(5120 + ar * 40 + ac8) * 2u,
                  Al + (brow + ar) * 1024 + kb + ac8);
            int br2 = u >> 4, bc8 = (u & 15) << 3;
            cpa16(base + (uint32_t)(10240 + br2 * 136 + bc8) * 2u,
                  Bh + (kb + br2) * ldn + bcol + bc8);
            cpa16(base + (uint32_t)(14592 + br2 * 136 + bc8) * 2u,
                  Bl + (kb + br2) * ldn + bcol + bc8);
        }
        asm volatile("cp.async.commit_group;\n" ::: "memory");
    };

    stage(0, 0);

    for (int ki = 0; ki < 32; ki++) {
        int buf = ki & 1;
        if (ki + 1 < 32) {
            stage((ki + 1) * 32, buf ^ 1);
            asm volatile("cp.async.wait_group 1;\n" ::: "memory");
        } else {
            asm volatile("cp.async.wait_group 0;\n" ::: "memory");
        }
        __syncthreads();

        uint32_t bAh = sbase + (uint32_t)buf * 37888u;
        uint32_t bAl = bAh + 10240u;
        uint32_t bBh = bAh + 20480u;
        uint32_t bBl = bAh + 29184u;

        #pragma unroll
        for (int ks = 0; ks < 2; ks++) {
            uint32_t aH[2][4], aL[2][4], bH[4][4], bL[4][4];
            #pragma unroll
            for (int mt = 0; mt < 2; mt++) {
                uint32_t off = 2u * ((uint32_t)(wm * 32 + mt * 16 + (lane & 15)) * 40
                                     + ks * 16 + ((lane >> 4) << 3));
                ldmx4(aH[mt], bAh + off);
                ldmx4(aL[mt], bAl + off);
            }
            #pragma unroll
            for (int np = 0; np < 4; np++) {
                uint32_t off = 2u * ((uint32_t)(ks * 16 + (lane & 15)) * 136
                                     + wn * 64 + np * 16 + ((lane >> 4) << 3));
                ldmx4t(bH[np], bBh + off);
                ldmx4t(bL[np], bBl + off);
            }
            #pragma unroll
            for (int mt = 0; mt < 2; mt++)
                #pragma unroll
                for (int nt = 0; nt < 8; nt++) {
                    const uint32_t* bh = &bH[nt >> 1][(nt & 1) * 2];
                    const uint32_t* bl = &bL[nt >> 1][(nt & 1) * 2];
                    mma_bf16(c[mt][nt], aH[mt], bh);
                    mma_bf16(c[mt][nt], aH[mt], bl);
                    mma_bf16(c[mt][nt], aL[mt], bh);
                }
        }
        __syncthreads();
    }

    if (MODE == 1) {
        #pragma unroll
        for (int mt = 0; mt < 2; mt++) {
            int r0 = brow + wm * 32 + mt * 16 + (lane >> 2);
            #pragma unroll
            for (int nt = 0; nt < 8; nt++) {
                int cc = bcol + wn * 64 + nt * 8 + (t4 << 1);
                float2 v0; v0.x = c[mt][nt][0]; v0.y = c[mt][nt][1];
                float2 v1; v1.x = c[mt][nt][2]; v1.y = c[mt][nt][3];
                *(float2*)(Cout + r0 * 1024 + cc)       = v0;
                *(float2*)(Cout + (r0 + 8) * 1024 + cc) = v1;
            }
        }
    } else {
        int region = (bcol < 1024) ? 0 : (bcol < 1280 ? 1 : 2);
        #pragma unroll
        for (int mt = 0; mt < 2; mt++) {
            int r0 = brow + wm * 32 + mt * 16 + (lane >> 2);
            int r1 = r0 + 8;
            int b0 = r0 >> 11, t0 = r0 & 2047;
            int b1 = r1 >> 11, t1 = r1 & 2047;
            if (region == 2) {
                int colb = bcol - 1280 + wn * 64;
                int h = colb >> 6;
                #pragma unroll
                for (int nt = 0; nt < 8; nt++) {
                    int d = nt * 8 + (t4 << 1);
                    int i0 = ((b0 * 4 + h) * 2048 + t0) * 64 + d;
                    int i1 = ((b1 * 4 + h) * 2048 + t1) * 64 + d;
                    store_hl(g_vh, g_vl, i0, c[mt][nt][0], c[mt][nt][1]);
                    store_hl(g_vh, g_vl, i1, c[mt][nt][2], c[mt][nt][3]);
                }
            } else {
                int colb = (region == 0) ? bcol + wn * 64 : bcol - 1024 + wn * 64;
                int h = colb >> 6;
                __nv_bfloat16* H = (region == 0) ? g_qh : g_kh;
                __nv_bfloat16* L = (region == 0) ? g_ql : g_kl;
                int nh   = (region == 0) ? 16 : 4;
                float sc = (region == 0) ? SOFTMAX_SCALE : 1.f;
                #pragma unroll
                for (int nt = 0; nt < 4; nt++) {
                    int d = nt * 8 + (t4 << 1);
                    float2 cc0 = *(const float2*)(cosb + t0 * 32 + d);
                    float2 ss0 = *(const float2*)(sinb + t0 * 32 + d);
                    float2 cc1 = *(const float2*)(cosb + t1 * 32 + d);
                    float2 ss1 = *(const float2*)(sinb + t1 * 32 + d);
                    float x1a = c[mt][nt][0],     x1b = c[mt][nt][1];
                    float x2a = c[mt][nt + 4][0], x2b = c[mt][nt + 4][1];
                    int i0 = ((b0 * nh + h) * 2048 + t0) * 64 + d;
                    store_hl(H, L, i0,      (x1a*cc0.x - x2a*ss0.x)*sc, (x1b*cc0.y - x2b*ss0.y)*sc);
                    store_hl(H, L, i0 + 32, (x2a*cc0.x + x1a*ss0.x)*sc, (x2b*cc0.y + x1b*ss0.y)*sc);
                    x1a = c[mt][nt][2];     x1b = c[mt][nt][3];
                    x2a = c[mt][nt + 4][2]; x2b = c[mt][nt + 4][3];
                    int i1 = ((b1 * nh + h) * 2048 + t1) * 64 + d;
                    store_hl(H, L, i1,      (x1a*cc1.x - x2a*ss1.x)*sc, (x1b*cc1.y - x2b*ss1.y)*sc);
                    store_hl(H, L, i1 + 32, (x2a*cc1.x + x1a*ss1.x)*sc, (x2b*cc1.y + x1b*ss1.y)*sc);
                }
            }
        }
    }
}

// ---------------------------------------------------------------------------
// MMA flash attention (bf16x3), pre-split K/V, cp.async double-buffered.
// Block = 256 (8 warps), each warp 16 q rows; K/V tiles 64x64, pitch 72.
// Dynamic smem 73728 B. grid = (16, 32); qt remapped so heavy CTAs go first.
// ---------------------------------------------------------------------------
__global__ void __launch_bounds__(256, 1) attn_kernel()
{
    extern __shared__ __align__(16) __nv_bfloat16 smem[];
    const uint32_t sbase = smem_u32(smem);

    const int tid  = threadIdx.x;
    const int lane = tid & 31;
    const int warp = tid >> 5;
    const int g    = lane >> 2;
    const int t4   = lane & 3;
    const int bh   = blockIdx.y;
    const int b    = bh >> 4, hh = bh & 15;
    const int kh   = hh >> 2;
    const int qt   = (int)gridDim.x - 1 - (int)blockIdx.x;   // heavy first

    const int r0 = qt * 128 + warp * 16 + g;
    const int r1 = r0 + 8;
    const int warp_max_row = qt * 128 + warp * 16 + 15;

    uint32_t qh[4][4], ql[4][4];
    {
        const __nv_bfloat16* q0h = g_qh + (bh * 2048 + r0) * 64;
        const __nv_bfloat16* q1h = g_qh + (bh * 2048 + r1) * 64;
        const __nv_bfloat16* q0l = g_ql + (bh * 2048 + r0) * 64;
        const __nv_bfloat16* q1l = g_ql + (bh * 2048 + r1) * 64;
        #pragma unroll
        for (int ks = 0; ks < 4; ks++) {
            int cb = ks * 16 + (t4 << 1);
            qh[ks][0] = *(const uint32_t*)(q0h + cb);
            qh[ks][1] = *(const uint32_t*)(q1h + cb);
            qh[ks][2] = *(const uint32_t*)(q0h + cb + 8);
            qh[ks][3] = *(const uint32_t*)(q1h + cb + 8);
            ql[ks][0] = *(const uint32_t*)(q0l + cb);
            ql[ks][1] = *(const uint32_t*)(q1l + cb);
            ql[ks][2] = *(const uint32_t*)(q0l + cb + 8);
            ql[ks][3] = *(const uint32_t*)(q1l + cb + 8);
        }
    }

    float o[8][4];
    #pragma unroll
    for (int nt = 0; nt < 8; nt++)
        #pragma unroll
        for (int i = 0; i < 4; i++) o[nt][i] = 0.f;
    float m0 = -1e30f, m1 = -1e30f, l0 = 0.f, l1 = 0.f;

    const __nv_bfloat16* src0 = g_kh + ((b * 4 + kh) * 2048) * 64;
    const __nv_bfloat16* src1 = g_kl + ((b * 4 + kh) * 2048) * 64;
    const __nv_bfloat16* src2 = g_vh + ((b * 4 + kh) * 2048) * 64;
    const __nv_bfloat16* src3 = g_vl + ((b * 4 + kh) * 2048) * 64;

    const int ntiles = 2 * qt + 2;

    auto stage = [&](int kt, int buf) {
        const __nv_bfloat16* srcs[4] = {src0, src1, src2, src3};
        #pragma unroll
        for (int a = 0; a < 4; a++) {
            uint32_t dbase = sbase + (uint32_t)(buf * 4 + a) * 9216u;
            const __nv_bfloat16* sp = srcs[a] + kt * 4096;
            #pragma unroll
            for (int i = 0; i < 2; i++) {
                int u = tid + i * 256;
                int row = u >> 3, c8 = (u & 7) << 3;
                cpa16(dbase + (uint32_t)(row * 72 + c8) * 2u, sp + u * 8);
            }
        }
        asm volatile("cp.async.commit_group;\n" ::: "memory");
    };

    stage(0, 0);

    for (int kt = 0; kt < ntiles; kt++) {
        int buf = kt & 1;
        if (kt + 1 < ntiles) {
            stage(kt + 1, buf ^ 1);
            asm volatile("cp.async.wait_group 1;\n" ::: "memory");
        } else {
            asm volatile("cp.async.wait_group 0;\n" ::: "memory");
        }
        __syncthreads();

        if (kt * 64 <= warp_max_row) {
            const uint32_t bKh = sbase + (uint32_t)(buf * 4 + 0) * 9216u;
            const uint32_t bKl = sbase + (uint32_t)(buf * 4 + 1) * 9216u;
            const uint32_t bVh = sbase + (uint32_t)(buf * 4 + 2) * 9216u;
            const uint32_t bVl = sbase + (uint32_t)(buf * 4 + 3) * 9216u;

            float s[8][4];
            #pragma unroll
            for (int nt = 0; nt < 8; nt++)
                #pragma unroll
                for (int i = 0; i < 4; i++) s[nt][i] = 0.f;

            #pragma unroll
            for (int ks = 0; ks < 4; ks++) {
                uint32_t kbh[4][4], kbl[4][4];
                #pragma unroll
                for (int pr = 0; pr < 4; pr++) {
                    int n_idx = pr * 16 + (lane & 7) + ((lane >> 4) << 3);
                    int koff  = 16 * ks + ((lane >> 3) & 1) * 8;
                    uint32_t off = 2u * (uint32_t)(n_idx * 72 + koff);
                    ldmx4(kbh[pr], bKh + off);
                    ldmx4(kbl[pr], bKl + off);
                }
                #pragma unroll
                for (int pr = 0; pr < 4; pr++)
                    #pragma unroll
                    for (int sub = 0; sub < 2; sub++) {
                        float* sc = s[pr * 2 + sub];
                        mma_bf16(sc, qh[ks], &kbh[pr][sub * 2]);
                        mma_bf16(sc, qh[ks], &kbl[pr][sub * 2]);
                        mma_bf16(sc, ql[ks], &kbh[pr][sub * 2]);
                    }
            }

            if (kt * 64 + 63 > qt * 128 + warp * 16) {
                #pragma unroll
                for (int nt = 0; nt < 8; nt++) {
                    int c0 = kt * 64 + nt * 8 + (t4 << 1);
                    if (c0     > r0) s[nt][0] = -1e30f;
                    if (c0 + 1 > r0) s[nt][1] = -1e30f;
                    if (c0     > r1) s[nt][2] = -1e30f;
                    if (c0 + 1 > r1) s[nt][3] = -1e30f;
                }
            }

            float t0 = -1e30f, t1 = -1e30f;
            #pragma unroll
            for (int nt = 0; nt < 8; nt++) {
                t0 = fmaxf(t0, fmaxf(s[nt][0], s[nt][1]));
                t1 = fmaxf(t1, fmaxf(s[nt][2], s[nt][3]));
            }
            t0 = fmaxf(t0, __shfl_xor_sync(0xffffffffu, t0, 1));
            t0 = fmaxf(t0, __shfl_xor_sync(0xffffffffu, t0, 2));
            t1 = fmaxf(t1, __shfl_xor_sync(0xffffffffu, t1, 1));
            t1 = fmaxf(t1, __shfl_xor_sync(0xffffffffu, t1, 2));

            float m0n = fmaxf(m0, t0), m1n = fmaxf(m1, t1);
            float c0f = ex2(m0 - m0n), c1f = ex2(m1 - m1n);
            m0 = m0n; m1 = m1n;

            float sum0 = 0.f, sum1 = 0.f;
            #pragma unroll
            for (int nt = 0; nt < 8; nt++) {
                float p0 = ex2(s[nt][0] - m0);
                float p1 = ex2(s[nt][1] - m0);
                float p2 = ex2(s[nt][2] - m1);
                float p3 = ex2(s[nt][3] - m1);
                sum0 += p0 + p1; sum1 += p2 + p3;
                s[nt][0] = p0; s[nt][1] = p1; s[nt][2] = p2; s[nt][3] = p3;
            }
            l0 = l0 * c0f + sum0;
            l1 = l1 * c1f + sum1;
            #pragma unroll
            for (int nt = 0; nt < 8; nt++) {
                o[nt][0] *= c0f; o[nt][1] *= c0f;
                o[nt][2] *= c1f; o[nt][3] *= c1f;
            }

            #pragma unroll
            for (int ks = 0; ks < 4; ks++) {
                uint32_t aPh[4], aPl[4];
                pack_hl(s[2*ks][0],   s[2*ks][1],   aPh[0], aPl[0]);
                pack_hl(s[2*ks][2],   s[2*ks][3],   aPh[1], aPl[1]);
                pack_hl(s[2*ks+1][0], s[2*ks+1][1], aPh[2], aPl[2]);
                pack_hl(s[2*ks+1][2], s[2*ks+1][3], aPh[3], aPl[3]);

                #pragma unroll
                for (int dp = 0; dp < 4; dp++) {
                    uint32_t vfh[4], vfl[4];
                    uint32_t off = 2u * (uint32_t)((16 * ks + (lane & 15)) * 72
                                                   + dp * 16 + ((lane >> 4) << 3));
                    ldmx4t(vfh, bVh + off);
                    ldmx4t(vfl, bVl + off);
                    #pragma unroll
                    for (int sub = 0; sub < 2; sub++) {
                        float* oc = o[dp * 2 + sub];
                        mma_bf16(oc, aPh, &vfh[sub * 2]);
                        mma_bf16(oc, aPh, &vfl[sub * 2]);
                        mma_bf16(oc, aPl, &vfh[sub * 2]);
                    }
                }
            }
        }
        __syncthreads();
    }

    l0 += __shfl_xor_sync(0xffffffffu, l0, 1);
    l0 += __shfl_xor_sync(0xffffffffu, l0, 2);
    l1 += __shfl_xor_sync(0xffffffffu, l1, 1);
    l1 += __shfl_xor_sync(0xffffffffu, l1, 2);
    float inv0 = 1.f / l0, inv1 = 1.f / l1;

    int y0 = (b * 2048 + r0) * 1024 + hh * 64;
    int y1 = (b * 2048 + r1) * 1024 + hh * 64;
    #pragma unroll
    for (int nt = 0; nt < 8; nt++) {
        int d = nt * 8 + (t4 << 1);
        store_hl(g_yh, g_yl, y0 + d, o[nt][0] * inv0, o[nt][1] * inv0);
        store_hl(g_yh, g_yl, y1 + d, o[nt][2] * inv1, o[nt][3] * inv1);
    }
}

// ---------------------------------------------------------------------------
// Launch: x, cos, sin, Wq, Wk, Wv, Wo. out = f32 [B,T,C].
// ---------------------------------------------------------------------------
extern "C" void kernel_launch(void* const* d_in, const int* in_sizes, int n_in,
                              void* d_out, int out_size)
{
    const float* x    = (const float*)d_in[0];
    const float* cosb = (const float*)d_in[1];
    const float* sinb = (const float*)d_in[2];
    const float* Wq   = (const float*)d_in[3];
    const float* Wk   = (const float*)d_in[4];
    const float* Wv   = (const float*)d_in[5];
    const float* Wo   = (const float*)d_in[6];
    float* out = (float*)d_out;

    static bool attr_set = false;
    if (!attr_set) {
        cudaFuncSetAttribute(attn_kernel,
                             cudaFuncAttributeMaxDynamicSharedMemorySize, 73728);
        cudaFuncSetAttribute(gemm_bf16<0>,
                             cudaFuncAttributeMaxDynamicSharedMemorySize, 75776);
        cudaFuncSetAttribute(gemm_bf16<1>,
                             cudaFuncAttributeMaxDynamicSharedMemorySize, 75776);
        attr_set = true;
    }

    // 0. one-shot fp32 -> bf16 hi/lo conversions
    cvt_x<<<4096, 256>>>(x);
    cvt_qkvw<<<1536, 256>>>(Wq, Wk, Wv);
    cvt_wo<<<1024, 256>>>(Wo);

    // 1. fused QKV projection + RoPE + scale (bf16x3, pipelined)
    gemm_bf16<0><<<dim3(12, 32), 256, 75776>>>(cosb, sinb, nullptr);

    // 2. causal flash attention (bf16x3 MMA, cp.async pipeline)
    attn_kernel<<<dim3(16, 32), 256, 73728>>>();

    // 3. output projection
    gemm_bf16<1><<<dim3(8, 32), 256, 75776>>>(nullptr, nullptr, out);
}

// round 6
// speedup vs baseline: 1.1094x; 1.1094x over previous
#include <cuda_runtime.h>
#include <cuda_bf16.h>
#include <cstdint>

// ---------------------------------------------------------------------------
// GQA: B=2, T=2048, C=1024, H=16 q-heads, KVH=4 kv-heads, D=64, causal, RoPE
// All GEMM operands pre-split to bf16 hi/lo in gmem; bf16x3 MMA everywhere.
// ---------------------------------------------------------------------------

__device__ __align__(16) __nv_bfloat16 g_xh[4194304], g_xl[4194304];
__device__ __align__(16) __nv_bfloat16 g_wqkvh[1572864], g_wqkvl[1572864];
__device__ __align__(16) __nv_bfloat16 g_woh[1048576], g_wol[1048576];
__device__ __align__(16) __nv_bfloat16 g_qh[4194304], g_ql[4194304];
__device__ __align__(16) __nv_bfloat16 g_kh[1048576], g_kl[1048576];
__device__ __align__(16) __nv_bfloat16 g_vh[1048576], g_vl[1048576];
__device__ __align__(16) __nv_bfloat16 g_yh[4194304], g_yl[4194304];

// ---------------------------------------------------------------------------
// helpers
// ---------------------------------------------------------------------------
__device__ __forceinline__ uint32_t smem_u32(const void* p) {
    return (uint32_t)__cvta_generic_to_shared(p);
}
__device__ __forceinline__ void ldmx4(uint32_t* r, uint32_t addr) {
    asm volatile("ldmatrix.sync.aligned.m8n8.x4.shared.b16 {%0,%1,%2,%3}, [%4];"
        : "=r"(r[0]), "=r"(r[1]), "=r"(r[2]), "=r"(r[3]) : "r"(addr));
}
__device__ __forceinline__ void ldmx4t(uint32_t* r, uint32_t addr) {
    asm volatile("ldmatrix.sync.aligned.m8n8.x4.trans.shared.b16 {%0,%1,%2,%3}, [%4];"
        : "=r"(r[0]), "=r"(r[1]), "=r"(r[2]), "=r"(r[3]) : "r"(addr));
}
__device__ __forceinline__ void mma_bf16(float* c, const uint32_t* a, const uint32_t* b) {
    asm volatile(
        "mma.sync.aligned.m16n8k16.row.col.f32.bf16.bf16.f32 "
        "{%0,%1,%2,%3}, {%4,%5,%6,%7}, {%8,%9}, {%0,%1,%2,%3};\n"
        : "+f"(c[0]), "+f"(c[1]), "+f"(c[2]), "+f"(c[3])
        : "r"(a[0]), "r"(a[1]), "r"(a[2]), "r"(a[3]), "r"(b[0]), "r"(b[1]));
}
__device__ __forceinline__ float ex2(float x) {
    float r;
    asm("ex2.approx.f32 %0, %1;" : "=f"(r) : "f"(x));
    return r;
}
__device__ __forceinline__ void pack_hl(float x, float y, uint32_t& h, uint32_t& l) {
    __nv_bfloat162 hb, lb;
    __nv_bfloat16 hx = __float2bfloat16(x);
    hb.x = hx; lb.x = __float2bfloat16(x - __bfloat162float(hx));
    __nv_bfloat16 hy = __float2bfloat16(y);
    hb.y = hy; lb.y = __float2bfloat16(y - __bfloat162float(hy));
    h = *(uint32_t*)&hb; l = *(uint32_t*)&lb;
}
__device__ __forceinline__ void store_hl(__nv_bfloat16* H, __nv_bfloat16* L,
                                         int idx, float a, float b) {
    uint32_t h, l; pack_hl(a, b, h, l);
    *(uint32_t*)(H + idx) = h;
    *(uint32_t*)(L + idx) = l;
}
__device__ __forceinline__ void cpa16(uint32_t dst, const void* src) {
    asm volatile("cp.async.cg.shared.global [%0], [%1], 16;\n" :: "r"(dst), "l"(src));
}

#define SOFTMAX_SCALE (0.125f * 1.44269504088896f)  // 1/sqrt(64) * log2(e)

// ---------------------------------------------------------------------------
// Conversion kernels: fp32 -> bf16 hi/lo (one-shot, memory-bound)
// ---------------------------------------------------------------------------
__global__ void cvt_x(const float* __restrict__ src) {
    int i = blockIdx.x * blockDim.x + threadIdx.x;        // < 1048576
    float4 v = ((const float4*)src)[i];
    uint32_t h0, l0, h1, l1;
    pack_hl(v.x, v.y, h0, l0);
    pack_hl(v.z, v.w, h1, l1);
    uint2 hv; hv.x = h0; hv.y = h1;
    uint2 lv; lv.x = l0; lv.y = l1;
    ((uint2*)g_xh)[i] = hv; ((uint2*)g_xl)[i] = lv;
}
__global__ void cvt_wo(const float* __restrict__ src) {
    int i = blockIdx.x * blockDim.x + threadIdx.x;        // < 262144
    float4 v = ((const float4*)src)[i];
    uint32_t h0, l0, h1, l1;
    pack_hl(v.x, v.y, h0, l0);
    pack_hl(v.z, v.w, h1, l1);
    uint2 hv; hv.x = h0; hv.y = h1;
    uint2 lv; lv.x = l0; lv.y = l1;
    ((uint2*)g_woh)[i] = hv; ((uint2*)g_wol)[i] = lv;
}
__global__ void cvt_qkvw(const float* __restrict__ Wq,
                         const float* __restrict__ Wk,
                         const float* __restrict__ Wv) {
    int i = blockIdx.x * blockDim.x + threadIdx.x;        // < 393216
    int k = i / 384;
    int n = (i % 384) * 4;
    float4 v;
    if (n < 1024)      v = *(const float4*)(Wq + k * 1024 + n);
    else if (n < 1280) v = *(const float4*)(Wk + k * 256 + n - 1024);
    else               v = *(const float4*)(Wv + k * 256 + n - 1280);
    uint32_t h0, l0, h1, l1;
    pack_hl(v.x, v.y, h0, l0);
    pack_hl(v.z, v.w, h1, l1);
    uint2 hv; hv.x = h0; hv.y = h1;
    uint2 lv; lv.x = l0; lv.y = l1;
    int o = k * 1536 + n;
    *(uint2*)(g_wqkvh + o) = hv; *(uint2*)(g_wqkvl + o) = lv;
}

// ---------------------------------------------------------------------------
// bf16x3 GEMM, pre-split operands, cp.async double-buffered, 2 CTAs/SM.
// Tile 128x128, BK=32, 8 warps (4x2), 2x8 m16n8k16 frags per warp, x3 MMAs.
// Stage = 37888 B, 2 stages = 75776 B dynamic; 2 CTAs -> 151.5 KB/SM.
// MODE 0: A=g_x, B=g_wqkv (ldn=1536); epilogue RoPE(+scale) -> g_{q,k,v}{h,l}
// MODE 1: A=g_y,  B=g_wo  (ldn=1024); epilogue fp32 -> Cout
// ---------------------------------------------------------------------------
template<int MODE>
__global__ void __launch_bounds__(256, 2) gemm_bf16(
    const float* __restrict__ cosb,
    const float* __restrict__ sinb,
    float* __restrict__ Cout)
{
    extern __shared__ __align__(16) __nv_bfloat16 sm[];
    const uint32_t sbase = smem_u32(sm);
    const int ldn = (MODE == 0) ? 1536 : 1024;

    const __nv_bfloat16* Ah = (MODE == 0) ? g_xh : g_yh;
    const __nv_bfloat16* Al = (MODE == 0) ? g_xl : g_yl;
    const __nv_bfloat16* Bh = (MODE == 0) ? g_wqkvh : g_woh;
    const __nv_bfloat16* Bl = (MODE == 0) ? g_wqkvl : g_wol;

    const int tid  = threadIdx.x;
    const int lane = tid & 31;
    const int warp = tid >> 5;
    const int wm   = warp >> 1;
    const int wn   = warp & 1;
    const int brow = blockIdx.y * 128;
    const int bcol = blockIdx.x * 128;
    const int t4   = lane & 3;

    float c[2][8][4];
    #pragma unroll
    for (int mt = 0; mt < 2; mt++)
        #pragma unroll
        for (int nt = 0; nt < 8; nt++)
            #pragma unroll
            for (int i = 0; i < 4; i++) c[mt][nt][i] = 0.f;

    auto stage = [&](int kb, int buf) {
        uint32_t base = sbase + (uint32_t)buf * 37888u;
        #pragma unroll
        for (int i = 0; i < 2; i++) {
            int u   = tid + i * 256;
            int ar  = u >> 2, ac8 = (u & 3) << 3;
            cpa16(base + (uint32_t)(ar * 40 + ac8) * 2u,
                  Ah + (brow + ar) * 1024 + kb + ac8);
            cpa16(base + (uint32_t)(5120 + ar * 40 + ac8) * 2u,
                  Al + (brow + ar) * 1024 + kb + ac8);
            int br2 = u >> 4, bc8 = (u & 15) << 3;
            cpa16(base + (uint32_t)(10240 + br2 * 136 + bc8) * 2u,
                  Bh + (kb + br2) * ldn + bcol + bc8);
            cpa16(base + (uint32_t)(14592 + br2 * 136 + bc8) * 2u,
                  Bl + (kb + br2) * ldn + bcol + bc8);
        }
        asm volatile("cp.async.commit_group;\n" ::: "memory");
    };

    stage(0, 0);

    for (int ki = 0; ki < 32; ki++) {
        int buf = ki & 1;
        if (ki + 1 < 32) {
            stage((ki + 1) * 32, buf ^ 1);
            asm volatile("cp.async.wait_group 1;\n" ::: "memory");
        } else {
            asm volatile("cp.async.wait_group 0;\n" ::: "memory");
        }
        __syncthreads();

        uint32_t bAh = sbase + (uint32_t)buf * 37888u;
        uint32_t bAl = bAh + 10240u;
        uint32_t bBh = bAh + 20480u;
        uint32_t bBl = bAh + 29184u;

        #pragma unroll
        for (int ks = 0; ks < 2; ks++) {
            uint32_t aH[2][4], aL[2][4], bH[4][4], bL[4][4];
            #pragma unroll
            for (int mt = 0; mt < 2; mt++) {
                uint32_t off = 2u * ((uint32_t)(wm * 32 + mt * 16 + (lane & 15)) * 40
                                     + ks * 16 + ((lane >> 4) << 3));
                ldmx4(aH[mt], bAh + off);
                ldmx4(aL[mt], bAl + off);
            }
            #pragma unroll
            for (int np = 0; np < 4; np++) {
                uint32_t off = 2u * ((uint32_t)(ks * 16 + (lane & 15)) * 136
                                     + wn * 64 + np * 16 + ((lane >> 4) << 3));
                ldmx4t(bH[np], bBh + off);
                ldmx4t(bL[np], bBl + off);
            }
            #pragma unroll
            for (int mt = 0; mt < 2; mt++)
                #pragma unroll
                for (int nt = 0; nt < 8; nt++) {
                    const uint32_t* bh = &bH[nt >> 1][(nt & 1) * 2];
                    const uint32_t* bl = &bL[nt >> 1][(nt & 1) * 2];
                    mma_bf16(c[mt][nt], aH[mt], bh);
                    mma_bf16(c[mt][nt], aH[mt], bl);
                    mma_bf16(c[mt][nt], aL[mt], bh);
                }
        }
        __syncthreads();
    }

    if (MODE == 1) {
        #pragma unroll
        for (int mt = 0; mt < 2; mt++) {
            int r0 = brow + wm * 32 + mt * 16 + (lane >> 2);
            #pragma unroll
            for (int nt = 0; nt < 8; nt++) {
                int cc = bcol + wn * 64 + nt * 8 + (t4 << 1);
                float2 v0; v0.x = c[mt][nt][0]; v0.y = c[mt][nt][1];
                float2 v1; v1.x = c[mt][nt][2]; v1.y = c[mt][nt][3];
                *(float2*)(Cout + r0 * 1024 + cc)       = v0;
                *(float2*)(Cout + (r0 + 8) * 1024 + cc) = v1;
            }
        }
    } else {
        int region = (bcol < 1024) ? 0 : (bcol < 1280 ? 1 : 2);
        #pragma unroll
        for (int mt = 0; mt < 2; mt++) {
            int r0 = brow + wm * 32 + mt * 16 + (lane >> 2);
            int r1 = r0 + 8;
            int b0 = r0 >> 11, t0 = r0 & 2047;
            int b1 = r1 >> 11, t1 = r1 & 2047;
            if (region == 2) {
                int colb = bcol - 1280 + wn * 64;
                int h = colb >> 6;
                #pragma unroll
                for (int nt = 0; nt < 8; nt++) {
                    int d = nt * 8 + (t4 << 1);
                    int i0 = ((b0 * 4 + h) * 2048 + t0) * 64 + d;
                    int i1 = ((b1 * 4 + h) * 2048 + t1) * 64 + d;
                    store_hl(g_vh, g_vl, i0, c[mt][nt][0], c[mt][nt][1]);
                    store_hl(g_vh, g_vl, i1, c[mt][nt][2], c[mt][nt][3]);
                }
            } else {
                int colb = (region == 0) ? bcol + wn * 64 : bcol - 1024 + wn * 64;
                int h = colb >> 6;
                __nv_bfloat16* H = (region == 0) ? g_qh : g_kh;
                __nv_bfloat16* L = (region == 0) ? g_ql : g_kl;
                int nh   = (region == 0) ? 16 : 4;
                float sc = (region == 0) ? SOFTMAX_SCALE : 1.f;
                #pragma unroll
                for (int nt = 0; nt < 4; nt++) {
                    int d = nt * 8 + (t4 << 1);
                    float2 cc0 = *(const float2*)(cosb + t0 * 32 + d);
                    float2 ss0 = *(const float2*)(sinb + t0 * 32 + d);
                    float2 cc1 = *(const float2*)(cosb + t1 * 32 + d);
                    float2 ss1 = *(const float2*)(sinb + t1 * 32 + d);
                    float x1a = c[mt][nt][0],     x1b = c[mt][nt][1];
                    float x2a = c[mt][nt + 4][0], x2b = c[mt][nt + 4][1];
                    int i0 = ((b0 * nh + h) * 2048 + t0) * 64 + d;
                    store_hl(H, L, i0,      (x1a*cc0.x - x2a*ss0.x)*sc, (x1b*cc0.y - x2b*ss0.y)*sc);
                    store_hl(H, L, i0 + 32, (x2a*cc0.x + x1a*ss0.x)*sc, (x2b*cc0.y + x1b*ss0.y)*sc);
                    x1a = c[mt][nt][2];     x1b = c[mt][nt][3];
                    x2a = c[mt][nt + 4][2]; x2b = c[mt][nt + 4][3];
                    int i1 = ((b1 * nh + h) * 2048 + t1) * 64 + d;
                    store_hl(H, L, i1,      (x1a*cc1.x - x2a*ss1.x)*sc, (x1b*cc1.y - x2b*ss1.y)*sc);
                    store_hl(H, L, i1 + 32, (x2a*cc1.x + x1a*ss1.x)*sc, (x2b*cc1.y + x1b*ss1.y)*sc);
                }
            }
        }
    }
}

// ---------------------------------------------------------------------------
// MMA flash attention (bf16x3), pre-split K/V, 3-stage cp.async ring with a
// single __syncthreads per tile.
// Block = 256 (8 warps), each warp 16 q rows; K/V tiles 64x64, pitch 72.
// Dynamic smem: 3 stages x 4 arrays x 9216 B = 110592 B. grid = (16, 32).
// ---------------------------------------------------------------------------
__global__ void __launch_bounds__(256, 1) attn_kernel()
{
    extern __shared__ __align__(16) __nv_bfloat16 smem[];
    const uint32_t sbase = smem_u32(smem);

    const int tid  = threadIdx.x;
    const int lane = tid & 31;
    const int warp = tid >> 5;
    const int g    = lane >> 2;
    const int t4   = lane & 3;
    const int bh   = blockIdx.y;
    const int b    = bh >> 4, hh = bh & 15;
    const int kh   = hh >> 2;
    const int qt   = (int)gridDim.x - 1 - (int)blockIdx.x;   // heavy first

    const int r0 = qt * 128 + warp * 16 + g;
    const int r1 = r0 + 8;
    const int warp_max_row = qt * 128 + warp * 16 + 15;

    uint32_t qh[4][4], ql[4][4];
    {
        const __nv_bfloat16* q0h = g_qh + (bh * 2048 + r0) * 64;
        const __nv_bfloat16* q1h = g_qh + (bh * 2048 + r1) * 64;
        const __nv_bfloat16* q0l = g_ql + (bh * 2048 + r0) * 64;
        const __nv_bfloat16* q1l = g_ql + (bh * 2048 + r1) * 64;
        #pragma unroll
        for (int ks = 0; ks < 4; ks++) {
            int cb = ks * 16 + (t4 << 1);
            qh[ks][0] = *(const uint32_t*)(q0h + cb);
            qh[ks][1] = *(const uint32_t*)(q1h + cb);
            qh[ks][2] = *(const uint32_t*)(q0h + cb + 8);
            qh[ks][3] = *(const uint32_t*)(q1h + cb + 8);
            ql[ks][0] = *(const uint32_t*)(q0l + cb);
            ql[ks][1] = *(const uint32_t*)(q1l + cb);
            ql[ks][2] = *(const uint32_t*)(q0l + cb + 8);
            ql[ks][3] = *(const uint32_t*)(q1l + cb + 8);
        }
    }

    float o[8][4];
    #pragma unroll
    for (int nt = 0; nt < 8; nt++)
        #pragma unroll
        for (int i = 0; i < 4; i++) o[nt][i] = 0.f;
    float m0 = -1e30f, m1 = -1e30f, l0 = 0.f, l1 = 0.f;

    const __nv_bfloat16* src0 = g_kh + ((b * 4 + kh) * 2048) * 64;
    const __nv_bfloat16* src1 = g_kl + ((b * 4 + kh) * 2048) * 64;
    const __nv_bfloat16* src2 = g_vh + ((b * 4 + kh) * 2048) * 64;
    const __nv_bfloat16* src3 = g_vl + ((b * 4 + kh) * 2048) * 64;

    const int ntiles = 2 * qt + 2;   // >= 2

    auto stage = [&](int kt, int buf) {
        const __nv_bfloat16* srcs[4] = {src0, src1, src2, src3};
        #pragma unroll
        for (int a = 0; a < 4; a++) {
            uint32_t dbase = sbase + (uint32_t)(buf * 4 + a) * 9216u;
            const __nv_bfloat16* sp = srcs[a] + kt * 4096;
            #pragma unroll
            for (int i = 0; i < 2; i++) {
                int u = tid + i * 256;
                int row = u >> 3, c8 = (u & 7) << 3;
                cpa16(dbase + (uint32_t)(row * 72 + c8) * 2u, sp + u * 8);
            }
        }
        asm volatile("cp.async.commit_group;\n" ::: "memory");
    };

    stage(0, 0);
    if (ntiles > 1) stage(1, 1);

    for (int kt = 0; kt < ntiles; kt++) {
        int buf = kt % 3;
        if (kt == ntiles - 1) {
            asm volatile("cp.async.wait_group 0;\n" ::: "memory");
        } else {
            asm volatile("cp.async.wait_group 1;\n" ::: "memory");
        }
        __syncthreads();

        if (kt * 64 <= warp_max_row) {
            const uint32_t bKh = sbase + (uint32_t)(buf * 4 + 0) * 9216u;
            const uint32_t bKl = sbase + (uint32_t)(buf * 4 + 1) * 9216u;
            const uint32_t bVh = sbase + (uint32_t)(buf * 4 + 2) * 9216u;
            const uint32_t bVl = sbase + (uint32_t)(buf * 4 + 3) * 9216u;

            float s[8][4];
            #pragma unroll
            for (int nt = 0; nt < 8; nt++)
                #pragma unroll
                for (int i = 0; i < 4; i++) s[nt][i] = 0.f;

            #pragma unroll
            for (int ks = 0; ks < 4; ks++) {
                uint32_t kbh[4][4], kbl[4][4];
                #pragma unroll
                for (int pr = 0; pr < 4; pr++) {
                    int n_idx = pr * 16 + (lane & 7) + ((lane >> 4) << 3);
                    int koff  = 16 * ks + ((lane >> 3) & 1) * 8;
                    uint32_t off = 2u * (uint32_t)(n_idx * 72 + koff);
                    ldmx4(kbh[pr], bKh + off);
                    ldmx4(kbl[pr], bKl + off);
                }
                #pragma unroll
                for (int pr = 0; pr < 4; pr++)
                    #pragma unroll
                    for (int sub = 0; sub < 2; sub++) {
                        float* sc = s[pr * 2 + sub];
                        mma_bf16(sc, qh[ks], &kbh[pr][sub * 2]);
                        mma_bf16(sc, qh[ks], &kbl[pr][sub * 2]);
                        mma_bf16(sc, ql[ks], &kbh[pr][sub * 2]);
                    }
            }

            if (kt * 64 + 63 > qt * 128 + warp * 16) {
                #pragma unroll
                for (int nt = 0; nt < 8; nt++) {
                    int c0 = kt * 64 + nt * 8 + (t4 << 1);
                    if (c0     > r0) s[nt][0] = -1e30f;
                    if (c0 + 1 > r0) s[nt][1] = -1e30f;
                    if (c0     > r1) s[nt][2] = -1e30f;
                    if (c0 + 1 > r1) s[nt][3] = -1e30f;
                }
            }

            float t0 = -1e30f, t1 = -1e30f;
            #pragma unroll
            for (int nt = 0; nt < 8; nt++) {
                t0 = fmaxf(t0, fmaxf(s[nt][0], s[nt][1]));
                t1 = fmaxf(t1, fmaxf(s[nt][2], s[nt][3]));
            }
            t0 = fmaxf(t0, __shfl_xor_sync(0xffffffffu, t0, 1));
            t0 = fmaxf(t0, __shfl_xor_sync(0xffffffffu, t0, 2));
            t1 = fmaxf(t1, __shfl_xor_sync(0xffffffffu, t1, 1));
            t1 = fmaxf(t1, __shfl_xor_sync(0xffffffffu, t1, 2));

            float m0n = fmaxf(m0, t0), m1n = fmaxf(m1, t1);
            float c0f = ex2(m0 - m0n), c1f = ex2(m1 - m1n);
            m0 = m0n; m1 = m1n;

            float sum0 = 0.f, sum1 = 0.f;
            #pragma unroll
            for (int nt = 0; nt < 8; nt++) {
                float p0 = ex2(s[nt][0] - m0);
                float p1 = ex2(s[nt][1] - m0);
                float p2 = ex2(s[nt][2] - m1);
                float p3 = ex2(s[nt][3] - m1);
                sum0 += p0 + p1; sum1 += p2 + p3;
                s[nt][0] = p0; s[nt][1] = p1; s[nt][2] = p2; s[nt][3] = p3;
            }
            l0 = l0 * c0f + sum0;
            l1 = l1 * c1f + sum1;
            #pragma unroll
            for (int nt = 0; nt < 8; nt++) {
                o[nt][0] *= c0f; o[nt][1] *= c0f;
                o[nt][2] *= c1f; o[nt][3] *= c1f;
            }

            #pragma unroll
            for (int ks = 0; ks < 4; ks++) {
                uint32_t aPh[4], aPl[4];
                pack_hl(s[2*ks][0],   s[2*ks][1],   aPh[0], aPl[0]);
                pack_hl(s[2*ks][2],   s[2*ks][3],   aPh[1], aPl[1]);
                pack_hl(s[2*ks+1][0], s[2*ks+1][1], aPh[2], aPl[2]);
                pack_hl(s[2*ks+1][2], s[2*ks+1][3], aPh[3], aPl[3]);

                #pragma unroll
                for (int dp = 0; dp < 4; dp++) {
                    uint32_t vfh[4], vfl[4];
                    uint32_t off = 2u * (uint32_t)((16 * ks + (lane & 15)) * 72
                                                   + dp * 16 + ((lane >> 4) << 3));
                    ldmx4t(vfh, bVh + off);
                    ldmx4t(vfl, bVl + off);
                    #pragma unroll
                    for (int sub = 0; sub < 2; sub++) {
                        float* oc = o[dp * 2 + sub];
                        mma_bf16(oc, aPh, &vfh[sub * 2]);
                        mma_bf16(oc, aPh, &vfl[sub * 2]);
                        mma_bf16(oc, aPl, &vfh[sub * 2]);
                    }
                }
            }
        }

        // issue stage kt+2 into ring slot (kt+2)%3; safe: all warps have
        // passed this iteration's barrier, so slot (kt+2)%3 == (kt-1)%3 is free
        if (kt + 2 < ntiles) stage(kt + 2, (kt + 2) % 3);
    }

    l0 += __shfl_xor_sync(0xffffffffu, l0, 1);
    l0 += __shfl_xor_sync(0xffffffffu, l0, 2);
    l1 += __shfl_xor_sync(0xffffffffu, l1, 1);
    l1 += __shfl_xor_sync(0xffffffffu, l1, 2);
    float inv0 = 1.f / l0, inv1 = 1.f / l1;

    int y0 = (b * 2048 + r0) * 1024 + hh * 64;
    int y1 = (b * 2048 + r1) * 1024 + hh * 64;
    #pragma unroll
    for (int nt = 0; nt < 8; nt++) {
        int d = nt * 8 + (t4 << 1);
        store_hl(g_yh, g_yl, y0 + d, o[nt][0] * inv0, o[nt][1] * inv0);
        store_hl(g_yh, g_yl, y1 + d, o[nt][2] * inv1, o[nt][3] * inv1);
    }
}

// ---------------------------------------------------------------------------
// Launch: x, cos, sin, Wq, Wk, Wv, Wo. out = f32 [B,T,C].
// ---------------------------------------------------------------------------
extern "C" void kernel_launch(void* const* d_in, const int* in_sizes, int n_in,
                              void* d_out, int out_size)
{
    const float* x    = (const float*)d_in[0];
    const float* cosb = (const float*)d_in[1];
    const float* sinb = (const float*)d_in[2];
    const float* Wq   = (const float*)d_in[3];
    const float* Wk   = (const float*)d_in[4];
    const float* Wv   = (const float*)d_in[5];
    const float* Wo   = (const float*)d_in[6];
    float* out = (float*)d_out;

    static bool attr_set = false;
    if (!attr_set) {
        cudaFuncSetAttribute(attn_kernel,
                             cudaFuncAttributeMaxDynamicSharedMemorySize, 110592);
        cudaFuncSetAttribute(gemm_bf16<0>,
                             cudaFuncAttributeMaxDynamicSharedMemorySize, 75776);
        cudaFuncSetAttribute(gemm_bf16<1>,
                             cudaFuncAttributeMaxDynamicSharedMemorySize, 75776);
        attr_set = true;
    }

    // 0. one-shot fp32 -> bf16 hi/lo conversions
    cvt_x<<<4096, 256>>>(x);
    cvt_qkvw<<<1536, 256>>>(Wq, Wk, Wv);
    cvt_wo<<<1024, 256>>>(Wo);

    // 1. fused QKV projection + RoPE + scale (bf16x3, 2 CTAs/SM)
    gemm_bf16<0><<<dim3(12, 32), 256, 75776>>>(cosb, sinb, nullptr);

    // 2. causal flash attention (bf16x3 MMA, 3-stage cp.async ring)
    attn_kernel<<<dim3(16, 32), 256, 110592>>>();

    // 3. output projection (2 CTAs/SM)
    gemm_bf16<1><<<dim3(8, 32), 256, 75776>>>(nullptr, nullptr, out);
}

// round 7
// speedup vs baseline: 1.1453x; 1.0324x over previous
#include <cuda_runtime.h>
#include <cuda_bf16.h>
#include <cstdint>

// ---------------------------------------------------------------------------
// GQA: B=2, T=2048, C=1024, H=16 q-heads, KVH=4 kv-heads, D=64, causal, RoPE
// All GEMM operands pre-split to bf16 hi/lo in gmem; bf16x3 MMA everywhere.
// ---------------------------------------------------------------------------

__device__ __align__(16) __nv_bfloat16 g_xh[4194304], g_xl[4194304];
__device__ __align__(16) __nv_bfloat16 g_wqkvh[1572864], g_wqkvl[1572864];
__device__ __align__(16) __nv_bfloat16 g_woh[1048576], g_wol[1048576];
__device__ __align__(16) __nv_bfloat16 g_qh[4194304], g_ql[4194304];
__device__ __align__(16) __nv_bfloat16 g_kh[1048576], g_kl[1048576];
__device__ __align__(16) __nv_bfloat16 g_vh[1048576], g_vl[1048576];
__device__ __align__(16) __nv_bfloat16 g_yh[4194304], g_yl[4194304];

// ---------------------------------------------------------------------------
// helpers
// ---------------------------------------------------------------------------
__device__ __forceinline__ uint32_t smem_u32(const void* p) {
    return (uint32_t)__cvta_generic_to_shared(p);
}
__device__ __forceinline__ void ldmx4(uint32_t* r, uint32_t addr) {
    asm volatile("ldmatrix.sync.aligned.m8n8.x4.shared.b16 {%0,%1,%2,%3}, [%4];"
        : "=r"(r[0]), "=r"(r[1]), "=r"(r[2]), "=r"(r[3]) : "r"(addr));
}
__device__ __forceinline__ void ldmx4t(uint32_t* r, uint32_t addr) {
    asm volatile("ldmatrix.sync.aligned.m8n8.x4.trans.shared.b16 {%0,%1,%2,%3}, [%4];"
        : "=r"(r[0]), "=r"(r[1]), "=r"(r[2]), "=r"(r[3]) : "r"(addr));
}
__device__ __forceinline__ void mma_bf16(float* c, const uint32_t* a, const uint32_t* b) {
    asm volatile(
        "mma.sync.aligned.m16n8k16.row.col.f32.bf16.bf16.f32 "
        "{%0,%1,%2,%3}, {%4,%5,%6,%7}, {%8,%9}, {%0,%1,%2,%3};\n"
        : "+f"(c[0]), "+f"(c[1]), "+f"(c[2]), "+f"(c[3])
        : "r"(a[0]), "r"(a[1]), "r"(a[2]), "r"(a[3]), "r"(b[0]), "r"(b[1]));
}
__device__ __forceinline__ float ex2(float x) {
    float r;
    asm("ex2.approx.f32 %0, %1;" : "=f"(r) : "f"(x));
    return r;
}
__device__ __forceinline__ void pack_hl(float x, float y, uint32_t& h, uint32_t& l) {
    __nv_bfloat162 hb, lb;
    __nv_bfloat16 hx = __float2bfloat16(x);
    hb.x = hx; lb.x = __float2bfloat16(x - __bfloat162float(hx));
    __nv_bfloat16 hy = __float2bfloat16(y);
    hb.y = hy; lb.y = __float2bfloat16(y - __bfloat162float(hy));
    h = *(uint32_t*)&hb; l = *(uint32_t*)&lb;
}
__device__ __forceinline__ void store_hl(__nv_bfloat16* H, __nv_bfloat16* L,
                                         int idx, float a, float b) {
    uint32_t h, l; pack_hl(a, b, h, l);
    *(uint32_t*)(H + idx) = h;
    *(uint32_t*)(L + idx) = l;
}
__device__ __forceinline__ void cpa16(uint32_t dst, const void* src) {
    asm volatile("cp.async.cg.shared.global [%0], [%1], 16;\n" :: "r"(dst), "l"(src));
}

#define SOFTMAX_SCALE (0.125f * 1.44269504088896f)  // 1/sqrt(64) * log2(e)

// ---------------------------------------------------------------------------
// Conversion kernels: fp32 -> bf16 hi/lo (one-shot, memory-bound)
// ---------------------------------------------------------------------------
__global__ void cvt_x(const float* __restrict__ src) {
    int i = blockIdx.x * blockDim.x + threadIdx.x;        // < 1048576
    float4 v = ((const float4*)src)[i];
    uint32_t h0, l0, h1, l1;
    pack_hl(v.x, v.y, h0, l0);
    pack_hl(v.z, v.w, h1, l1);
    uint2 hv; hv.x = h0; hv.y = h1;
    uint2 lv; lv.x = l0; lv.y = l1;
    ((uint2*)g_xh)[i] = hv; ((uint2*)g_xl)[i] = lv;
}
__global__ void cvt_wo(const float* __restrict__ src) {
    int i = blockIdx.x * blockDim.x + threadIdx.x;        // < 262144
    float4 v = ((const float4*)src)[i];
    uint32_t h0, l0, h1, l1;
    pack_hl(v.x, v.y, h0, l0);
    pack_hl(v.z, v.w, h1, l1);
    uint2 hv; hv.x = h0; hv.y = h1;
    uint2 lv; lv.x = l0; lv.y = l1;
    ((uint2*)g_woh)[i] = hv; ((uint2*)g_wol)[i] = lv;
}
__global__ void cvt_qkvw(const float* __restrict__ Wq,
                         const float* __restrict__ Wk,
                         const float* __restrict__ Wv) {
    int i = blockIdx.x * blockDim.x + threadIdx.x;        // < 393216
    int k = i / 384;
    int n = (i % 384) * 4;
    float4 v;
    if (n < 1024)      v = *(const float4*)(Wq + k * 1024 + n);
    else if (n < 1280) v = *(const float4*)(Wk + k * 256 + n - 1024);
    else               v = *(const float4*)(Wv + k * 256 + n - 1280);
    uint32_t h0, l0, h1, l1;
    pack_hl(v.x, v.y, h0, l0);
    pack_hl(v.z, v.w, h1, l1);
    uint2 hv; hv.x = h0; hv.y = h1;
    uint2 lv; lv.x = l0; lv.y = l1;
    int o = k * 1536 + n;
    *(uint2*)(g_wqkvh + o) = hv; *(uint2*)(g_wqkvl + o) = lv;
}

// ---------------------------------------------------------------------------
// bf16x3 GEMM, pre-split operands, cp.async double-buffered, 2 CTAs/SM.
// Tile 128x128, BK=32, 8 warps (4x2), 2x8 m16n8k16 frags per warp, x3 MMAs.
// Stage = 37888 B, 2 stages = 75776 B dynamic; 2 CTAs -> 151.5 KB/SM.
// MODE 0: A=g_x, B=g_wqkv (ldn=1536); epilogue RoPE(+scale) -> g_{q,k,v}{h,l}
// MODE 1: A=g_y,  B=g_wo  (ldn=1024); epilogue fp32 -> Cout
// ---------------------------------------------------------------------------
template<int MODE>
__global__ void __launch_bounds__(256, 2) gemm_bf16(
    const float* __restrict__ cosb,
    const float* __restrict__ sinb,
    float* __restrict__ Cout)
{
    extern __shared__ __align__(16) __nv_bfloat16 sm[];
    const uint32_t sbase = smem_u32(sm);
    const int ldn = (MODE == 0) ? 1536 : 1024;

    const __nv_bfloat16* Ah = (MODE == 0) ? g_xh : g_yh;
    const __nv_bfloat16* Al = (MODE == 0) ? g_xl : g_yl;
    const __nv_bfloat16* Bh = (MODE == 0) ? g_wqkvh : g_woh;
    const __nv_bfloat16* Bl = (MODE == 0) ? g_wqkvl : g_wol;

    const int tid  = threadIdx.x;
    const int lane = tid & 31;
    const int warp = tid >> 5;
    const int wm   = warp >> 1;
    const int wn   = warp & 1;
    const int brow = blockIdx.y * 128;
    const int bcol = blockIdx.x * 128;
    const int t4   = lane & 3;

    float c[2][8][4];
    #pragma unroll
    for (int mt = 0; mt < 2; mt++)
        #pragma unroll
        for (int nt = 0; nt < 8; nt++)
            #pragma unroll
            for (int i = 0; i < 4; i++) c[mt][nt][i] = 0.f;

    auto stage = [&](int kb, int buf) {
        uint32_t base = sbase + (uint32_t)buf * 37888u;
        #pragma unroll
        for (int i = 0; i < 2; i++) {
            int u   = tid + i * 256;
            int ar  = u >> 2, ac8 = (u & 3) << 3;
            cpa16(base + (uint32_t)(ar * 40 + ac8) * 2u,
                  Ah + (brow + ar) * 1024 + kb + ac8);
            cpa16(base + (uint32_t)(5120 + ar * 40 + ac8) * 2u,
                  Al + (brow + ar) * 1024 + kb + ac8);
            int br2 = u >> 4, bc8 = (u & 15) << 3;
            cpa16(base + (uint32_t)(10240 + br2 * 136 + bc8) * 2u,
                  Bh + (kb + br2) * ldn + bcol + bc8);
            cpa16(base + (uint32_t)(14592 + br2 * 136 + bc8) * 2u,
                  Bl + (kb + br2) * ldn + bcol + bc8);
        }
        asm volatile("cp.async.commit_group;\n" ::: "memory");
    };

    stage(0, 0);

    for (int ki = 0; ki < 32; ki++) {
        int buf = ki & 1;
        if (ki + 1 < 32) {
            stage((ki + 1) * 32, buf ^ 1);
            asm volatile("cp.async.wait_group 1;\n" ::: "memory");
        } else {
            asm volatile("cp.async.wait_group 0;\n" ::: "memory");
        }
        __syncthreads();

        uint32_t bAh = sbase + (uint32_t)buf * 37888u;
        uint32_t bAl = bAh + 10240u;
        uint32_t bBh = bAh + 20480u;
        uint32_t bBl = bAh + 29184u;

        #pragma unroll
        for (int ks = 0; ks < 2; ks++) {
            uint32_t aH[2][4], aL[2][4], bH[4][4], bL[4][4];
            #pragma unroll
            for (int mt = 0; mt < 2; mt++) {
                uint32_t off = 2u * ((uint32_t)(wm * 32 + mt * 16 + (lane & 15)) * 40
                                     + ks * 16 + ((lane >> 4) << 3));
                ldmx4(aH[mt], bAh + off);
                ldmx4(aL[mt], bAl + off);
            }
            #pragma unroll
            for (int np = 0; np < 4; np++) {
                uint32_t off = 2u * ((uint32_t)(ks * 16 + (lane & 15)) * 136
                                     + wn * 64 + np * 16 + ((lane >> 4) << 3));
                ldmx4t(bH[np], bBh + off);
                ldmx4t(bL[np], bBl + off);
            }
            #pragma unroll
            for (int mt = 0; mt < 2; mt++)
                #pragma unroll
                for (int nt = 0; nt < 8; nt++) {
                    const uint32_t* bh = &bH[nt >> 1][(nt & 1) * 2];
                    const uint32_t* bl = &bL[nt >> 1][(nt & 1) * 2];
                    mma_bf16(c[mt][nt], aH[mt], bh);
                    mma_bf16(c[mt][nt], aH[mt], bl);
                    mma_bf16(c[mt][nt], aL[mt], bh);
                }
        }
        __syncthreads();
    }

    if (MODE == 1) {
        #pragma unroll
        for (int mt = 0; mt < 2; mt++) {
            int r0 = brow + wm * 32 + mt * 16 + (lane >> 2);
            #pragma unroll
            for (int nt = 0; nt < 8; nt++) {
                int cc = bcol + wn * 64 + nt * 8 + (t4 << 1);
                float2 v0; v0.x = c[mt][nt][0]; v0.y = c[mt][nt][1];
                float2 v1; v1.x = c[mt][nt][2]; v1.y = c[mt][nt][3];
                *(float2*)(Cout + r0 * 1024 + cc)       = v0;
                *(float2*)(Cout + (r0 + 8) * 1024 + cc) = v1;
            }
        }
    } else {
        int region = (bcol < 1024) ? 0 : (bcol < 1280 ? 1 : 2);
        #pragma unroll
        for (int mt = 0; mt < 2; mt++) {
            int r0 = brow + wm * 32 + mt * 16 + (lane >> 2);
            int r1 = r0 + 8;
            int b0 = r0 >> 11, t0 = r0 & 2047;
            int b1 = r1 >> 11, t1 = r1 & 2047;
            if (region == 2) {
                int colb = bcol - 1280 + wn * 64;
                int h = colb >> 6;
                #pragma unroll
                for (int nt = 0; nt < 8; nt++) {
                    int d = nt * 8 + (t4 << 1);
                    int i0 = ((b0 * 4 + h) * 2048 + t0) * 64 + d;
                    int i1 = ((b1 * 4 + h) * 2048 + t1) * 64 + d;
                    store_hl(g_vh, g_vl, i0, c[mt][nt][0], c[mt][nt][1]);
                    store_hl(g_vh, g_vl, i1, c[mt][nt][2], c[mt][nt][3]);
                }
            } else {
                int colb = (region == 0) ? bcol + wn * 64 : bcol - 1024 + wn * 64;
                int h = colb >> 6;
                __nv_bfloat16* H = (region == 0) ? g_qh : g_kh;
                __nv_bfloat16* L = (region == 0) ? g_ql : g_kl;
                int nh   = (region == 0) ? 16 : 4;
                float sc = (region == 0) ? SOFTMAX_SCALE : 1.f;
                #pragma unroll
                for (int nt = 0; nt < 4; nt++) {
                    int d = nt * 8 + (t4 << 1);
                    float2 cc0 = *(const float2*)(cosb + t0 * 32 + d);
                    float2 ss0 = *(const float2*)(sinb + t0 * 32 + d);
                    float2 cc1 = *(const float2*)(cosb + t1 * 32 + d);
                    float2 ss1 = *(const float2*)(sinb + t1 * 32 + d);
                    float x1a = c[mt][nt][0],     x1b = c[mt][nt][1];
                    float x2a = c[mt][nt + 4][0], x2b = c[mt][nt + 4][1];
                    int i0 = ((b0 * nh + h) * 2048 + t0) * 64 + d;
                    store_hl(H, L, i0,      (x1a*cc0.x - x2a*ss0.x)*sc, (x1b*cc0.y - x2b*ss0.y)*sc);
                    store_hl(H, L, i0 + 32, (x2a*cc0.x + x1a*ss0.x)*sc, (x2b*cc0.y + x1b*ss0.y)*sc);
                    x1a = c[mt][nt][2];     x1b = c[mt][nt][3];
                    x2a = c[mt][nt + 4][2]; x2b = c[mt][nt + 4][3];
                    int i1 = ((b1 * nh + h) * 2048 + t1) * 64 + d;
                    store_hl(H, L, i1,      (x1a*cc1.x - x2a*ss1.x)*sc, (x1b*cc1.y - x2b*ss1.y)*sc);
                    store_hl(H, L, i1 + 32, (x2a*cc1.x + x1a*ss1.x)*sc, (x2b*cc1.y + x1b*ss1.y)*sc);
                }
            }
        }
    }
}

// ---------------------------------------------------------------------------
// MMA flash attention (bf16x3), pre-split K/V, 3-stage cp.async ring,
// single __syncthreads per tile, 2 CTAs/SM.
// Block = 128 (4 warps), each warp 16 q rows -> CTA = 64 q rows.
// K/V tiles 64x64, pitch 72. Smem: 3 x 4 x 9216 = 110592 B per CTA
// (2 CTAs = 216 KB/SM). grid = (32, 32), heavy CTAs first.
// ---------------------------------------------------------------------------
__global__ void __launch_bounds__(128, 2) attn_kernel()
{
    extern __shared__ __align__(16) __nv_bfloat16 smem[];
    const uint32_t sbase = smem_u32(smem);

    const int tid  = threadIdx.x;
    const int lane = tid & 31;
    const int warp = tid >> 5;          // 0..3
    const int g    = lane >> 2;
    const int t4   = lane & 3;
    const int bh   = blockIdx.y;
    const int b    = bh >> 4, hh = bh & 15;
    const int kh   = hh >> 2;
    const int qt   = (int)gridDim.x - 1 - (int)blockIdx.x;   // heavy first

    const int r0 = qt * 64 + warp * 16 + g;
    const int r1 = r0 + 8;
    const int warp_max_row = qt * 64 + warp * 16 + 15;
    const int warp_min_row = qt * 64 + warp * 16;

    uint32_t qh[4][4], ql[4][4];
    {
        const __nv_bfloat16* q0h = g_qh + (bh * 2048 + r0) * 64;
        const __nv_bfloat16* q1h = g_qh + (bh * 2048 + r1) * 64;
        const __nv_bfloat16* q0l = g_ql + (bh * 2048 + r0) * 64;
        const __nv_bfloat16* q1l = g_ql + (bh * 2048 + r1) * 64;
        #pragma unroll
        for (int ks = 0; ks < 4; ks++) {
            int cb = ks * 16 + (t4 << 1);
            qh[ks][0] = *(const uint32_t*)(q0h + cb);
            qh[ks][1] = *(const uint32_t*)(q1h + cb);
            qh[ks][2] = *(const uint32_t*)(q0h + cb + 8);
            qh[ks][3] = *(const uint32_t*)(q1h + cb + 8);
            ql[ks][0] = *(const uint32_t*)(q0l + cb);
            ql[ks][1] = *(const uint32_t*)(q1l + cb);
            ql[ks][2] = *(const uint32_t*)(q0l + cb + 8);
            ql[ks][3] = *(const uint32_t*)(q1l + cb + 8);
        }
    }

    float o[8][4];
    #pragma unroll
    for (int nt = 0; nt < 8; nt++)
        #pragma unroll
        for (int i = 0; i < 4; i++) o[nt][i] = 0.f;
    float m0 = -1e30f, m1 = -1e30f, l0 = 0.f, l1 = 0.f;

    const __nv_bfloat16* src0 = g_kh + ((b * 4 + kh) * 2048) * 64;
    const __nv_bfloat16* src1 = g_kl + ((b * 4 + kh) * 2048) * 64;
    const __nv_bfloat16* src2 = g_vh + ((b * 4 + kh) * 2048) * 64;
    const __nv_bfloat16* src3 = g_vl + ((b * 4 + kh) * 2048) * 64;

    const int ntiles = qt + 1;   // 64-key tiles up to & including diagonal

    // stage one K/V tile: 4 arrays x 512 16B chunks, 128 threads x 4 each
    auto stage = [&](int kt, int buf) {
        const __nv_bfloat16* srcs[4] = {src0, src1, src2, src3};
        #pragma unroll
        for (int a = 0; a < 4; a++) {
            uint32_t dbase = sbase + (uint32_t)(buf * 4 + a) * 9216u;
            const __nv_bfloat16* sp = srcs[a] + kt * 4096;
            #pragma unroll
            for (int i = 0; i < 4; i++) {
                int u = tid + i * 128;
                int row = u >> 3, c8 = (u & 7) << 3;
                cpa16(dbase + (uint32_t)(row * 72 + c8) * 2u, sp + u * 8);
            }
        }
        asm volatile("cp.async.commit_group;\n" ::: "memory");
    };

    stage(0, 0);
    if (ntiles > 1) stage(1, 1);

    for (int kt = 0; kt < ntiles; kt++) {
        int buf = kt % 3;
        if (kt == ntiles - 1) {
            asm volatile("cp.async.wait_group 0;\n" ::: "memory");
        } else {
            asm volatile("cp.async.wait_group 1;\n" ::: "memory");
        }
        __syncthreads();

        {
            const uint32_t bKh = sbase + (uint32_t)(buf * 4 + 0) * 9216u;
            const uint32_t bKl = sbase + (uint32_t)(buf * 4 + 1) * 9216u;
            const uint32_t bVh = sbase + (uint32_t)(buf * 4 + 2) * 9216u;
            const uint32_t bVl = sbase + (uint32_t)(buf * 4 + 3) * 9216u;

            float s[8][4];
            #pragma unroll
            for (int nt = 0; nt < 8; nt++)
                #pragma unroll
                for (int i = 0; i < 4; i++) s[nt][i] = 0.f;

            #pragma unroll
            for (int ks = 0; ks < 4; ks++) {
                uint32_t kbh[4][4], kbl[4][4];
                #pragma unroll
                for (int pr = 0; pr < 4; pr++) {
                    int n_idx = pr * 16 + (lane & 7) + ((lane >> 4) << 3);
                    int koff  = 16 * ks + ((lane >> 3) & 1) * 8;
                    uint32_t off = 2u * (uint32_t)(n_idx * 72 + koff);
                    ldmx4(kbh[pr], bKh + off);
                    ldmx4(kbl[pr], bKl + off);
                }
                #pragma unroll
                for (int pr = 0; pr < 4; pr++)
                    #pragma unroll
                    for (int sub = 0; sub < 2; sub++) {
                        float* sc = s[pr * 2 + sub];
                        mma_bf16(sc, qh[ks], &kbh[pr][sub * 2]);
                        mma_bf16(sc, qh[ks], &kbl[pr][sub * 2]);
                        mma_bf16(sc, ql[ks], &kbh[pr][sub * 2]);
                    }
            }

            if (kt * 64 + 63 > warp_min_row) {
                #pragma unroll
                for (int nt = 0; nt < 8; nt++) {
                    int c0 = kt * 64 + nt * 8 + (t4 << 1);
                    if (c0     > r0) s[nt][0] = -1e30f;
                    if (c0 + 1 > r0) s[nt][1] = -1e30f;
                    if (c0     > r1) s[nt][2] = -1e30f;
                    if (c0 + 1 > r1) s[nt][3] = -1e30f;
                }
            }

            float t0 = -1e30f, t1 = -1e30f;
            #pragma unroll
            for (int nt = 0; nt < 8; nt++) {
                t0 = fmaxf(t0, fmaxf(s[nt][0], s[nt][1]));
                t1 = fmaxf(t1, fmaxf(s[nt][2], s[nt][3]));
            }
            t0 = fmaxf(t0, __shfl_xor_sync(0xffffffffu, t0, 1));
            t0 = fmaxf(t0, __shfl_xor_sync(0xffffffffu, t0, 2));
            t1 = fmaxf(t1, __shfl_xor_sync(0xffffffffu, t1, 1));
            t1 = fmaxf(t1, __shfl_xor_sync(0xffffffffu, t1, 2));

            float m0n = fmaxf(m0, t0), m1n = fmaxf(m1, t1);
            float c0f = ex2(m0 - m0n), c1f = ex2(m1 - m1n);
            m0 = m0n; m1 = m1n;

            float sum0 = 0.f, sum1 = 0.f;
            #pragma unroll
            for (int nt = 0; nt < 8; nt++) {
                float p0 = ex2(s[nt][0] - m0);
                float p1 = ex2(s[nt][1] - m0);
                float p2 = ex2(s[nt][2] - m1);
                float p3 = ex2(s[nt][3] - m1);
                sum0 += p0 + p1; sum1 += p2 + p3;
                s[nt][0] = p0; s[nt][1] = p1; s[nt][2] = p2; s[nt][3] = p3;
            }
            l0 = l0 * c0f + sum0;
            l1 = l1 * c1f + sum1;
            #pragma unroll
            for (int nt = 0; nt < 8; nt++) {
                o[nt][0] *= c0f; o[nt][1] *= c0f;
                o[nt][2] *= c1f; o[nt][3] *= c1f;
            }

            #pragma unroll
            for (int ks = 0; ks < 4; ks++) {
                uint32_t aPh[4], aPl[4];
                pack_hl(s[2*ks][0],   s[2*ks][1],   aPh[0], aPl[0]);
                pack_hl(s[2*ks][2],   s[2*ks][3],   aPh[1], aPl[1]);
                pack_hl(s[2*ks+1][0], s[2*ks+1][1], aPh[2], aPl[2]);
                pack_hl(s[2*ks+1][2], s[2*ks+1][3], aPh[3], aPl[3]);

                #pragma unroll
                for (int dp = 0; dp < 4; dp++) {
                    uint32_t vfh[4], vfl[4];
                    uint32_t off = 2u * (uint32_t)((16 * ks + (lane & 15)) * 72
                                                   + dp * 16 + ((lane >> 4) << 3));
                    ldmx4t(vfh, bVh + off);
                    ldmx4t(vfl, bVl + off);
                    #pragma unroll
                    for (int sub = 0; sub < 2; sub++) {
                        float* oc = o[dp * 2 + sub];
                        mma_bf16(oc, aPh, &vfh[sub * 2]);
                        mma_bf16(oc, aPh, &vfl[sub * 2]);
                        mma_bf16(oc, aPl, &vfh[sub * 2]);
                    }
                }
            }
        }

        // issue stage kt+2 into ring slot (kt+2)%3; safe: all warps have
        // passed this iteration's barrier, so slot (kt+2)%3 == (kt-1)%3 is free
        if (kt + 2 < ntiles) stage(kt + 2, (kt + 2) % 3);
    }

    l0 += __shfl_xor_sync(0xffffffffu, l0, 1);
    l0 += __shfl_xor_sync(0xffffffffu, l0, 2);
    l1 += __shfl_xor_sync(0xffffffffu, l1, 1);
    l1 += __shfl_xor_sync(0xffffffffu, l1, 2);
    float inv0 = 1.f / l0, inv1 = 1.f / l1;

    int y0 = (b * 2048 + r0) * 1024 + hh * 64;
    int y1 = (b * 2048 + r1) * 1024 + hh * 64;
    #pragma unroll
    for (int nt = 0; nt < 8; nt++) {
        int d = nt * 8 + (t4 << 1);
        store_hl(g_yh, g_yl, y0 + d, o[nt][0] * inv0, o[nt][1] * inv0);
        store_hl(g_yh, g_yl, y1 + d, o[nt][2] * inv1, o[nt][3] * inv1);
    }
}

// ---------------------------------------------------------------------------
// Launch: x, cos, sin, Wq, Wk, Wv, Wo. out = f32 [B,T,C].
// ---------------------------------------------------------------------------
extern "C" void kernel_launch(void* const* d_in, const int* in_sizes, int n_in,
                              void* d_out, int out_size)
{
    const float* x    = (const float*)d_in[0];
    const float* cosb = (const float*)d_in[1];
    const float* sinb = (const float*)d_in[2];
    const float* Wq   = (const float*)d_in[3];
    const float* Wk   = (const float*)d_in[4];
    const float* Wv   = (const float*)d_in[5];
    const float* Wo   = (const float*)d_in[6];
    float* out = (float*)d_out;

    static bool attr_set = false;
    if (!attr_set) {
        cudaFuncSetAttribute(attn_kernel,
                             cudaFuncAttributeMaxDynamicSharedMemorySize, 110592);
        cudaFuncSetAttribute(gemm_bf16<0>,
                             cudaFuncAttributeMaxDynamicSharedMemorySize, 75776);
        cudaFuncSetAttribute(gemm_bf16<1>,
                             cudaFuncAttributeMaxDynamicSharedMemorySize, 75776);
        attr_set = true;
    }

    // 0. one-shot fp32 -> bf16 hi/lo conversions
    cvt_x<<<4096, 256>>>(x);
    cvt_qkvw<<<1536, 256>>>(Wq, Wk, Wv);
    cvt_wo<<<1024, 256>>>(Wo);

    // 1. fused QKV projection + RoPE + scale (bf16x3, 2 CTAs/SM)
    gemm_bf16<0><<<dim3(12, 32), 256, 75776>>>(cosb, sinb, nullptr);

    // 2. causal flash attention (bf16x3 MMA, 3-stage ring, 2 CTAs/SM)
    attn_kernel<<<dim3(32, 32), 128, 110592>>>();

    // 3. output projection (2 CTAs/SM)
    gemm_bf16<1><<<dim3(8, 32), 256, 75776>>>(nullptr, nullptr, out);
}

// round 9
// speedup vs baseline: 1.2054x; 1.0524x over previous
#include <cuda_runtime.h>
#include <cuda_bf16.h>
#include <cstdint>

// ---------------------------------------------------------------------------
// GQA: B=2, T=2048, C=1024, H=16 q-heads, KVH=4 kv-heads, D=64, causal, RoPE
// All GEMM operands pre-split to bf16 hi/lo in gmem; HMMA bf16x3 everywhere.
// (tcgen05 is NOT available: harness ptxas targets sm_103 base.)
// ---------------------------------------------------------------------------

__device__ __align__(16) __nv_bfloat16 g_xh[4194304], g_xl[4194304];
__device__ __align__(16) __nv_bfloat16 g_wqkvh[1572864], g_wqkvl[1572864];
__device__ __align__(16) __nv_bfloat16 g_woh[1048576], g_wol[1048576];
__device__ __align__(16) __nv_bfloat16 g_qh[4194304], g_ql[4194304];
__device__ __align__(16) __nv_bfloat16 g_kh[1048576], g_kl[1048576];
__device__ __align__(16) __nv_bfloat16 g_vh[1048576], g_vl[1048576];
__device__ __align__(16) __nv_bfloat16 g_yh[4194304], g_yl[4194304];

// ---------------------------------------------------------------------------
// helpers
// ---------------------------------------------------------------------------
__device__ __forceinline__ uint32_t smem_u32(const void* p) {
    return (uint32_t)__cvta_generic_to_shared(p);
}
__device__ __forceinline__ void ldmx4(uint32_t* r, uint32_t addr) {
    asm volatile("ldmatrix.sync.aligned.m8n8.x4.shared.b16 {%0,%1,%2,%3}, [%4];"
        : "=r"(r[0]), "=r"(r[1]), "=r"(r[2]), "=r"(r[3]) : "r"(addr));
}
__device__ __forceinline__ void ldmx4t(uint32_t* r, uint32_t addr) {
    asm volatile("ldmatrix.sync.aligned.m8n8.x4.trans.shared.b16 {%0,%1,%2,%3}, [%4];"
        : "=r"(r[0]), "=r"(r[1]), "=r"(r[2]), "=r"(r[3]) : "r"(addr));
}
__device__ __forceinline__ void mma_bf16(float* c, const uint32_t* a, const uint32_t* b) {
    asm volatile(
        "mma.sync.aligned.m16n8k16.row.col.f32.bf16.bf16.f32 "
        "{%0,%1,%2,%3}, {%4,%5,%6,%7}, {%8,%9}, {%0,%1,%2,%3};\n"
        : "+f"(c[0]), "+f"(c[1]), "+f"(c[2]), "+f"(c[3])
        : "r"(a[0]), "r"(a[1]), "r"(a[2]), "r"(a[3]), "r"(b[0]), "r"(b[1]));
}
__device__ __forceinline__ float ex2(float x) {
    float r;
    asm("ex2.approx.f32 %0, %1;" : "=f"(r) : "f"(x));
    return r;
}
__device__ __forceinline__ void pack_hl(float x, float y, uint32_t& h, uint32_t& l) {
    __nv_bfloat162 hb, lb;
    __nv_bfloat16 hx = __float2bfloat16(x);
    hb.x = hx; lb.x = __float2bfloat16(x - __bfloat162float(hx));
    __nv_bfloat16 hy = __float2bfloat16(y);
    hb.y = hy; lb.y = __float2bfloat16(y - __bfloat162float(hy));
    h = *(uint32_t*)&hb; l = *(uint32_t*)&lb;
}
__device__ __forceinline__ void store_hl(__nv_bfloat16* H, __nv_bfloat16* L,
                                         int idx, float a, float b) {
    uint32_t h, l; pack_hl(a, b, h, l);
    *(uint32_t*)(H + idx) = h;
    *(uint32_t*)(L + idx) = l;
}
__device__ __forceinline__ void cpa16(uint32_t dst, const void* src) {
    asm volatile("cp.async.cg.shared.global [%0], [%1], 16;\n" :: "r"(dst), "l"(src));
}

#define SOFTMAX_SCALE (0.125f * 1.44269504088896f)  // 1/sqrt(64) * log2(e)

// ---------------------------------------------------------------------------
// Conversion kernels: fp32 -> bf16 hi/lo (one-shot, memory-bound)
// ---------------------------------------------------------------------------
__global__ void cvt_x(const float* __restrict__ src) {
    int i = blockIdx.x * blockDim.x + threadIdx.x;        // < 1048576
    float4 v = ((const float4*)src)[i];
    uint32_t h0, l0, h1, l1;
    pack_hl(v.x, v.y, h0, l0);
    pack_hl(v.z, v.w, h1, l1);
    uint2 hv; hv.x = h0; hv.y = h1;
    uint2 lv; lv.x = l0; lv.y = l1;
    ((uint2*)g_xh)[i] = hv; ((uint2*)g_xl)[i] = lv;
}
__global__ void cvt_wo(const float* __restrict__ src) {
    int i = blockIdx.x * blockDim.x + threadIdx.x;        // < 262144
    float4 v = ((const float4*)src)[i];
    uint32_t h0, l0, h1, l1;
    pack_hl(v.x, v.y, h0, l0);
    pack_hl(v.z, v.w, h1, l1);
    uint2 hv; hv.x = h0; hv.y = h1;
    uint2 lv; lv.x = l0; lv.y = l1;
    ((uint2*)g_woh)[i] = hv; ((uint2*)g_wol)[i] = lv;
}
__global__ void cvt_qkvw(const float* __restrict__ Wq,
                         const float* __restrict__ Wk,
                         const float* __restrict__ Wv) {
    int i = blockIdx.x * blockDim.x + threadIdx.x;        // < 393216
    int k = i / 384;
    int n = (i % 384) * 4;
    float4 v;
    if (n < 1024)      v = *(const float4*)(Wq + k * 1024 + n);
    else if (n < 1280) v = *(const float4*)(Wk + k * 256 + n - 1024);
    else               v = *(const float4*)(Wv + k * 256 + n - 1280);
    uint32_t h0, l0, h1, l1;
    pack_hl(v.x, v.y, h0, l0);
    pack_hl(v.z, v.w, h1, l1);
    uint2 hv; hv.x = h0; hv.y = h1;
    uint2 lv; lv.x = l0; lv.y = l1;
    int o = k * 1536 + n;
    *(uint2*)(g_wqkvh + o) = hv; *(uint2*)(g_wqkvl + o) = lv;
}

// ---------------------------------------------------------------------------
// bf16x3 GEMM, pre-split operands, 3-stage cp.async ring (ONE sync per slab),
// 2 CTAs/SM. Tile 128x128, BK=32, 8 warps (4x2), 2x8 frags/warp, x3 MMAs.
// Stage = 37888 B, 3 stages = 113664 B dynamic; 2 CTAs -> 227.3 KB/SM.
// MODE 0: A=g_x, B=g_wqkv (ldn=1536); epilogue RoPE(+scale) -> g_{q,k,v}{h,l}
// MODE 1: A=g_y,  B=g_wo  (ldn=1024); epilogue fp32 -> Cout
// ---------------------------------------------------------------------------
template<int MODE>
__global__ void __launch_bounds__(256, 2) gemm_bf16(
    const float* __restrict__ cosb,
    const float* __restrict__ sinb,
    float* __restrict__ Cout)
{
    extern __shared__ __align__(16) __nv_bfloat16 sm[];
    const uint32_t sbase = smem_u32(sm);
    const int ldn = (MODE == 0) ? 1536 : 1024;

    const __nv_bfloat16* Ah = (MODE == 0) ? g_xh : g_yh;
    const __nv_bfloat16* Al = (MODE == 0) ? g_xl : g_yl;
    const __nv_bfloat16* Bh = (MODE == 0) ? g_wqkvh : g_woh;
    const __nv_bfloat16* Bl = (MODE == 0) ? g_wqkvl : g_wol;

    const int tid  = threadIdx.x;
    const int lane = tid & 31;
    const int warp = tid >> 5;
    const int wm   = warp >> 1;
    const int wn   = warp & 1;
    const int brow = blockIdx.y * 128;
    const int bcol = blockIdx.x * 128;
    const int t4   = lane & 3;

    float c[2][8][4];
    #pragma unroll
    for (int mt = 0; mt < 2; mt++)
        #pragma unroll
        for (int nt = 0; nt < 8; nt++)
            #pragma unroll
            for (int i = 0; i < 4; i++) c[mt][nt][i] = 0.f;

    auto stage = [&](int ki, int buf) {
        int kb = ki * 32;
        uint32_t base = sbase + (uint32_t)buf * 37888u;
        #pragma unroll
        for (int i = 0; i < 2; i++) {
            int u   = tid + i * 256;
            int ar  = u >> 2, ac8 = (u & 3) << 3;
            cpa16(base + (uint32_t)(ar * 40 + ac8) * 2u,
                  Ah + (brow + ar) * 1024 + kb + ac8);
            cpa16(base + (uint32_t)(5120 + ar * 40 + ac8) * 2u,
                  Al + (brow + ar) * 1024 + kb + ac8);
            int br2 = u >> 4, bc8 = (u & 15) << 3;
            cpa16(base + (uint32_t)(10240 + br2 * 136 + bc8) * 2u,
                  Bh + (kb + br2) * ldn + bcol + bc8);
            cpa16(base + (uint32_t)(14592 + br2 * 136 + bc8) * 2u,
                  Bl + (kb + br2) * ldn + bcol + bc8);
        }
        asm volatile("cp.async.commit_group;\n" ::: "memory");
    };

    stage(0, 0);
    stage(1, 1);

    for (int ki = 0; ki < 32; ki++) {
        int buf = ki % 3;
        if (ki == 31) {
            asm volatile("cp.async.wait_group 0;\n" ::: "memory");
        } else {
            asm volatile("cp.async.wait_group 1;\n" ::: "memory");
        }
        __syncthreads();

        uint32_t bAh = sbase + (uint32_t)buf * 37888u;
        uint32_t bAl = bAh + 10240u;
        uint32_t bBh = bAh + 20480u;
        uint32_t bBl = bAh + 29184u;

        #pragma unroll
        for (int ks = 0; ks < 2; ks++) {
            uint32_t aH[2][4], aL[2][4], bH[4][4], bL[4][4];
            #pragma unroll
            for (int mt = 0; mt < 2; mt++) {
                uint32_t off = 2u * ((uint32_t)(wm * 32 + mt * 16 + (lane & 15)) * 40
                                     + ks * 16 + ((lane >> 4) << 3));
                ldmx4(aH[mt], bAh + off);
                ldmx4(aL[mt], bAl + off);
            }
            #pragma unroll
            for (int np = 0; np < 4; np++) {
                uint32_t off = 2u * ((uint32_t)(ks * 16 + (lane & 15)) * 136
                                     + wn * 64 + np * 16 + ((lane >> 4) << 3));
                ldmx4t(bH[np], bBh + off);
                ldmx4t(bL[np], bBl + off);
            }
            #pragma unroll
            for (int mt = 0; mt < 2; mt++)
                #pragma unroll
                for (int nt = 0; nt < 8; nt++) {
                    const uint32_t* bh = &bH[nt >> 1][(nt & 1) * 2];
                    const uint32_t* bl = &bL[nt >> 1][(nt & 1) * 2];
                    mma_bf16(c[mt][nt], aH[mt], bh);
                    mma_bf16(c[mt][nt], aH[mt], bl);
                    mma_bf16(c[mt][nt], aL[mt], bh);
                }
        }

        // 3-slot ring: slot (ki+2)%3 == (ki-1)%3; every warp has passed this
        // iteration's barrier, so the previous iteration's slot is free.
        if (ki + 2 < 32) stage(ki + 2, (ki + 2) % 3);
    }

    if (MODE == 1) {
        #pragma unroll
        for (int mt = 0; mt < 2; mt++) {
            int r0 = brow + wm * 32 + mt * 16 + (lane >> 2);
            #pragma unroll
            for (int nt = 0; nt < 8; nt++) {
                int cc = bcol + wn * 64 + nt * 8 + (t4 << 1);
                float2 v0; v0.x = c[mt][nt][0]; v0.y = c[mt][nt][1];
                float2 v1; v1.x = c[mt][nt][2]; v1.y = c[mt][nt][3];
                *(float2*)(Cout + r0 * 1024 + cc)       = v0;
                *(float2*)(Cout + (r0 + 8) * 1024 + cc) = v1;
            }
        }
    } else {
        int region = (bcol < 1024) ? 0 : (bcol < 1280 ? 1 : 2);
        #pragma unroll
        for (int mt = 0; mt < 2; mt++) {
            int r0 = brow + wm * 32 + mt * 16 + (lane >> 2);
            int r1 = r0 + 8;
            int b0 = r0 >> 11, t0 = r0 & 2047;
            int b1 = r1 >> 11, t1 = r1 & 2047;
            if (region == 2) {
                int colb = bcol - 1280 + wn * 64;
                int h = colb >> 6;
                #pragma unroll
                for (int nt = 0; nt < 8; nt++) {
                    int d = nt * 8 + (t4 << 1);
                    int i0 = ((b0 * 4 + h) * 2048 + t0) * 64 + d;
                    int i1 = ((b1 * 4 + h) * 2048 + t1) * 64 + d;
                    store_hl(g_vh, g_vl, i0, c[mt][nt][0], c[mt][nt][1]);
                    store_hl(g_vh, g_vl, i1, c[mt][nt][2], c[mt][nt][3]);
                }
            } else {
                int colb = (region == 0) ? bcol + wn * 64 : bcol - 1024 + wn * 64;
                int h = colb >> 6;
                __nv_bfloat16* H = (region == 0) ? g_qh : g_kh;
                __nv_bfloat16* L = (region == 0) ? g_ql : g_kl;
                int nh   = (region == 0) ? 16 : 4;
                float sc = (region == 0) ? SOFTMAX_SCALE : 1.f;
                #pragma unroll
                for (int nt = 0; nt < 4; nt++) {
                    int d = nt * 8 + (t4 << 1);
                    float2 cc0 = *(const float2*)(cosb + t0 * 32 + d);
                    float2 ss0 = *(const float2*)(sinb + t0 * 32 + d);
                    float2 cc1 = *(const float2*)(cosb + t1 * 32 + d);
                    float2 ss1 = *(const float2*)(sinb + t1 * 32 + d);
                    float x1a = c[mt][nt][0],     x1b = c[mt][nt][1];
                    float x2a = c[mt][nt + 4][0], x2b = c[mt][nt + 4][1];
                    int i0 = ((b0 * nh + h) * 2048 + t0) * 64 + d;
                    store_hl(H, L, i0,      (x1a*cc0.x - x2a*ss0.x)*sc, (x1b*cc0.y - x2b*ss0.y)*sc);
                    store_hl(H, L, i0 + 32, (x2a*cc0.x + x1a*ss0.x)*sc, (x2b*cc0.y + x1b*ss0.y)*sc);
                    x1a = c[mt][nt][2];     x1b = c[mt][nt][3];
                    x2a = c[mt][nt + 4][2]; x2b = c[mt][nt + 4][3];
                    int i1 = ((b1 * nh + h) * 2048 + t1) * 64 + d;
                    store_hl(H, L, i1,      (x1a*cc1.x - x2a*ss1.x)*sc, (x1b*cc1.y - x2b*ss1.y)*sc);
                    store_hl(H, L, i1 + 32, (x2a*cc1.x + x1a*ss1.x)*sc, (x2b*cc1.y + x1b*ss1.y)*sc);
                }
            }
        }
    }
}

// ---------------------------------------------------------------------------
// MMA flash attention (bf16x3, HMMA), pre-split K/V.
// XOR-swizzled 64x64 bf16 tiles (8 KB each, no padding), 2-stage double
// buffer, 3 CTAs/SM. Block = 128 (4 warps), 64 q rows per CTA.
// Stage = 4 arrays x 8192 B = 32768 B; 2 stages = 65536 B/CTA (3 CTAs: 196.6 KB).
// grid = (32, 32), heavy CTAs first.
// Smem layout per array: row*128 + ((chunk ^ (row&7)) * 16), chunk = 16B col.
// ---------------------------------------------------------------------------
__global__ void __launch_bounds__(128, 3) attn_kernel()
{
    extern __shared__ __align__(16) __nv_bfloat16 smem[];
    const uint32_t sbase = smem_u32(smem);

    const int tid  = threadIdx.x;
    const int lane = tid & 31;
    const int warp = tid >> 5;          // 0..3
    const int g    = lane >> 2;
    const int t4   = lane & 3;
    const int bh   = blockIdx.y;
    const int b    = bh >> 4, hh = bh & 15;
    const int kh   = hh >> 2;
    const int qt   = (int)gridDim.x - 1 - (int)blockIdx.x;   // heavy first

    const int r0 = qt * 64 + warp * 16 + g;
    const int r1 = r0 + 8;
    const int warp_min_row = qt * 64 + warp * 16;

    uint32_t qh[4][4], ql[4][4];
    {
        const __nv_bfloat16* q0h = g_qh + (bh * 2048 + r0) * 64;
        const __nv_bfloat16* q1h = g_qh + (bh * 2048 + r1) * 64;
        const __nv_bfloat16* q0l = g_ql + (bh * 2048 + r0) * 64;
        const __nv_bfloat16* q1l = g_ql + (bh * 2048 + r1) * 64;
        #pragma unroll
        for (int ks = 0; ks < 4; ks++) {
            int cb = ks * 16 + (t4 << 1);
            qh[ks][0] = *(const uint32_t*)(q0h + cb);
            qh[ks][1] = *(const uint32_t*)(q1h + cb);
            qh[ks][2] = *(const uint32_t*)(q0h + cb + 8);
            qh[ks][3] = *(const uint32_t*)(q1h + cb + 8);
            ql[ks][0] = *(const uint32_t*)(q0l + cb);
            ql[ks][1] = *(const uint32_t*)(q1l + cb);
            ql[ks][2] = *(const uint32_t*)(q0l + cb + 8);
            ql[ks][3] = *(const uint32_t*)(q1l + cb + 8);
        }
    }

    float o[8][4];
    #pragma unroll
    for (int nt = 0; nt < 8; nt++)
        #pragma unroll
        for (int i = 0; i < 4; i++) o[nt][i] = 0.f;
    float m0 = -1e30f, m1 = -1e30f, l0 = 0.f, l1 = 0.f;

    const __nv_bfloat16* src0 = g_kh + ((b * 4 + kh) * 2048) * 64;
    const __nv_bfloat16* src1 = g_kl + ((b * 4 + kh) * 2048) * 64;
    const __nv_bfloat16* src2 = g_vh + ((b * 4 + kh) * 2048) * 64;
    const __nv_bfloat16* src3 = g_vl + ((b * 4 + kh) * 2048) * 64;

    const int ntiles = qt + 1;

    // stage one K/V tile: 4 arrays x 512 16B chunks, XOR swizzle
    auto stage = [&](int kt, int buf) {
        const __nv_bfloat16* srcs[4] = {src0, src1, src2, src3};
        #pragma unroll
        for (int a = 0; a < 4; a++) {
            uint32_t dbase = sbase + (uint32_t)buf * 32768u + (uint32_t)a * 8192u;
            const __nv_bfloat16* sp = srcs[a] + kt * 4096;
            #pragma unroll
            for (int i = 0; i < 4; i++) {
                int u = tid + i * 128;          // 0..511
                int row = u >> 3, ch = u & 7;
                cpa16(dbase + (uint32_t)(row * 128) + (uint32_t)((ch ^ (row & 7)) << 4),
                      sp + u * 8);
            }
        }
        asm volatile("cp.async.commit_group;\n" ::: "memory");
    };

    stage(0, 0);
    if (ntiles > 1) stage(1, 1);

    for (int kt = 0; kt < ntiles; kt++) {
        int buf = kt & 1;
        if (kt == ntiles - 1) {
            asm volatile("cp.async.wait_group 0;\n" ::: "memory");
        } else {
            asm volatile("cp.async.wait_group 1;\n" ::: "memory");
        }
        __syncthreads();

        {
            const uint32_t bKh = sbase + (uint32_t)buf * 32768u;
            const uint32_t bKl = bKh + 8192u;
            const uint32_t bVh = bKh + 16384u;
            const uint32_t bVl = bKh + 24576u;

            float s[8][4];
            #pragma unroll
            for (int nt = 0; nt < 8; nt++)
                #pragma unroll
                for (int i = 0; i < 4; i++) s[nt][i] = 0.f;

            #pragma unroll
            for (int ks = 0; ks < 4; ks++) {
                uint32_t kbh[4][4], kbl[4][4];
                #pragma unroll
                for (int pr = 0; pr < 4; pr++) {
                    int n_idx = pr * 16 + (lane & 7) + ((lane >> 4) << 3);
                    int chv   = 2 * ks + ((lane >> 3) & 1);       // 16B chunk col
                    uint32_t off = (uint32_t)(n_idx * 128)
                                 + (uint32_t)((chv ^ (n_idx & 7)) << 4);
                    ldmx4(kbh[pr], bKh + off);
                    ldmx4(kbl[pr], bKl + off);
                }
                #pragma unroll
                for (int pr = 0; pr < 4; pr++)
                    #pragma unroll
                    for (int sub = 0; sub < 2; sub++) {
                        float* sc = s[pr * 2 + sub];
                        mma_bf16(sc, qh[ks], &kbh[pr][sub * 2]);
                        mma_bf16(sc, qh[ks], &kbl[pr][sub * 2]);
                        mma_bf16(sc, ql[ks], &kbh[pr][sub * 2]);
                    }
            }

            if (kt * 64 + 63 > warp_min_row) {
                #pragma unroll
                for (int nt = 0; nt < 8; nt++) {
                    int c0 = kt * 64 + nt * 8 + (t4 << 1);
                    if (c0     > r0) s[nt][0] = -1e30f;
                    if (c0 + 1 > r0) s[nt][1] = -1e30f;
                    if (c0     > r1) s[nt][2] = -1e30f;
                    if (c0 + 1 > r1) s[nt][3] = -1e30f;
                }
            }

            float t0 = -1e30f, t1 = -1e30f;
            #pragma unroll
            for (int nt = 0; nt < 8; nt++) {
                t0 = fmaxf(t0, fmaxf(s[nt][0], s[nt][1]));
                t1 = fmaxf(t1, fmaxf(s[nt][2], s[nt][3]));
            }
            t0 = fmaxf(t0, __shfl_xor_sync(0xffffffffu, t0, 1));
            t0 = fmaxf(t0, __shfl_xor_sync(0xffffffffu, t0, 2));
            t1 = fmaxf(t1, __shfl_xor_sync(0xffffffffu, t1, 1));
            t1 = fmaxf(t1, __shfl_xor_sync(0xffffffffu, t1, 2));

            float m0n = fmaxf(m0, t0), m1n = fmaxf(m1, t1);
            float c0f = ex2(m0 - m0n), c1f = ex2(m1 - m1n);
            m0 = m0n; m1 = m1n;

            float sum0 = 0.f, sum1 = 0.f;
            #pragma unroll
            for (int nt = 0; nt < 8; nt++) {
                float p0 = ex2(s[nt][0] - m0);
                float p1 = ex2(s[nt][1] - m0);
                float p2 = ex2(s[nt][2] - m1);
                float p3 = ex2(s[nt][3] - m1);
                sum0 += p0 + p1; sum1 += p2 + p3;
                s[nt][0] = p0; s[nt][1] = p1; s[nt][2] = p2; s[nt][3] = p3;
            }
            l0 = l0 * c0f + sum0;
            l1 = l1 * c1f + sum1;
            #pragma unroll
            for (int nt = 0; nt < 8; nt++) {
                o[nt][0] *= c0f; o[nt][1] *= c0f;
                o[nt][2] *= c1f; o[nt][3] *= c1f;
            }

            #pragma unroll
            for (int ks = 0; ks < 4; ks++) {
                uint32_t aPh[4], aPl[4];
                pack_hl(s[2*ks][0],   s[2*ks][1],   aPh[0], aPl[0]);
                pack_hl(s[2*ks][2],   s[2*ks][3],   aPh[1], aPl[1]);
                pack_hl(s[2*ks+1][0], s[2*ks+1][1], aPh[2], aPl[2]);
                pack_hl(s[2*ks+1][2], s[2*ks+1][3], aPh[3], aPl[3]);

                #pragma unroll
                for (int dp = 0; dp < 4; dp++) {
                    uint32_t vfh[4], vfl[4];
                    int row  = 16 * ks + (lane & 15);
                    int chv  = dp * 2 + (lane >> 4);              // 16B chunk col
                    uint32_t off = (uint32_t)(row * 128)
                                 + (uint32_t)((chv ^ (row & 7)) << 4);
                    ldmx4t(vfh, bVh + off);
                    ldmx4t(vfl, bVl + off);
                    #pragma unroll
                    for (int sub = 0; sub < 2; sub++) {
                        float* oc = o[dp * 2 + sub];
                        mma_bf16(oc, aPh, &vfh[sub * 2]);
                        mma_bf16(oc, aPh, &vfl[sub * 2]);
                        mma_bf16(oc, aPl, &vfh[sub * 2]);
                    }
                }
            }
        }

        // second barrier: all warps done reading this buffer before it is
        // overwritten by the stage below (2-slot ring needs it).
        __syncthreads();
        if (kt + 2 < ntiles) stage(kt + 2, buf);
    }

    l0 += __shfl_xor_sync(0xffffffffu, l0, 1);
    l0 += __shfl_xor_sync(0xffffffffu, l0, 2);
    l1 += __shfl_xor_sync(0xffffffffu, l1, 1);
    l1 += __shfl_xor_sync(0xffffffffu, l1, 2);
    float inv0 = 1.f / l0, inv1 = 1.f / l1;

    int y0 = (b * 2048 + r0) * 1024 + hh * 64;
    int y1 = (b * 2048 + r1) * 1024 + hh * 64;
    #pragma unroll
    for (int nt = 0; nt < 8; nt++) {
        int d = nt * 8 + (t4 << 1);
        store_hl(g_yh, g_yl, y0 + d, o[nt][0] * inv0, o[nt][1] * inv0);
        store_hl(g_yh, g_yl, y1 + d, o[nt][2] * inv1, o[nt][3] * inv1);
    }
}

// ---------------------------------------------------------------------------
// Launch: x, cos, sin, Wq, Wk, Wv, Wo. out = f32 [B,T,C].
// ---------------------------------------------------------------------------
extern "C" void kernel_launch(void* const* d_in, const int* in_sizes, int n_in,
                              void* d_out, int out_size)
{
    const float* x    = (const float*)d_in[0];
    const float* cosb = (const float*)d_in[1];
    const float* sinb = (const float*)d_in[2];
    const float* Wq   = (const float*)d_in[3];
    const float* Wk   = (const float*)d_in[4];
    const float* Wv   = (const float*)d_in[5];
    const float* Wo   = (const float*)d_in[6];
    float* out = (float*)d_out;

    static bool attr_set = false;
    if (!attr_set) {
        cudaFuncSetAttribute(attn_kernel,
                             cudaFuncAttributeMaxDynamicSharedMemorySize, 65536);
        cudaFuncSetAttribute(gemm_bf16<0>,
                             cudaFuncAttributeMaxDynamicSharedMemorySize, 113664);
        cudaFuncSetAttribute(gemm_bf16<1>,
                             cudaFuncAttributeMaxDynamicSharedMemorySize, 113664);
        attr_set = true;
    }

    // 0. one-shot fp32 -> bf16 hi/lo conversions
    cvt_x<<<4096, 256>>>(x);
    cvt_qkvw<<<1536, 256>>>(Wq, Wk, Wv);
    cvt_wo<<<1024, 256>>>(Wo);

    // 1. fused QKV projection + RoPE + scale (bf16x3, 3-stage ring, 2 CTAs/SM)
    gemm_bf16<0><<<dim3(12, 32), 256, 113664>>>(cosb, sinb, nullptr);

    // 2. causal flash attention (bf16x3, swizzled 2-stage, 3 CTAs/SM)
    attn_kernel<<<dim3(32, 32), 128, 65536>>>();

    // 3. output projection (3-stage ring, 2 CTAs/SM)
    gemm_bf16<1><<<dim3(8, 32), 256, 113664>>>(nullptr, nullptr, out);
}

// round 10
// speedup vs baseline: 1.3123x; 1.0887x over previous
#include <cuda_runtime.h>
#include <cuda_bf16.h>
#include <cuda_fp16.h>
#include <cstdint>

// ---------------------------------------------------------------------------
// GQA: B=2, T=2048, C=1024, H=16 q-heads, KVH=4 kv-heads, D=64, causal, RoPE
// GEMM operands bf16 hi/lo (x3 MMA); attention PV path fp16 (P x1, V hi/lo).
// (tcgen05 NOT available: harness ptxas targets sm_103 base. HMMA only.)
// ---------------------------------------------------------------------------

__device__ __align__(16) __nv_bfloat16 g_xh[4194304], g_xl[4194304];
__device__ __align__(16) __nv_bfloat16 g_wqkvh[1572864], g_wqkvl[1572864];
__device__ __align__(16) __nv_bfloat16 g_woh[1048576], g_wol[1048576];
__device__ __align__(16) __nv_bfloat16 g_qh[4194304], g_ql[4194304];
__device__ __align__(16) __nv_bfloat16 g_kh[1048576], g_kl[1048576];
__device__ __align__(16) __half       g_vh[1048576], g_vl[1048576];   // fp16!
__device__ __align__(16) __nv_bfloat16 g_yh[4194304], g_yl[4194304];

// ---------------------------------------------------------------------------
// helpers
// ---------------------------------------------------------------------------
__device__ __forceinline__ uint32_t smem_u32(const void* p) {
    return (uint32_t)__cvta_generic_to_shared(p);
}
__device__ __forceinline__ void ldmx4(uint32_t* r, uint32_t addr) {
    asm volatile("ldmatrix.sync.aligned.m8n8.x4.shared.b16 {%0,%1,%2,%3}, [%4];"
        : "=r"(r[0]), "=r"(r[1]), "=r"(r[2]), "=r"(r[3]) : "r"(addr));
}
__device__ __forceinline__ void ldmx4t(uint32_t* r, uint32_t addr) {
    asm volatile("ldmatrix.sync.aligned.m8n8.x4.trans.shared.b16 {%0,%1,%2,%3}, [%4];"
        : "=r"(r[0]), "=r"(r[1]), "=r"(r[2]), "=r"(r[3]) : "r"(addr));
}
__device__ __forceinline__ void mma_bf16(float* c, const uint32_t* a, const uint32_t* b) {
    asm volatile(
        "mma.sync.aligned.m16n8k16.row.col.f32.bf16.bf16.f32 "
        "{%0,%1,%2,%3}, {%4,%5,%6,%7}, {%8,%9}, {%0,%1,%2,%3};\n"
        : "+f"(c[0]), "+f"(c[1]), "+f"(c[2]), "+f"(c[3])
        : "r"(a[0]), "r"(a[1]), "r"(a[2]), "r"(a[3]), "r"(b[0]), "r"(b[1]));
}
__device__ __forceinline__ void mma_f16(float* c, const uint32_t* a, const uint32_t* b) {
    asm volatile(
        "mma.sync.aligned.m16n8k16.row.col.f32.f16.f16.f32 "
        "{%0,%1,%2,%3}, {%4,%5,%6,%7}, {%8,%9}, {%0,%1,%2,%3};\n"
        : "+f"(c[0]), "+f"(c[1]), "+f"(c[2]), "+f"(c[3])
        : "r"(a[0]), "r"(a[1]), "r"(a[2]), "r"(a[3]), "r"(b[0]), "r"(b[1]));
}
__device__ __forceinline__ float ex2(float x) {
    float r;
    asm("ex2.approx.f32 %0, %1;" : "=f"(r) : "f"(x));
    return r;
}
__device__ __forceinline__ void pack_hl(float x, float y, uint32_t& h, uint32_t& l) {
    __nv_bfloat162 hb, lb;
    __nv_bfloat16 hx = __float2bfloat16(x);
    hb.x = hx; lb.x = __float2bfloat16(x - __bfloat162float(hx));
    __nv_bfloat16 hy = __float2bfloat16(y);
    hb.y = hy; lb.y = __float2bfloat16(y - __bfloat162float(hy));
    h = *(uint32_t*)&hb; l = *(uint32_t*)&lb;
}
__device__ __forceinline__ void store_hl(__nv_bfloat16* H, __nv_bfloat16* L,
                                         int idx, float a, float b) {
    uint32_t h, l; pack_hl(a, b, h, l);
    *(uint32_t*)(H + idx) = h;
    *(uint32_t*)(L + idx) = l;
}
// fp16 hi/lo split store
__device__ __forceinline__ void store_hl16(__half* H, __half* L,
                                           int idx, float a, float b) {
    __half ha = __float2half_rn(a), hb = __float2half_rn(b);
    __half2 hv; hv.x = ha; hv.y = hb;
    __half2 lv;
    lv.x = __float2half_rn(a - __half2float(ha));
    lv.y = __float2half_rn(b - __half2float(hb));
    *(__half2*)(H + idx) = hv;
    *(__half2*)(L + idx) = lv;
}
__device__ __forceinline__ uint32_t pack_f16x2(float a, float b) {
    __half2 h = __floats2half2_rn(a, b);
    return *(uint32_t*)&h;
}
__device__ __forceinline__ void cpa16(uint32_t dst, const void* src) {
    asm volatile("cp.async.cg.shared.global [%0], [%1], 16;\n" :: "r"(dst), "l"(src));
}

#define SOFTMAX_SCALE (0.125f * 1.44269504088896f)  // 1/sqrt(64) * log2(e)

// ---------------------------------------------------------------------------
// Conversion kernels: fp32 -> bf16 hi/lo (one-shot, memory-bound)
// ---------------------------------------------------------------------------
__global__ void cvt_x(const float* __restrict__ src) {
    int i = blockIdx.x * blockDim.x + threadIdx.x;        // < 1048576
    float4 v = ((const float4*)src)[i];
    uint32_t h0, l0, h1, l1;
    pack_hl(v.x, v.y, h0, l0);
    pack_hl(v.z, v.w, h1, l1);
    uint2 hv; hv.x = h0; hv.y = h1;
    uint2 lv; lv.x = l0; lv.y = l1;
    ((uint2*)g_xh)[i] = hv; ((uint2*)g_xl)[i] = lv;
}
__global__ void cvt_wo(const float* __restrict__ src) {
    int i = blockIdx.x * blockDim.x + threadIdx.x;        // < 262144
    float4 v = ((const float4*)src)[i];
    uint32_t h0, l0, h1, l1;
    pack_hl(v.x, v.y, h0, l0);
    pack_hl(v.z, v.w, h1, l1);
    uint2 hv; hv.x = h0; hv.y = h1;
    uint2 lv; lv.x = l0; lv.y = l1;
    ((uint2*)g_woh)[i] = hv; ((uint2*)g_wol)[i] = lv;
}
__global__ void cvt_qkvw(const float* __restrict__ Wq,
                         const float* __restrict__ Wk,
                         const float* __restrict__ Wv) {
    int i = blockIdx.x * blockDim.x + threadIdx.x;        // < 393216
    int k = i / 384;
    int n = (i % 384) * 4;
    float4 v;
    if (n < 1024)      v = *(const float4*)(Wq + k * 1024 + n);
    else if (n < 1280) v = *(const float4*)(Wk + k * 256 + n - 1024);
    else               v = *(const float4*)(Wv + k * 256 + n - 1280);
    uint32_t h0, l0, h1, l1;
    pack_hl(v.x, v.y, h0, l0);
    pack_hl(v.z, v.w, h1, l1);
    uint2 hv; hv.x = h0; hv.y = h1;
    uint2 lv; lv.x = l0; lv.y = l1;
    int o = k * 1536 + n;
    *(uint2*)(g_wqkvh + o) = hv; *(uint2*)(g_wqkvl + o) = lv;
}

// ---------------------------------------------------------------------------
// bf16x3 GEMM, pre-split operands, 3-stage cp.async ring (ONE sync per slab),
// 2 CTAs/SM. Tile 128x128, BK=32, 8 warps (4x2), 2x8 frags/warp, x3 MMAs.
// MODE 0: A=g_x, B=g_wqkv (ldn=1536); epilogue RoPE(+scale) -> q/k bf16, v fp16
// MODE 1: A=g_y,  B=g_wo  (ldn=1024); epilogue fp32 -> Cout
// ---------------------------------------------------------------------------
template<int MODE>
__global__ void __launch_bounds__(256, 2) gemm_bf16(
    const float* __restrict__ cosb,
    const float* __restrict__ sinb,
    float* __restrict__ Cout)
{
    extern __shared__ __align__(16) __nv_bfloat16 sm[];
    const uint32_t sbase = smem_u32(sm);
    const int ldn = (MODE == 0) ? 1536 : 1024;

    const __nv_bfloat16* Ah = (MODE == 0) ? g_xh : g_yh;
    const __nv_bfloat16* Al = (MODE == 0) ? g_xl : g_yl;
    const __nv_bfloat16* Bh = (MODE == 0) ? g_wqkvh : g_woh;
    const __nv_bfloat16* Bl = (MODE == 0) ? g_wqkvl : g_wol;

    const int tid  = threadIdx.x;
    const int lane = tid & 31;
    const int warp = tid >> 5;
    const int wm   = warp >> 1;
    const int wn   = warp & 1;
    const int brow = blockIdx.y * 128;
    const int bcol = blockIdx.x * 128;
    const int t4   = lane & 3;

    float c[2][8][4];
    #pragma unroll
    for (int mt = 0; mt < 2; mt++)
        #pragma unroll
        for (int nt = 0; nt < 8; nt++)
            #pragma unroll
            for (int i = 0; i < 4; i++) c[mt][nt][i] = 0.f;

    auto stage = [&](int ki, int buf) {
        int kb = ki * 32;
        uint32_t base = sbase + (uint32_t)buf * 37888u;
        #pragma unroll
        for (int i = 0; i < 2; i++) {
            int u   = tid + i * 256;
            int ar  = u >> 2, ac8 = (u & 3) << 3;
            cpa16(base + (uint32_t)(ar * 40 + ac8) * 2u,
                  Ah + (brow + ar) * 1024 + kb + ac8);
            cpa16(base + (uint32_t)(5120 + ar * 40 + ac8) * 2u,
                  Al + (brow + ar) * 1024 + kb + ac8);
            int br2 = u >> 4, bc8 = (u & 15) << 3;
            cpa16(base + (uint32_t)(10240 + br2 * 136 + bc8) * 2u,
                  Bh + (kb + br2) * ldn + bcol + bc8);
            cpa16(base + (uint32_t)(14592 + br2 * 136 + bc8) * 2u,
                  Bl + (kb + br2) * ldn + bcol + bc8);
        }
        asm volatile("cp.async.commit_group;\n" ::: "memory");
    };

    stage(0, 0);
    stage(1, 1);

    for (int ki = 0; ki < 32; ki++) {
        int buf = ki % 3;
        if (ki == 31) {
            asm volatile("cp.async.wait_group 0;\n" ::: "memory");
        } else {
            asm volatile("cp.async.wait_group 1;\n" ::: "memory");
        }
        __syncthreads();

        uint32_t bAh = sbase + (uint32_t)buf * 37888u;
        uint32_t bAl = bAh + 10240u;
        uint32_t bBh = bAh + 20480u;
        uint32_t bBl = bAh + 29184u;

        #pragma unroll
        for (int ks = 0; ks < 2; ks++) {
            uint32_t aH[2][4], aL[2][4], bH[4][4], bL[4][4];
            #pragma unroll
            for (int mt = 0; mt < 2; mt++) {
                uint32_t off = 2u * ((uint32_t)(wm * 32 + mt * 16 + (lane & 15)) * 40
                                     + ks * 16 + ((lane >> 4) << 3));
                ldmx4(aH[mt], bAh + off);
                ldmx4(aL[mt], bAl + off);
            }
            #pragma unroll
            for (int np = 0; np < 4; np++) {
                uint32_t off = 2u * ((uint32_t)(ks * 16 + (lane & 15)) * 136
                                     + wn * 64 + np * 16 + ((lane >> 4) << 3));
                ldmx4t(bH[np], bBh + off);
                ldmx4t(bL[np], bBl + off);
            }
            #pragma unroll
            for (int mt = 0; mt < 2; mt++)
                #pragma unroll
                for (int nt = 0; nt < 8; nt++) {
                    const uint32_t* bh = &bH[nt >> 1][(nt & 1) * 2];
                    const uint32_t* bl = &bL[nt >> 1][(nt & 1) * 2];
                    mma_bf16(c[mt][nt], aH[mt], bh);
                    mma_bf16(c[mt][nt], aH[mt], bl);
                    mma_bf16(c[mt][nt], aL[mt], bh);
                }
        }

        if (ki + 2 < 32) stage(ki + 2, (ki + 2) % 3);
    }

    if (MODE == 1) {
        #pragma unroll
        for (int mt = 0; mt < 2; mt++) {
            int r0 = brow + wm * 32 + mt * 16 + (lane >> 2);
            #pragma unroll
            for (int nt = 0; nt < 8; nt++) {
                int cc = bcol + wn * 64 + nt * 8 + (t4 << 1);
                float2 v0; v0.x = c[mt][nt][0]; v0.y = c[mt][nt][1];
                float2 v1; v1.x = c[mt][nt][2]; v1.y = c[mt][nt][3];
                *(float2*)(Cout + r0 * 1024 + cc)       = v0;
                *(float2*)(Cout + (r0 + 8) * 1024 + cc) = v1;
            }
        }
    } else {
        int region = (bcol < 1024) ? 0 : (bcol < 1280 ? 1 : 2);
        #pragma unroll
        for (int mt = 0; mt < 2; mt++) {
            int r0 = brow + wm * 32 + mt * 16 + (lane >> 2);
            int r1 = r0 + 8;
            int b0 = r0 >> 11, t0 = r0 & 2047;
            int b1 = r1 >> 11, t1 = r1 & 2047;
            if (region == 2) {
                int colb = bcol - 1280 + wn * 64;
                int h = colb >> 6;
                #pragma unroll
                for (int nt = 0; nt < 8; nt++) {
                    int d = nt * 8 + (t4 << 1);
                    int i0 = ((b0 * 4 + h) * 2048 + t0) * 64 + d;
                    int i1 = ((b1 * 4 + h) * 2048 + t1) * 64 + d;
                    store_hl16(g_vh, g_vl, i0, c[mt][nt][0], c[mt][nt][1]);
                    store_hl16(g_vh, g_vl, i1, c[mt][nt][2], c[mt][nt][3]);
                }
            } else {
                int colb = (region == 0) ? bcol + wn * 64 : bcol - 1024 + wn * 64;
                int h = colb >> 6;
                __nv_bfloat16* H = (region == 0) ? g_qh : g_kh;
                __nv_bfloat16* L = (region == 0) ? g_ql : g_kl;
                int nh   = (region == 0) ? 16 : 4;
                float sc = (region == 0) ? SOFTMAX_SCALE : 1.f;
                #pragma unroll
                for (int nt = 0; nt < 4; nt++) {
                    int d = nt * 8 + (t4 << 1);
                    float2 cc0 = *(const float2*)(cosb + t0 * 32 + d);
                    float2 ss0 = *(const float2*)(sinb + t0 * 32 + d);
                    float2 cc1 = *(const float2*)(cosb + t1 * 32 + d);
                    float2 ss1 = *(const float2*)(sinb + t1 * 32 + d);
                    float x1a = c[mt][nt][0],     x1b = c[mt][nt][1];
                    float x2a = c[mt][nt + 4][0], x2b = c[mt][nt + 4][1];
                    int i0 = ((b0 * nh + h) * 2048 + t0) * 64 + d;
                    store_hl(H, L, i0,      (x1a*cc0.x - x2a*ss0.x)*sc, (x1b*cc0.y - x2b*ss0.y)*sc);
                    store_hl(H, L, i0 + 32, (x2a*cc0.x + x1a*ss0.x)*sc, (x2b*cc0.y + x1b*ss0.y)*sc);
                    x1a = c[mt][nt][2];     x1b = c[mt][nt][3];
                    x2a = c[mt][nt + 4][2]; x2b = c[mt][nt + 4][3];
                    int i1 = ((b1 * nh + h) * 2048 + t1) * 64 + d;
                    store_hl(H, L, i1,      (x1a*cc1.x - x2a*ss1.x)*sc, (x1b*cc1.y - x2b*ss1.y)*sc);
                    store_hl(H, L, i1 + 32, (x2a*cc1.x + x1a*ss1.x)*sc, (x2b*cc1.y + x1b*ss1.y)*sc);
                }
            }
        }
    }
}

// ---------------------------------------------------------------------------
// MMA flash attention: QK bf16x3 (HMMA), PV fp16 (P x1, V hi/lo -> 2 MMAs).
// XOR-swizzled 64x64 tiles (8 KB each), 2-stage double buffer, 3 CTAs/SM.
// Block = 128 (4 warps), 64 q rows per CTA. grid = (32, 32), heavy first.
// ---------------------------------------------------------------------------
__global__ void __launch_bounds__(128, 3) attn_kernel()
{
    extern __shared__ __align__(16) __nv_bfloat16 smem[];
    const uint32_t sbase = smem_u32(smem);

    const int tid  = threadIdx.x;
    const int lane = tid & 31;
    const int warp = tid >> 5;          // 0..3
    const int g    = lane >> 2;
    const int t4   = lane & 3;
    const int bh   = blockIdx.y;
    const int b    = bh >> 4, hh = bh & 15;
    const int kh   = hh >> 2;
    const int qt   = (int)gridDim.x - 1 - (int)blockIdx.x;   // heavy first

    const int r0 = qt * 64 + warp * 16 + g;
    const int r1 = r0 + 8;
    const int warp_min_row = qt * 64 + warp * 16;

    uint32_t qh[4][4], ql[4][4];
    {
        const __nv_bfloat16* q0h = g_qh + (bh * 2048 + r0) * 64;
        const __nv_bfloat16* q1h = g_qh + (bh * 2048 + r1) * 64;
        const __nv_bfloat16* q0l = g_ql + (bh * 2048 + r0) * 64;
        const __nv_bfloat16* q1l = g_ql + (bh * 2048 + r1) * 64;
        #pragma unroll
        for (int ks = 0; ks < 4; ks++) {
            int cb = ks * 16 + (t4 << 1);
            qh[ks][0] = *(const uint32_t*)(q0h + cb);
            qh[ks][1] = *(const uint32_t*)(q1h + cb);
            qh[ks][2] = *(const uint32_t*)(q0h + cb + 8);
            qh[ks][3] = *(const uint32_t*)(q1h + cb + 8);
            ql[ks][0] = *(const uint32_t*)(q0l + cb);
            ql[ks][1] = *(const uint32_t*)(q1l + cb);
            ql[ks][2] = *(const uint32_t*)(q0l + cb + 8);
            ql[ks][3] = *(const uint32_t*)(q1l + cb + 8);
        }
    }

    float o[8][4];
    #pragma unroll
    for (int nt = 0; nt < 8; nt++)
        #pragma unroll
        for (int i = 0; i < 4; i++) o[nt][i] = 0.f;
    float m0 = -1e30f, m1 = -1e30f, l0 = 0.f, l1 = 0.f;

    const __nv_bfloat16* src0 = g_kh + ((b * 4 + kh) * 2048) * 64;
    const __nv_bfloat16* src1 = g_kl + ((b * 4 + kh) * 2048) * 64;
    const __half*        src2 = g_vh + ((b * 4 + kh) * 2048) * 64;
    const __half*        src3 = g_vl + ((b * 4 + kh) * 2048) * 64;

    const int ntiles = qt + 1;

    // stage one K/V tile: 4 arrays x 512 16B chunks, XOR swizzle
    auto stage = [&](int kt, int buf) {
        uint32_t base = sbase + (uint32_t)buf * 32768u;
        #pragma unroll
        for (int i = 0; i < 4; i++) {
            int u = tid + i * 128;          // 0..511
            int row = u >> 3, ch = u & 7;
            uint32_t sw = (uint32_t)(row * 128) + (uint32_t)((ch ^ (row & 7)) << 4);
            cpa16(base +           sw, src0 + kt * 4096 + u * 8);
            cpa16(base +  8192u  + sw, src1 + kt * 4096 + u * 8);
            cpa16(base + 16384u  + sw, src2 + kt * 4096 + u * 8);
            cpa16(base + 24576u  + sw, src3 + kt * 4096 + u * 8);
        }
        asm volatile("cp.async.commit_group;\n" ::: "memory");
    };

    stage(0, 0);
    if (ntiles > 1) stage(1, 1);

    for (int kt = 0; kt < ntiles; kt++) {
        int buf = kt & 1;
        if (kt == ntiles - 1) {
            asm volatile("cp.async.wait_group 0;\n" ::: "memory");
        } else {
            asm volatile("cp.async.wait_group 1;\n" ::: "memory");
        }
        __syncthreads();

        {
            const uint32_t bKh = sbase + (uint32_t)buf * 32768u;
            const uint32_t bKl = bKh + 8192u;
            const uint32_t bVh = bKh + 16384u;
            const uint32_t bVl = bKh + 24576u;

            float s[8][4];
            #pragma unroll
            for (int nt = 0; nt < 8; nt++)
                #pragma unroll
                for (int i = 0; i < 4; i++) s[nt][i] = 0.f;

            #pragma unroll
            for (int ks = 0; ks < 4; ks++) {
                uint32_t kbh[4][4], kbl[4][4];
                #pragma unroll
                for (int pr = 0; pr < 4; pr++) {
                    int n_idx = pr * 16 + (lane & 7) + ((lane >> 4) << 3);
                    int chv   = 2 * ks + ((lane >> 3) & 1);       // 16B chunk col
                    uint32_t off = (uint32_t)(n_idx * 128)
                                 + (uint32_t)((chv ^ (n_idx & 7)) << 4);
                    ldmx4(kbh[pr], bKh + off);
                    ldmx4(kbl[pr], bKl + off);
                }
                #pragma unroll
                for (int pr = 0; pr < 4; pr++)
                    #pragma unroll
                    for (int sub = 0; sub < 2; sub++) {
                        float* sc = s[pr * 2 + sub];
                        mma_bf16(sc, qh[ks], &kbh[pr][sub * 2]);
                        mma_bf16(sc, qh[ks], &kbl[pr][sub * 2]);
                        mma_bf16(sc, ql[ks], &kbh[pr][sub * 2]);
                    }
            }

            if (kt * 64 + 63 > warp_min_row) {
                #pragma unroll
                for (int nt = 0; nt < 8; nt++) {
                    int c0 = kt * 64 + nt * 8 + (t4 << 1);
                    if (c0     > r0) s[nt][0] = -1e30f;
                    if (c0 + 1 > r0) s[nt][1] = -1e30f;
                    if (c0     > r1) s[nt][2] = -1e30f;
                    if (c0 + 1 > r1) s[nt][3] = -1e30f;
                }
            }

            float t0 = -1e30f, t1 = -1e30f;
            #pragma unroll
            for (int nt = 0; nt < 8; nt++) {
                t0 = fmaxf(t0, fmaxf(s[nt][0], s[nt][1]));
                t1 = fmaxf(t1, fmaxf(s[nt][2], s[nt][3]));
            }
            t0 = fmaxf(t0, __shfl_xor_sync(0xffffffffu, t0, 1));
            t0 = fmaxf(t0, __shfl_xor_sync(0xffffffffu, t0, 2));
            t1 = fmaxf(t1, __shfl_xor_sync(0xffffffffu, t1, 1));
            t1 = fmaxf(t1, __shfl_xor_sync(0xffffffffu, t1, 2));

            float m0n = fmaxf(m0, t0), m1n = fmaxf(m1, t1);
            float c0f = ex2(m0 - m0n), c1f = ex2(m1 - m1n);
            m0 = m0n; m1 = m1n;

            float sum0 = 0.f, sum1 = 0.f;
            #pragma unroll
            for (int nt = 0; nt < 8; nt++) {
                float p0 = ex2(s[nt][0] - m0);
                float p1 = ex2(s[nt][1] - m0);
                float p2 = ex2(s[nt][2] - m1);
                float p3 = ex2(s[nt][3] - m1);
                sum0 += p0 + p1; sum1 += p2 + p3;
                s[nt][0] = p0; s[nt][1] = p1; s[nt][2] = p2; s[nt][3] = p3;
            }
            l0 = l0 * c0f + sum0;
            l1 = l1 * c1f + sum1;
            #pragma unroll
            for (int nt = 0; nt < 8; nt++) {
                o[nt][0] *= c0f; o[nt][1] *= c0f;
                o[nt][2] *= c1f; o[nt][3] *= c1f;
            }

            // ---- O += P V (P single fp16, V fp16 hi/lo -> 2 MMAs/frag) ----
            #pragma unroll
            for (int ks = 0; ks < 4; ks++) {
                uint32_t aP[4];
                aP[0] = pack_f16x2(s[2*ks][0],   s[2*ks][1]);
                aP[1] = pack_f16x2(s[2*ks][2],   s[2*ks][3]);
                aP[2] = pack_f16x2(s[2*ks+1][0], s[2*ks+1][1]);
                aP[3] = pack_f16x2(s[2*ks+1][2], s[2*ks+1][3]);

                #pragma unroll
                for (int dp = 0; dp < 4; dp++) {
                    uint32_t vfh[4], vfl[4];
                    int row  = 16 * ks + (lane & 15);
                    int chv  = dp * 2 + (lane >> 4);
                    uint32_t off = (uint32_t)(row * 128)
                                 + (uint32_t)((chv ^ (row & 7)) << 4);
                    ldmx4t(vfh, bVh + off);
                    ldmx4t(vfl, bVl + off);
                    #pragma unroll
                    for (int sub = 0; sub < 2; sub++) {
                        float* oc = o[dp * 2 + sub];
                        mma_f16(oc, aP, &vfh[sub * 2]);
                        mma_f16(oc, aP, &vfl[sub * 2]);
                    }
                }
            }
        }

        __syncthreads();
        if (kt + 2 < ntiles) stage(kt + 2, buf);
    }

    l0 += __shfl_xor_sync(0xffffffffu, l0, 1);
    l0 += __shfl_xor_sync(0xffffffffu, l0, 2);
    l1 += __shfl_xor_sync(0xffffffffu, l1, 1);
    l1 += __shfl_xor_sync(0xffffffffu, l1, 2);
    float inv0 = 1.f / l0, inv1 = 1.f / l1;

    int y0 = (b * 2048 + r0) * 1024 + hh * 64;
    int y1 = (b * 2048 + r1) * 1024 + hh * 64;
    #pragma unroll
    for (int nt = 0; nt < 8; nt++) {
        int d = nt * 8 + (t4 << 1);
        store_hl(g_yh, g_yl, y0 + d, o[nt][0] * inv0, o[nt][1] * inv0);
        store_hl(g_yh, g_yl, y1 + d, o[nt][2] * inv1, o[nt][3] * inv1);
    }
}

// ---------------------------------------------------------------------------
// Launch: x, cos, sin, Wq, Wk, Wv, Wo. out = f32 [B,T,C].
// ---------------------------------------------------------------------------
extern "C" void kernel_launch(void* const* d_in, const int* in_sizes, int n_in,
                              void* d_out, int out_size)
{
    const float* x    = (const float*)d_in[0];
    const float* cosb = (const float*)d_in[1];
    const float* sinb = (const float*)d_in[2];
    const float* Wq   = (const float*)d_in[3];
    const float* Wk   = (const float*)d_in[4];
    const float* Wv   = (const float*)d_in[5];
    const float* Wo   = (const float*)d_in[6];
    float* out = (float*)d_out;

    static bool attr_set = false;
    if (!attr_set) {
        cudaFuncSetAttribute(attn_kernel,
                             cudaFuncAttributeMaxDynamicSharedMemorySize, 65536);
        cudaFuncSetAttribute(gemm_bf16<0>,
                             cudaFuncAttributeMaxDynamicSharedMemorySize, 113664);
        cudaFuncSetAttribute(gemm_bf16<1>,
                             cudaFuncAttributeMaxDynamicSharedMemorySize, 113664);
        attr_set = true;
    }

    // 0. one-shot fp32 -> bf16 hi/lo conversions
    cvt_x<<<4096, 256>>>(x);
    cvt_qkvw<<<1536, 256>>>(Wq, Wk, Wv);
    cvt_wo<<<1024, 256>>>(Wo);

    // 1. fused QKV projection + RoPE + scale (bf16x3, 3-stage ring, 2 CTAs/SM)
    gemm_bf16<0><<<dim3(12, 32), 256, 113664>>>(cosb, sinb, nullptr);

    // 2. causal flash attention (QK bf16x3, PV fp16 x2; 3 CTAs/SM)
    attn_kernel<<<dim3(32, 32), 128, 65536>>>();

    // 3. output projection (3-stage ring, 2 CTAs/SM)
    gemm_bf16<1><<<dim3(8, 32), 256, 113664>>>(nullptr, nullptr, out);
}

// round 11
// speedup vs baseline: 1.3998x; 1.0666x over previous
#include <cuda_runtime.h>
#include <cuda_bf16.h>
#include <cuda_fp16.h>
#include <cstdint>

// ---------------------------------------------------------------------------
// GQA: B=2, T=2048, C=1024, H=16 q-heads, KVH=4 kv-heads, D=64, causal, RoPE
// GEMM operands bf16 hi/lo (x3 MMA); attention: QK bf16x3, P fp16, V fp16 x1.
// (tcgen05 NOT available: harness ptxas targets sm_103 base. HMMA only.)
// ---------------------------------------------------------------------------

__device__ __align__(16) __nv_bfloat16 g_xh[4194304], g_xl[4194304];
__device__ __align__(16) __nv_bfloat16 g_wqkvh[1572864], g_wqkvl[1572864];
__device__ __align__(16) __nv_bfloat16 g_woh[1048576], g_wol[1048576];
__device__ __align__(16) __nv_bfloat16 g_qh[4194304], g_ql[4194304];
__device__ __align__(16) __nv_bfloat16 g_kh[1048576], g_kl[1048576];
__device__ __align__(16) __half       g_vh[1048576];                  // fp16 x1
__device__ __align__(16) __nv_bfloat16 g_yh[4194304], g_yl[4194304];

// ---------------------------------------------------------------------------
// helpers
// ---------------------------------------------------------------------------
__device__ __forceinline__ uint32_t smem_u32(const void* p) {
    return (uint32_t)__cvta_generic_to_shared(p);
}
__device__ __forceinline__ void ldmx4(uint32_t* r, uint32_t addr) {
    asm volatile("ldmatrix.sync.aligned.m8n8.x4.shared.b16 {%0,%1,%2,%3}, [%4];"
        : "=r"(r[0]), "=r"(r[1]), "=r"(r[2]), "=r"(r[3]) : "r"(addr));
}
__device__ __forceinline__ void ldmx4t(uint32_t* r, uint32_t addr) {
    asm volatile("ldmatrix.sync.aligned.m8n8.x4.trans.shared.b16 {%0,%1,%2,%3}, [%4];"
        : "=r"(r[0]), "=r"(r[1]), "=r"(r[2]), "=r"(r[3]) : "r"(addr));
}
__device__ __forceinline__ void mma_bf16(float* c, const uint32_t* a, const uint32_t* b) {
    asm volatile(
        "mma.sync.aligned.m16n8k16.row.col.f32.bf16.bf16.f32 "
        "{%0,%1,%2,%3}, {%4,%5,%6,%7}, {%8,%9}, {%0,%1,%2,%3};\n"
        : "+f"(c[0]), "+f"(c[1]), "+f"(c[2]), "+f"(c[3])
        : "r"(a[0]), "r"(a[1]), "r"(a[2]), "r"(a[3]), "r"(b[0]), "r"(b[1]));
}
__device__ __forceinline__ void mma_f16(float* c, const uint32_t* a, const uint32_t* b) {
    asm volatile(
        "mma.sync.aligned.m16n8k16.row.col.f32.f16.f16.f32 "
        "{%0,%1,%2,%3}, {%4,%5,%6,%7}, {%8,%9}, {%0,%1,%2,%3};\n"
        : "+f"(c[0]), "+f"(c[1]), "+f"(c[2]), "+f"(c[3])
        : "r"(a[0]), "r"(a[1]), "r"(a[2]), "r"(a[3]), "r"(b[0]), "r"(b[1]));
}
__device__ __forceinline__ float ex2(float x) {
    float r;
    asm("ex2.approx.f32 %0, %1;" : "=f"(r) : "f"(x));
    return r;
}
__device__ __forceinline__ void pack_hl(float x, float y, uint32_t& h, uint32_t& l) {
    __nv_bfloat162 hb, lb;
    __nv_bfloat16 hx = __float2bfloat16(x);
    hb.x = hx; lb.x = __float2bfloat16(x - __bfloat162float(hx));
    __nv_bfloat16 hy = __float2bfloat16(y);
    hb.y = hy; lb.y = __float2bfloat16(y - __bfloat162float(hy));
    h = *(uint32_t*)&hb; l = *(uint32_t*)&lb;
}
__device__ __forceinline__ void store_hl(__nv_bfloat16* H, __nv_bfloat16* L,
                                         int idx, float a, float b) {
    uint32_t h, l; pack_hl(a, b, h, l);
    *(uint32_t*)(H + idx) = h;
    *(uint32_t*)(L + idx) = l;
}
__device__ __forceinline__ void store_h16(__half* H, int idx, float a, float b) {
    __half2 hv = __floats2half2_rn(a, b);
    *(__half2*)(H + idx) = hv;
}
__device__ __forceinline__ uint32_t pack_f16x2(float a, float b) {
    __half2 h = __floats2half2_rn(a, b);
    return *(uint32_t*)&h;
}
__device__ __forceinline__ void cpa16(uint32_t dst, const void* src) {
    asm volatile("cp.async.cg.shared.global [%0], [%1], 16;\n" :: "r"(dst), "l"(src));
}

#define SOFTMAX_SCALE (0.125f * 1.44269504088896f)  // 1/sqrt(64) * log2(e)

// ---------------------------------------------------------------------------
// Conversion kernels: fp32 -> bf16 hi/lo (one-shot, memory-bound)
// ---------------------------------------------------------------------------
__global__ void cvt_x(const float* __restrict__ src) {
    int i = blockIdx.x * blockDim.x + threadIdx.x;        // < 1048576
    float4 v = ((const float4*)src)[i];
    uint32_t h0, l0, h1, l1;
    pack_hl(v.x, v.y, h0, l0);
    pack_hl(v.z, v.w, h1, l1);
    uint2 hv; hv.x = h0; hv.y = h1;
    uint2 lv; lv.x = l0; lv.y = l1;
    ((uint2*)g_xh)[i] = hv; ((uint2*)g_xl)[i] = lv;
}
__global__ void cvt_wo(const float* __restrict__ src) {
    int i = blockIdx.x * blockDim.x + threadIdx.x;        // < 262144
    float4 v = ((const float4*)src)[i];
    uint32_t h0, l0, h1, l1;
    pack_hl(v.x, v.y, h0, l0);
    pack_hl(v.z, v.w, h1, l1);
    uint2 hv; hv.x = h0; hv.y = h1;
    uint2 lv; lv.x = l0; lv.y = l1;
    ((uint2*)g_woh)[i] = hv; ((uint2*)g_wol)[i] = lv;
}
__global__ void cvt_qkvw(const float* __restrict__ Wq,
                         const float* __restrict__ Wk,
                         const float* __restrict__ Wv) {
    int i = blockIdx.x * blockDim.x + threadIdx.x;        // < 393216
    int k = i / 384;
    int n = (i % 384) * 4;
    float4 v;
    if (n < 1024)      v = *(const float4*)(Wq + k * 1024 + n);
    else if (n < 1280) v = *(const float4*)(Wk + k * 256 + n - 1024);
    else               v = *(const float4*)(Wv + k * 256 + n - 1280);
    uint32_t h0, l0, h1, l1;
    pack_hl(v.x, v.y, h0, l0);
    pack_hl(v.z, v.w, h1, l1);
    uint2 hv; hv.x = h0; hv.y = h1;
    uint2 lv; lv.x = l0; lv.y = l1;
    int o = k * 1536 + n;
    *(uint2*)(g_wqkvh + o) = hv; *(uint2*)(g_wqkvl + o) = lv;
}

// ---------------------------------------------------------------------------
// bf16x3 GEMM, pre-split operands, 3-stage cp.async ring (ONE sync per slab),
// 2 CTAs/SM. Tile 128x128, BK=32, 8 warps (4x2), 2x8 frags/warp, x3 MMAs.
// MODE 0: A=g_x, B=g_wqkv (ldn=1536); epilogue RoPE(+scale) -> q/k bf16 hi/lo,
//         v single fp16.
// MODE 1: A=g_y,  B=g_wo  (ldn=1024); epilogue fp32 -> Cout
// ---------------------------------------------------------------------------
template<int MODE>
__global__ void __launch_bounds__(256, 2) gemm_bf16(
    const float* __restrict__ cosb,
    const float* __restrict__ sinb,
    float* __restrict__ Cout)
{
    extern __shared__ __align__(16) __nv_bfloat16 sm[];
    const uint32_t sbase = smem_u32(sm);
    const int ldn = (MODE == 0) ? 1536 : 1024;

    const __nv_bfloat16* Ah = (MODE == 0) ? g_xh : g_yh;
    const __nv_bfloat16* Al = (MODE == 0) ? g_xl : g_yl;
    const __nv_bfloat16* Bh = (MODE == 0) ? g_wqkvh : g_woh;
    const __nv_bfloat16* Bl = (MODE == 0) ? g_wqkvl : g_wol;

    const int tid  = threadIdx.x;
    const int lane = tid & 31;
    const int warp = tid >> 5;
    const int wm   = warp >> 1;
    const int wn   = warp & 1;
    const int brow = blockIdx.y * 128;
    const int bcol = blockIdx.x * 128;
    const int t4   = lane & 3;

    float c[2][8][4];
    #pragma unroll
    for (int mt = 0; mt < 2; mt++)
        #pragma unroll
        for (int nt = 0; nt < 8; nt++)
            #pragma unroll
            for (int i = 0; i < 4; i++) c[mt][nt][i] = 0.f;

    auto stage = [&](int ki, int buf) {
        int kb = ki * 32;
        uint32_t base = sbase + (uint32_t)buf * 37888u;
        #pragma unroll
        for (int i = 0; i < 2; i++) {
            int u   = tid + i * 256;
            int ar  = u >> 2, ac8 = (u & 3) << 3;
            cpa16(base + (uint32_t)(ar * 40 + ac8) * 2u,
                  Ah + (brow + ar) * 1024 + kb + ac8);
            cpa16(base + (uint32_t)(5120 + ar * 40 + ac8) * 2u,
                  Al + (brow + ar) * 1024 + kb + ac8);
            int br2 = u >> 4, bc8 = (u & 15) << 3;
            cpa16(base + (uint32_t)(10240 + br2 * 136 + bc8) * 2u,
                  Bh + (kb + br2) * ldn + bcol + bc8);
            cpa16(base + (uint32_t)(14592 + br2 * 136 + bc8) * 2u,
                  Bl + (kb + br2) * ldn + bcol + bc8);
        }
        asm volatile("cp.async.commit_group;\n" ::: "memory");
    };

    stage(0, 0);
    stage(1, 1);

    for (int ki = 0; ki < 32; ki++) {
        int buf = ki % 3;
        if (ki == 31) {
            asm volatile("cp.async.wait_group 0;\n" ::: "memory");
        } else {
            asm volatile("cp.async.wait_group 1;\n" ::: "memory");
        }
        __syncthreads();

        uint32_t bAh = sbase + (uint32_t)buf * 37888u;
        uint32_t bAl = bAh + 10240u;
        uint32_t bBh = bAh + 20480u;
        uint32_t bBl = bAh + 29184u;

        #pragma unroll
        for (int ks = 0; ks < 2; ks++) {
            uint32_t aH[2][4], aL[2][4], bH[4][4], bL[4][4];
            #pragma unroll
            for (int mt = 0; mt < 2; mt++) {
                uint32_t off = 2u * ((uint32_t)(wm * 32 + mt * 16 + (lane & 15)) * 40
                                     + ks * 16 + ((lane >> 4) << 3));
                ldmx4(aH[mt], bAh + off);
                ldmx4(aL[mt], bAl + off);
            }
            #pragma unroll
            for (int np = 0; np < 4; np++) {
                uint32_t off = 2u * ((uint32_t)(ks * 16 + (lane & 15)) * 136
                                     + wn * 64 + np * 16 + ((lane >> 4) << 3));
                ldmx4t(bH[np], bBh + off);
                ldmx4t(bL[np], bBl + off);
            }
            #pragma unroll
            for (int mt = 0; mt < 2; mt++)
                #pragma unroll
                for (int nt = 0; nt < 8; nt++) {
                    const uint32_t* bh = &bH[nt >> 1][(nt & 1) * 2];
                    const uint32_t* bl = &bL[nt >> 1][(nt & 1) * 2];
                    mma_bf16(c[mt][nt], aH[mt], bh);
                    mma_bf16(c[mt][nt], aH[mt], bl);
                    mma_bf16(c[mt][nt], aL[mt], bh);
                }
        }

        if (ki + 2 < 32) stage(ki + 2, (ki + 2) % 3);
    }

    if (MODE == 1) {
        #pragma unroll
        for (int mt = 0; mt < 2; mt++) {
            int r0 = brow + wm * 32 + mt * 16 + (lane >> 2);
            #pragma unroll
            for (int nt = 0; nt < 8; nt++) {
                int cc = bcol + wn * 64 + nt * 8 + (t4 << 1);
                float2 v0; v0.x = c[mt][nt][0]; v0.y = c[mt][nt][1];
                float2 v1; v1.x = c[mt][nt][2]; v1.y = c[mt][nt][3];
                *(float2*)(Cout + r0 * 1024 + cc)       = v0;
                *(float2*)(Cout + (r0 + 8) * 1024 + cc) = v1;
            }
        }
    } else {
        int region = (bcol < 1024) ? 0 : (bcol < 1280 ? 1 : 2);
        #pragma unroll
        for (int mt = 0; mt < 2; mt++) {
            int r0 = brow + wm * 32 + mt * 16 + (lane >> 2);
            int r1 = r0 + 8;
            int b0 = r0 >> 11, t0 = r0 & 2047;
            int b1 = r1 >> 11, t1 = r1 & 2047;
            if (region == 2) {
                int colb = bcol - 1280 + wn * 64;
                int h = colb >> 6;
                #pragma unroll
                for (int nt = 0; nt < 8; nt++) {
                    int d = nt * 8 + (t4 << 1);
                    int i0 = ((b0 * 4 + h) * 2048 + t0) * 64 + d;
                    int i1 = ((b1 * 4 + h) * 2048 + t1) * 64 + d;
                    store_h16(g_vh, i0, c[mt][nt][0], c[mt][nt][1]);
                    store_h16(g_vh, i1, c[mt][nt][2], c[mt][nt][3]);
                }
            } else {
                int colb = (region == 0) ? bcol + wn * 64 : bcol - 1024 + wn * 64;
                int h = colb >> 6;
                __nv_bfloat16* H = (region == 0) ? g_qh : g_kh;
                __nv_bfloat16* L = (region == 0) ? g_ql : g_kl;
                int nh   = (region == 0) ? 16 : 4;
                float sc = (region == 0) ? SOFTMAX_SCALE : 1.f;
                #pragma unroll
                for (int nt = 0; nt < 4; nt++) {
                    int d = nt * 8 + (t4 << 1);
                    float2 cc0 = *(const float2*)(cosb + t0 * 32 + d);
                    float2 ss0 = *(const float2*)(sinb + t0 * 32 + d);
                    float2 cc1 = *(const float2*)(cosb + t1 * 32 + d);
                    float2 ss1 = *(const float2*)(sinb + t1 * 32 + d);
                    float x1a = c[mt][nt][0],     x1b = c[mt][nt][1];
                    float x2a = c[mt][nt + 4][0], x2b = c[mt][nt + 4][1];
                    int i0 = ((b0 * nh + h) * 2048 + t0) * 64 + d;
                    store_hl(H, L, i0,      (x1a*cc0.x - x2a*ss0.x)*sc, (x1b*cc0.y - x2b*ss0.y)*sc);
                    store_hl(H, L, i0 + 32, (x2a*cc0.x + x1a*ss0.x)*sc, (x2b*cc0.y + x1b*ss0.y)*sc);
                    x1a = c[mt][nt][2];     x1b = c[mt][nt][3];
                    x2a = c[mt][nt + 4][2]; x2b = c[mt][nt + 4][3];
                    int i1 = ((b1 * nh + h) * 2048 + t1) * 64 + d;
                    store_hl(H, L, i1,      (x1a*cc1.x - x2a*ss1.x)*sc, (x1b*cc1.y - x2b*ss1.y)*sc);
                    store_hl(H, L, i1 + 32, (x2a*cc1.x + x1a*ss1.x)*sc, (x2b*cc1.y + x1b*ss1.y)*sc);
                }
            }
        }
    }
}

// ---------------------------------------------------------------------------
// MMA flash attention: QK bf16x3, P fp16, V single fp16 (1 MMA per frag).
// XOR-swizzled 64x64 tiles (8 KB each); 3 arrays (Kh,Kl,Vh) per stage = 24 KB.
// 3-stage ring, ONE __syncthreads per tile, 3 CTAs/SM (221 KB smem).
// Block = 128 (4 warps), 64 q rows per CTA. grid = (32, 32), heavy first.
// ---------------------------------------------------------------------------
__global__ void __launch_bounds__(128, 3) attn_kernel()
{
    extern __shared__ __align__(16) __nv_bfloat16 smem[];
    const uint32_t sbase = smem_u32(smem);

    const int tid  = threadIdx.x;
    const int lane = tid & 31;
    const int warp = tid >> 5;          // 0..3
    const int g    = lane >> 2;
    const int t4   = lane & 3;
    const int bh   = blockIdx.y;
    const int b    = bh >> 4, hh = bh & 15;
    const int kh   = hh >> 2;
    const int qt   = (int)gridDim.x - 1 - (int)blockIdx.x;   // heavy first

    const int r0 = qt * 64 + warp * 16 + g;
    const int r1 = r0 + 8;
    const int warp_min_row = qt * 64 + warp * 16;

    uint32_t qh[4][4], ql[4][4];
    {
        const __nv_bfloat16* q0h = g_qh + (bh * 2048 + r0) * 64;
        const __nv_bfloat16* q1h = g_qh + (bh * 2048 + r1) * 64;
        const __nv_bfloat16* q0l = g_ql + (bh * 2048 + r0) * 64;
        const __nv_bfloat16* q1l = g_ql + (bh * 2048 + r1) * 64;
        #pragma unroll
        for (int ks = 0; ks < 4; ks++) {
            int cb = ks * 16 + (t4 << 1);
            qh[ks][0] = *(const uint32_t*)(q0h + cb);
            qh[ks][1] = *(const uint32_t*)(q1h + cb);
            qh[ks][2] = *(const uint32_t*)(q0h + cb + 8);
            qh[ks][3] = *(const uint32_t*)(q1h + cb + 8);
            ql[ks][0] = *(const uint32_t*)(q0l + cb);
            ql[ks][1] = *(const uint32_t*)(q1l + cb);
            ql[ks][2] = *(const uint32_t*)(q0l + cb + 8);
            ql[ks][3] = *(const uint32_t*)(q1l + cb + 8);
        }
    }

    float o[8][4];
    #pragma unroll
    for (int nt = 0; nt < 8; nt++)
        #pragma unroll
        for (int i = 0; i < 4; i++) o[nt][i] = 0.f;
    float m0 = -1e30f, m1 = -1e30f, l0 = 0.f, l1 = 0.f;

    const __nv_bfloat16* src0 = g_kh + ((b * 4 + kh) * 2048) * 64;
    const __nv_bfloat16* src1 = g_kl + ((b * 4 + kh) * 2048) * 64;
    const __half*        src2 = g_vh + ((b * 4 + kh) * 2048) * 64;

    const int ntiles = qt + 1;

    // stage one K/V tile: 3 arrays x 512 16B chunks, XOR swizzle
    auto stage = [&](int kt, int buf) {
        uint32_t base = sbase + (uint32_t)buf * 24576u;
        #pragma unroll
        for (int i = 0; i < 4; i++) {
            int u = tid + i * 128;          // 0..511
            int row = u >> 3, ch = u & 7;
            uint32_t sw = (uint32_t)(row * 128) + (uint32_t)((ch ^ (row & 7)) << 4);
            cpa16(base +          sw, src0 + kt * 4096 + u * 8);
            cpa16(base +  8192u + sw, src1 + kt * 4096 + u * 8);
            cpa16(base + 16384u + sw, src2 + kt * 4096 + u * 8);
        }
        asm volatile("cp.async.commit_group;\n" ::: "memory");
    };

    stage(0, 0);
    if (ntiles > 1) stage(1, 1);

    for (int kt = 0; kt < ntiles; kt++) {
        int buf = kt % 3;
        if (kt == ntiles - 1) {
            asm volatile("cp.async.wait_group 0;\n" ::: "memory");
        } else {
            asm volatile("cp.async.wait_group 1;\n" ::: "memory");
        }
        __syncthreads();

        {
            const uint32_t bKh = sbase + (uint32_t)buf * 24576u;
            const uint32_t bKl = bKh + 8192u;
            const uint32_t bVh = bKh + 16384u;

            float s[8][4];
            #pragma unroll
            for (int nt = 0; nt < 8; nt++)
                #pragma unroll
                for (int i = 0; i < 4; i++) s[nt][i] = 0.f;

            #pragma unroll
            for (int ks = 0; ks < 4; ks++) {
                uint32_t kbh[4][4], kbl[4][4];
                #pragma unroll
                for (int pr = 0; pr < 4; pr++) {
                    int n_idx = pr * 16 + (lane & 7) + ((lane >> 4) << 3);
                    int chv   = 2 * ks + ((lane >> 3) & 1);       // 16B chunk col
                    uint32_t off = (uint32_t)(n_idx * 128)
                                 + (uint32_t)((chv ^ (n_idx & 7)) << 4);
                    ldmx4(kbh[pr], bKh + off);
                    ldmx4(kbl[pr], bKl + off);
                }
                #pragma unroll
                for (int pr = 0; pr < 4; pr++)
                    #pragma unroll
                    for (int sub = 0; sub < 2; sub++) {
                        float* sc = s[pr * 2 + sub];
                        mma_bf16(sc, qh[ks], &kbh[pr][sub * 2]);
                        mma_bf16(sc, qh[ks], &kbl[pr][sub * 2]);
                        mma_bf16(sc, ql[ks], &kbh[pr][sub * 2]);
                    }
            }

            if (kt * 64 + 63 > warp_min_row) {
                #pragma unroll
                for (int nt = 0; nt < 8; nt++) {
                    int c0 = kt * 64 + nt * 8 + (t4 << 1);
                    if (c0     > r0) s[nt][0] = -1e30f;
                    if (c0 + 1 > r0) s[nt][1] = -1e30f;
                    if (c0     > r1) s[nt][2] = -1e30f;
                    if (c0 + 1 > r1) s[nt][3] = -1e30f;
                }
            }

            float t0 = -1e30f, t1 = -1e30f;
            #pragma unroll
            for (int nt = 0; nt < 8; nt++) {
                t0 = fmaxf(t0, fmaxf(s[nt][0], s[nt][1]));
                t1 = fmaxf(t1, fmaxf(s[nt][2], s[nt][3]));
            }
            t0 = fmaxf(t0, __shfl_xor_sync(0xffffffffu, t0, 1));
            t0 = fmaxf(t0, __shfl_xor_sync(0xffffffffu, t0, 2));
            t1 = fmaxf(t1, __shfl_xor_sync(0xffffffffu, t1, 1));
            t1 = fmaxf(t1, __shfl_xor_sync(0xffffffffu, t1, 2));

            float m0n = fmaxf(m0, t0), m1n = fmaxf(m1, t1);
            float c0f = ex2(m0 - m0n), c1f = ex2(m1 - m1n);
            m0 = m0n; m1 = m1n;

            float sum0 = 0.f, sum1 = 0.f;
            #pragma unroll
            for (int nt = 0; nt < 8; nt++) {
                float p0 = ex2(s[nt][0] - m0);
                float p1 = ex2(s[nt][1] - m0);
                float p2 = ex2(s[nt][2] - m1);
                float p3 = ex2(s[nt][3] - m1);
                sum0 += p0 + p1; sum1 += p2 + p3;
                s[nt][0] = p0; s[nt][1] = p1; s[nt][2] = p2; s[nt][3] = p3;
            }
            l0 = l0 * c0f + sum0;
            l1 = l1 * c1f + sum1;
            #pragma unroll
            for (int nt = 0; nt < 8; nt++) {
                o[nt][0] *= c0f; o[nt][1] *= c0f;
                o[nt][2] *= c1f; o[nt][3] *= c1f;
            }

            // ---- O += P V (P fp16, V single fp16 -> 1 MMA per frag) ----
            #pragma unroll
            for (int ks = 0; ks < 4; ks++) {
                uint32_t aP[4];
                aP[0] = pack_f16x2(s[2*ks][0],   s[2*ks][1]);
                aP[1] = pack_f16x2(s[2*ks][2],   s[2*ks][3]);
                aP[2] = pack_f16x2(s[2*ks+1][0], s[2*ks+1][1]);
                aP[3] = pack_f16x2(s[2*ks+1][2], s[2*ks+1][3]);

                #pragma unroll
                for (int dp = 0; dp < 4; dp++) {
                    uint32_t vfh[4];
                    int row  = 16 * ks + (lane & 15);
                    int chv  = dp * 2 + (lane >> 4);
                    uint32_t off = (uint32_t)(row * 128)
                                 + (uint32_t)((chv ^ (row & 7)) << 4);
                    ldmx4t(vfh, bVh + off);
                    mma_f16(o[dp * 2 + 0], aP, &vfh[0]);
                    mma_f16(o[dp * 2 + 1], aP, &vfh[2]);
                }
            }
        }

        // 3-slot ring: slot (kt+2)%3 == (kt-1)%3; all warps have passed this
        // iteration's barrier, so the previous iteration's slot is free.
        if (kt + 2 < ntiles) stage(kt + 2, (kt + 2) % 3);
    }

    l0 += __shfl_xor_sync(0xffffffffu, l0, 1);
    l0 += __shfl_xor_sync(0xffffffffu, l0, 2);
    l1 += __shfl_xor_sync(0xffffffffu, l1, 1);
    l1 += __shfl_xor_sync(0xffffffffu, l1, 2);
    float inv0 = 1.f / l0, inv1 = 1.f / l1;

    int y0 = (b * 2048 + r0) * 1024 + hh * 64;
    int y1 = (b * 2048 + r1) * 1024 + hh * 64;
    #pragma unroll
    for (int nt = 0; nt < 8; nt++) {
        int d = nt * 8 + (t4 << 1);
        store_hl(g_yh, g_yl, y0 + d, o[nt][0] * inv0, o[nt][1] * inv0);
        store_hl(g_yh, g_yl, y1 + d, o[nt][2] * inv1, o[nt][3] * inv1);
    }
}

// ---------------------------------------------------------------------------
// Launch: x, cos, sin, Wq, Wk, Wv, Wo. out = f32 [B,T,C].
// ---------------------------------------------------------------------------
extern "C" void kernel_launch(void* const* d_in, const int* in_sizes, int n_in,
                              void* d_out, int out_size)
{
    const float* x    = (const float*)d_in[0];
    const float* cosb = (const float*)d_in[1];
    const float* sinb = (const float*)d_in[2];
    const float* Wq   = (const float*)d_in[3];
    const float* Wk   = (const float*)d_in[4];
    const float* Wv   = (const float*)d_in[5];
    const float* Wo   = (const float*)d_in[6];
    float* out = (float*)d_out;

    static bool attr_set = false;
    if (!attr_set) {
        cudaFuncSetAttribute(attn_kernel,
                             cudaFuncAttributeMaxDynamicSharedMemorySize, 73728);
        cudaFuncSetAttribute(gemm_bf16<0>,
                             cudaFuncAttributeMaxDynamicSharedMemorySize, 113664);
        cudaFuncSetAttribute(gemm_bf16<1>,
                             cudaFuncAttributeMaxDynamicSharedMemorySize, 113664);
        attr_set = true;
    }

    // 0. one-shot fp32 -> bf16 hi/lo conversions
    cvt_x<<<4096, 256>>>(x);
    cvt_qkvw<<<1536, 256>>>(Wq, Wk, Wv);
    cvt_wo<<<1024, 256>>>(Wo);

    // 1. fused QKV projection + RoPE + scale (bf16x3, 3-stage ring, 2 CTAs/SM)
    gemm_bf16<0><<<dim3(12, 32), 256, 113664>>>(cosb, sinb, nullptr);

    // 2. causal flash attention (QK bf16x3, PV fp16 x1; 3-stage ring, 3 CTAs/SM)
    attn_kernel<<<dim3(32, 32), 128, 73728>>>();

    // 3. output projection (3-stage ring, 2 CTAs/SM)
    gemm_bf16<1><<<dim3(8, 32), 256, 113664>>>(nullptr, nullptr, out);
}

// round 12
// speedup vs baseline: 2.6906x; 1.9222x over previous
#include <cuda_runtime.h>
#include <cuda_bf16.h>
#include <cuda_fp16.h>
#include <cstdint>

// ---------------------------------------------------------------------------
// GQA: B=2, T=2048, C=1024, H=16 q-heads, KVH=4 kv-heads, D=64, causal, RoPE
// FULL single-fp16 pipeline (fp32 accumulation everywhere). Calibrated error
// model: each fp16 operand rounding adds ~2e-4 norm-relative in quadrature;
// total ~4.5e-4 << 1e-3. HMMA only (tcgen05 unavailable on this toolchain).
// ---------------------------------------------------------------------------

__device__ __align__(16) __half g_x[4194304];
__device__ __align__(16) __half g_wqkv[1572864];
__device__ __align__(16) __half g_wo[1048576];
__device__ __align__(16) __half g_q[4194304];
__device__ __align__(16) __half g_k[1048576];
__device__ __align__(16) __half g_v[1048576];
__device__ __align__(16) __half g_y[4194304];

// ---------------------------------------------------------------------------
// helpers
// ---------------------------------------------------------------------------
__device__ __forceinline__ uint32_t smem_u32(const void* p) {
    return (uint32_t)__cvta_generic_to_shared(p);
}
__device__ __forceinline__ void ldmx4(uint32_t* r, uint32_t addr) {
    asm volatile("ldmatrix.sync.aligned.m8n8.x4.shared.b16 {%0,%1,%2,%3}, [%4];"
        : "=r"(r[0]), "=r"(r[1]), "=r"(r[2]), "=r"(r[3]) : "r"(addr));
}
__device__ __forceinline__ void ldmx4t(uint32_t* r, uint32_t addr) {
    asm volatile("ldmatrix.sync.aligned.m8n8.x4.trans.shared.b16 {%0,%1,%2,%3}, [%4];"
        : "=r"(r[0]), "=r"(r[1]), "=r"(r[2]), "=r"(r[3]) : "r"(addr));
}
__device__ __forceinline__ void mma_f16(float* c, const uint32_t* a, const uint32_t* b) {
    asm volatile(
        "mma.sync.aligned.m16n8k16.row.col.f32.f16.f16.f32 "
        "{%0,%1,%2,%3}, {%4,%5,%6,%7}, {%8,%9}, {%0,%1,%2,%3};\n"
        : "+f"(c[0]), "+f"(c[1]), "+f"(c[2]), "+f"(c[3])
        : "r"(a[0]), "r"(a[1]), "r"(a[2]), "r"(a[3]), "r"(b[0]), "r"(b[1]));
}
__device__ __forceinline__ float ex2(float x) {
    float r;
    asm("ex2.approx.f32 %0, %1;" : "=f"(r) : "f"(x));
    return r;
}
__device__ __forceinline__ void store_h16(__half* H, int idx, float a, float b) {
    __half2 hv = __floats2half2_rn(a, b);
    *(__half2*)(H + idx) = hv;
}
__device__ __forceinline__ uint32_t pack_f16x2(float a, float b) {
    __half2 h = __floats2half2_rn(a, b);
    return *(uint32_t*)&h;
}
__device__ __forceinline__ uint2 cvt4_f16(float4 v) {
    __half2 h0 = __floats2half2_rn(v.x, v.y);
    __half2 h1 = __floats2half2_rn(v.z, v.w);
    uint2 r; r.x = *(uint32_t*)&h0; r.y = *(uint32_t*)&h1;
    return r;
}
__device__ __forceinline__ void cpa16(uint32_t dst, const void* src) {
    asm volatile("cp.async.cg.shared.global [%0], [%1], 16;\n" :: "r"(dst), "l"(src));
}

#define SOFTMAX_SCALE (0.125f * 1.44269504088896f)  // 1/sqrt(64) * log2(e)

// ---------------------------------------------------------------------------
// Conversion kernels: fp32 -> fp16 (one-shot, memory-bound)
// ---------------------------------------------------------------------------
__global__ void cvt_x(const float* __restrict__ src) {
    int i = blockIdx.x * blockDim.x + threadIdx.x;        // < 1048576
    ((uint2*)g_x)[i] = cvt4_f16(((const float4*)src)[i]);
}
__global__ void cvt_wo(const float* __restrict__ src) {
    int i = blockIdx.x * blockDim.x + threadIdx.x;        // < 262144
    ((uint2*)g_wo)[i] = cvt4_f16(((const float4*)src)[i]);
}
__global__ void cvt_qkvw(const float* __restrict__ Wq,
                         const float* __restrict__ Wk,
                         const float* __restrict__ Wv) {
    int i = blockIdx.x * blockDim.x + threadIdx.x;        // < 393216
    int k = i / 384;
    int n = (i % 384) * 4;
    float4 v;
    if (n < 1024)      v = *(const float4*)(Wq + k * 1024 + n);
    else if (n < 1280) v = *(const float4*)(Wk + k * 256 + n - 1024);
    else               v = *(const float4*)(Wv + k * 256 + n - 1280);
    *(uint2*)(g_wqkv + k * 1536 + n) = cvt4_f16(v);
}

// ---------------------------------------------------------------------------
// fp16 GEMM (fp32 accum), 3-stage cp.async ring (ONE sync per slab), 2 CTAs/SM.
// Tile 128x128, BK=32, 8 warps (4x2), 2x8 m16n8k16 frags per warp, 1 MMA each.
// Stage = A(128x40 halves) + B(32x136 halves) = 18944 B; 3 stages = 56832 B.
// MODE 0: A=g_x, B=g_wqkv (ldn=1536); epilogue RoPE(+scale) -> g_q/g_k/g_v fp16
// MODE 1: A=g_y,  B=g_wo  (ldn=1024); epilogue fp32 -> Cout
// ---------------------------------------------------------------------------
template<int MODE>
__global__ void __launch_bounds__(256, 2) gemm_fp16(
    const float* __restrict__ cosb,
    const float* __restrict__ sinb,
    float* __restrict__ Cout)
{
    extern __shared__ __align__(16) __half sm[];
    const uint32_t sbase = smem_u32(sm);
    const int ldn = (MODE == 0) ? 1536 : 1024;

    const __half* A = (MODE == 0) ? g_x : g_y;
    const __half* B = (MODE == 0) ? g_wqkv : g_wo;

    const int tid  = threadIdx.x;
    const int lane = tid & 31;
    const int warp = tid >> 5;
    const int wm   = warp >> 1;
    const int wn   = warp & 1;
    const int brow = blockIdx.y * 128;
    const int bcol = blockIdx.x * 128;
    const int t4   = lane & 3;

    float c[2][8][4];
    #pragma unroll
    for (int mt = 0; mt < 2; mt++)
        #pragma unroll
        for (int nt = 0; nt < 8; nt++)
            #pragma unroll
            for (int i = 0; i < 4; i++) c[mt][nt][i] = 0.f;

    auto stage = [&](int ki, int buf) {
        int kb = ki * 32;
        uint32_t base = sbase + (uint32_t)buf * 18944u;
        #pragma unroll
        for (int i = 0; i < 2; i++) {
            int u   = tid + i * 256;          // 0..511
            int ar  = u >> 2, ac8 = (u & 3) << 3;
            cpa16(base + (uint32_t)(ar * 40 + ac8) * 2u,
                  A + (brow + ar) * 1024 + kb + ac8);
            int br2 = u >> 4, bc8 = (u & 15) << 3;
            cpa16(base + 10240u + (uint32_t)(br2 * 136 + bc8) * 2u,
                  B + (kb + br2) * ldn + bcol + bc8);
        }
        asm volatile("cp.async.commit_group;\n" ::: "memory");
    };

    stage(0, 0);
    stage(1, 1);

    for (int ki = 0; ki < 32; ki++) {
        int buf = ki % 3;
        if (ki == 31) {
            asm volatile("cp.async.wait_group 0;\n" ::: "memory");
        } else {
            asm volatile("cp.async.wait_group 1;\n" ::: "memory");
        }
        __syncthreads();

        uint32_t bA = sbase + (uint32_t)buf * 18944u;
        uint32_t bB = bA + 10240u;

        #pragma unroll
        for (int ks = 0; ks < 2; ks++) {
            uint32_t a[2][4], b[4][4];
            #pragma unroll
            for (int mt = 0; mt < 2; mt++) {
                uint32_t off = 2u * ((uint32_t)(wm * 32 + mt * 16 + (lane & 15)) * 40
                                     + ks * 16 + ((lane >> 4) << 3));
                ldmx4(a[mt], bA + off);
            }
            #pragma unroll
            for (int np = 0; np < 4; np++) {
                uint32_t off = 2u * ((uint32_t)(ks * 16 + (lane & 15)) * 136
                                     + wn * 64 + np * 16 + ((lane >> 4) << 3));
                ldmx4t(b[np], bB + off);
            }
            #pragma unroll
            for (int mt = 0; mt < 2; mt++)
                #pragma unroll
                for (int nt = 0; nt < 8; nt++)
                    mma_f16(c[mt][nt], a[mt], &b[nt >> 1][(nt & 1) * 2]);
        }

        if (ki + 2 < 32) stage(ki + 2, (ki + 2) % 3);
    }

    if (MODE == 1) {
        #pragma unroll
        for (int mt = 0; mt < 2; mt++) {
            int r0 = brow + wm * 32 + mt * 16 + (lane >> 2);
            #pragma unroll
            for (int nt = 0; nt < 8; nt++) {
                int cc = bcol + wn * 64 + nt * 8 + (t4 << 1);
                float2 v0; v0.x = c[mt][nt][0]; v0.y = c[mt][nt][1];
                float2 v1; v1.x = c[mt][nt][2]; v1.y = c[mt][nt][3];
                *(float2*)(Cout + r0 * 1024 + cc)       = v0;
                *(float2*)(Cout + (r0 + 8) * 1024 + cc) = v1;
            }
        }
    } else {
        int region = (bcol < 1024) ? 0 : (bcol < 1280 ? 1 : 2);
        #pragma unroll
        for (int mt = 0; mt < 2; mt++) {
            int r0 = brow + wm * 32 + mt * 16 + (lane >> 2);
            int r1 = r0 + 8;
            int b0 = r0 >> 11, t0 = r0 & 2047;
            int b1 = r1 >> 11, t1 = r1 & 2047;
            if (region == 2) {
                int colb = bcol - 1280 + wn * 64;
                int h = colb >> 6;
                #pragma unroll
                for (int nt = 0; nt < 8; nt++) {
                    int d = nt * 8 + (t4 << 1);
                    int i0 = ((b0 * 4 + h) * 2048 + t0) * 64 + d;
                    int i1 = ((b1 * 4 + h) * 2048 + t1) * 64 + d;
                    store_h16(g_v, i0, c[mt][nt][0], c[mt][nt][1]);
                    store_h16(g_v, i1, c[mt][nt][2], c[mt][nt][3]);
                }
            } else {
                int colb = (region == 0) ? bcol + wn * 64 : bcol - 1024 + wn * 64;
                int h = colb >> 6;
                __half* H = (region == 0) ? g_q : g_k;
                int nh   = (region == 0) ? 16 : 4;
                float sc = (region == 0) ? SOFTMAX_SCALE : 1.f;
                #pragma unroll
                for (int nt = 0; nt < 4; nt++) {
                    int d = nt * 8 + (t4 << 1);
                    float2 cc0 = *(const float2*)(cosb + t0 * 32 + d);
                    float2 ss0 = *(const float2*)(sinb + t0 * 32 + d);
                    float2 cc1 = *(const float2*)(cosb + t1 * 32 + d);
                    float2 ss1 = *(const float2*)(sinb + t1 * 32 + d);
                    float x1a = c[mt][nt][0],     x1b = c[mt][nt][1];
                    float x2a = c[mt][nt + 4][0], x2b = c[mt][nt + 4][1];
                    int i0 = ((b0 * nh + h) * 2048 + t0) * 64 + d;
                    store_h16(H, i0,      (x1a*cc0.x - x2a*ss0.x)*sc, (x1b*cc0.y - x2b*ss0.y)*sc);
                    store_h16(H, i0 + 32, (x2a*cc0.x + x1a*ss0.x)*sc, (x2b*cc0.y + x1b*ss0.y)*sc);
                    x1a = c[mt][nt][2];     x1b = c[mt][nt][3];
                    x2a = c[mt][nt + 4][2]; x2b = c[mt][nt + 4][3];
                    int i1 = ((b1 * nh + h) * 2048 + t1) * 64 + d;
                    store_h16(H, i1,      (x1a*cc1.x - x2a*ss1.x)*sc, (x1b*cc1.y - x2b*ss1.y)*sc);
                    store_h16(H, i1 + 32, (x2a*cc1.x + x1a*ss1.x)*sc, (x2b*cc1.y + x1b*ss1.y)*sc);
                }
            }
        }
    }
}

// ---------------------------------------------------------------------------
// MMA flash attention: ALL fp16 x1 (QK 1 MMA, PV 1 MMA per frag), fp32 accum.
// XOR-swizzled 64x64 tiles (8 KB each); stage = K + V = 16 KB.
// 3-stage ring, ONE __syncthreads per tile, 4 CTAs/SM (196.6 KB smem).
// Block = 128 (4 warps), 64 q rows per CTA. grid = (32, 32), heavy first.
// ---------------------------------------------------------------------------
__global__ void __launch_bounds__(128, 4) attn_kernel()
{
    extern __shared__ __align__(16) __half smem[];
    const uint32_t sbase = smem_u32(smem);

    const int tid  = threadIdx.x;
    const int lane = tid & 31;
    const int warp = tid >> 5;          // 0..3
    const int g    = lane >> 2;
    const int t4   = lane & 3;
    const int bh   = blockIdx.y;
    const int b    = bh >> 4, hh = bh & 15;
    const int kh   = hh >> 2;
    const int qt   = (int)gridDim.x - 1 - (int)blockIdx.x;   // heavy first

    const int r0 = qt * 64 + warp * 16 + g;
    const int r1 = r0 + 8;
    const int warp_min_row = qt * 64 + warp * 16;

    uint32_t qf[4][4];
    {
        const __half* q0 = g_q + (bh * 2048 + r0) * 64;
        const __half* q1 = g_q + (bh * 2048 + r1) * 64;
        #pragma unroll
        for (int ks = 0; ks < 4; ks++) {
            int cb = ks * 16 + (t4 << 1);
            qf[ks][0] = *(const uint32_t*)(q0 + cb);
            qf[ks][1] = *(const uint32_t*)(q1 + cb);
            qf[ks][2] = *(const uint32_t*)(q0 + cb + 8);
            qf[ks][3] = *(const uint32_t*)(q1 + cb + 8);
        }
    }

    float o[8][4];
    #pragma unroll
    for (int nt = 0; nt < 8; nt++)
        #pragma unroll
        for (int i = 0; i < 4; i++) o[nt][i] = 0.f;
    float m0 = -1e30f, m1 = -1e30f, l0 = 0.f, l1 = 0.f;

    const __half* srcK = g_k + ((b * 4 + kh) * 2048) * 64;
    const __half* srcV = g_v + ((b * 4 + kh) * 2048) * 64;

    const int ntiles = qt + 1;

    // stage one K/V tile: 2 arrays x 512 16B chunks, XOR swizzle
    auto stage = [&](int kt, int buf) {
        uint32_t base = sbase + (uint32_t)buf * 16384u;
        #pragma unroll
        for (int i = 0; i < 4; i++) {
            int u = tid + i * 128;          // 0..511
            int row = u >> 3, ch = u & 7;
            uint32_t sw = (uint32_t)(row * 128) + (uint32_t)((ch ^ (row & 7)) << 4);
            cpa16(base +          sw, srcK + kt * 4096 + u * 8);
            cpa16(base + 8192u  + sw, srcV + kt * 4096 + u * 8);
        }
        asm volatile("cp.async.commit_group;\n" ::: "memory");
    };

    stage(0, 0);
    if (ntiles > 1) stage(1, 1);

    for (int kt = 0; kt < ntiles; kt++) {
        int buf = kt % 3;
        if (kt == ntiles - 1) {
            asm volatile("cp.async.wait_group 0;\n" ::: "memory");
        } else {
            asm volatile("cp.async.wait_group 1;\n" ::: "memory");
        }
        __syncthreads();

        {
            const uint32_t bK = sbase + (uint32_t)buf * 16384u;
            const uint32_t bV = bK + 8192u;

            float s[8][4];
            #pragma unroll
            for (int nt = 0; nt < 8; nt++)
                #pragma unroll
                for (int i = 0; i < 4; i++) s[nt][i] = 0.f;

            #pragma unroll
            for (int ks = 0; ks < 4; ks++) {
                uint32_t kb[4][4];
                #pragma unroll
                for (int pr = 0; pr < 4; pr++) {
                    int n_idx = pr * 16 + (lane & 7) + ((lane >> 4) << 3);
                    int chv   = 2 * ks + ((lane >> 3) & 1);       // 16B chunk col
                    uint32_t off = (uint32_t)(n_idx * 128)
                                 + (uint32_t)((chv ^ (n_idx & 7)) << 4);
                    ldmx4(kb[pr], bK + off);
                }
                #pragma unroll
                for (int pr = 0; pr < 4; pr++)
                    #pragma unroll
                    for (int sub = 0; sub < 2; sub++)
                        mma_f16(s[pr * 2 + sub], qf[ks], &kb[pr][sub * 2]);
            }

            if (kt * 64 + 63 > warp_min_row) {
                #pragma unroll
                for (int nt = 0; nt < 8; nt++) {
                    int c0 = kt * 64 + nt * 8 + (t4 << 1);
                    if (c0     > r0) s[nt][0] = -1e30f;
                    if (c0 + 1 > r0) s[nt][1] = -1e30f;
                    if (c0     > r1) s[nt][2] = -1e30f;
                    if (c0 + 1 > r1) s[nt][3] = -1e30f;
                }
            }

            float t0 = -1e30f, t1 = -1e30f;
            #pragma unroll
            for (int nt = 0; nt < 8; nt++) {
                t0 = fmaxf(t0, fmaxf(s[nt][0], s[nt][1]));
                t1 = fmaxf(t1, fmaxf(s[nt][2], s[nt][3]));
            }
            t0 = fmaxf(t0, __shfl_xor_sync(0xffffffffu, t0, 1));
            t0 = fmaxf(t0, __shfl_xor_sync(0xffffffffu, t0, 2));
            t1 = fmaxf(t1, __shfl_xor_sync(0xffffffffu, t1, 1));
            t1 = fmaxf(t1, __shfl_xor_sync(0xffffffffu, t1, 2));

            float m0n = fmaxf(m0, t0), m1n = fmaxf(m1, t1);
            float c0f = ex2(m0 - m0n), c1f = ex2(m1 - m1n);
            m0 = m0n; m1 = m1n;

            float sum0 = 0.f, sum1 = 0.f;
            #pragma unroll
            for (int nt = 0; nt < 8; nt++) {
                float p0 = ex2(s[nt][0] - m0);
                float p1 = ex2(s[nt][1] - m0);
                float p2 = ex2(s[nt][2] - m1);
                float p3 = ex2(s[nt][3] - m1);
                sum0 += p0 + p1; sum1 += p2 + p3;
                s[nt][0] = p0; s[nt][1] = p1; s[nt][2] = p2; s[nt][3] = p3;
            }
            l0 = l0 * c0f + sum0;
            l1 = l1 * c1f + sum1;
            #pragma unroll
            for (int nt = 0; nt < 8; nt++) {
                o[nt][0] *= c0f; o[nt][1] *= c0f;
                o[nt][2] *= c1f; o[nt][3] *= c1f;
            }

            // ---- O += P V (P fp16, V fp16 -> 1 MMA per frag) ----
            #pragma unroll
            for (int ks = 0; ks < 4; ks++) {
                uint32_t aP[4];
                aP[0] = pack_f16x2(s[2*ks][0],   s[2*ks][1]);
                aP[1] = pack_f16x2(s[2*ks][2],   s[2*ks][3]);
                aP[2] = pack_f16x2(s[2*ks+1][0], s[2*ks+1][1]);
                aP[3] = pack_f16x2(s[2*ks+1][2], s[2*ks+1][3]);

                #pragma unroll
                for (int dp = 0; dp < 4; dp++) {
                    uint32_t vf[4];
                    int row  = 16 * ks + (lane & 15);
                    int chv  = dp * 2 + (lane >> 4);
                    uint32_t off = (uint32_t)(row * 128)
                                 + (uint32_t)((chv ^ (row & 7)) << 4);
                    ldmx4t(vf, bV + off);
                    mma_f16(o[dp * 2 + 0], aP, &vf[0]);
                    mma_f16(o[dp * 2 + 1], aP, &vf[2]);
                }
            }
        }

        // 3-slot ring: slot (kt+2)%3 == (kt-1)%3; all warps have passed this
        // iteration's barrier, so the previous iteration's slot is free.
        if (kt + 2 < ntiles) stage(kt + 2, (kt + 2) % 3);
    }

    l0 += __shfl_xor_sync(0xffffffffu, l0, 1);
    l0 += __shfl_xor_sync(0xffffffffu, l0, 2);
    l1 += __shfl_xor_sync(0xffffffffu, l1, 1);
    l1 += __shfl_xor_sync(0xffffffffu, l1, 2);
    float inv0 = 1.f / l0, inv1 = 1.f / l1;

    int y0 = (b * 2048 + r0) * 1024 + hh * 64;
    int y1 = (b * 2048 + r1) * 1024 + hh * 64;
    #pragma unroll
    for (int nt = 0; nt < 8; nt++) {
        int d = nt * 8 + (t4 << 1);
        store_h16(g_y, y0 + d, o[nt][0] * inv0, o[nt][1] * inv0);
        store_h16(g_y, y1 + d, o[nt][2] * inv1, o[nt][3] * inv1);
    }
}

// ---------------------------------------------------------------------------
// Launch: x, cos, sin, Wq, Wk, Wv, Wo. out = f32 [B,T,C].
// ---------------------------------------------------------------------------
extern "C" void kernel_launch(void* const* d_in, const int* in_sizes, int n_in,
                              void* d_out, int out_size)
{
    const float* x    = (const float*)d_in[0];
    const float* cosb = (const float*)d_in[1];
    const float* sinb = (const float*)d_in[2];
    const float* Wq   = (const float*)d_in[3];
    const float* Wk   = (const float*)d_in[4];
    const float* Wv   = (const float*)d_in[5];
    const float* Wo   = (const float*)d_in[6];
    float* out = (float*)d_out;

    static bool attr_set = false;
    if (!attr_set) {
        cudaFuncSetAttribute(attn_kernel,
                             cudaFuncAttributeMaxDynamicSharedMemorySize, 49152);
        cudaFuncSetAttribute(gemm_fp16<0>,
                             cudaFuncAttributeMaxDynamicSharedMemorySize, 56832);
        cudaFuncSetAttribute(gemm_fp16<1>,
                             cudaFuncAttributeMaxDynamicSharedMemorySize, 56832);
        attr_set = true;
    }

    // 0. one-shot fp32 -> fp16 conversions
    cvt_x<<<4096, 256>>>(x);
    cvt_qkvw<<<1536, 256>>>(Wq, Wk, Wv);
    cvt_wo<<<1024, 256>>>(Wo);

    // 1. fused QKV projection + RoPE + scale (fp16 x1, 3-stage ring, 2 CTAs/SM)
    gemm_fp16<0><<<dim3(12, 32), 256, 56832>>>(cosb, sinb, nullptr);

    // 2. causal flash attention (fp16 x1 QK + PV; 3-stage ring, 4 CTAs/SM)
    attn_kernel<<<dim3(32, 32), 128, 49152>>>();

    // 3. output projection (fp16 x1, 3-stage ring, 2 CTAs/SM)
    gemm_fp16<1><<<dim3(8, 32), 256, 56832>>>(nullptr, nullptr, out);
}

// round 13
// speedup vs baseline: 2.7347x; 1.0164x over previous
#include <cuda_runtime.h>
#include <cuda_bf16.h>
#include <cuda_fp16.h>
#include <cstdint>

// ---------------------------------------------------------------------------
// GQA: B=2, T=2048, C=1024, H=16 q-heads, KVH=4 kv-heads, D=64, causal, RoPE
// Full single-fp16 pipeline (fp32 accum). Q/K head-dims stored PERMUTED in
// interleaved rope-pair order (2j <-> d=j, 2j+1 <-> d=j+32): QK^T invariant,
// RoPE becomes per-thread register math in any tile shape.
// ---------------------------------------------------------------------------

__device__ __align__(16) __half g_x[4194304];
__device__ __align__(16) __half g_wqkv[1572864];   // [K=1024][N=1536], Q/K cols permuted
__device__ __align__(16) __half g_wo[1048576];
__device__ __align__(16) __half g_q[4194304];      // permuted head-dim
__device__ __align__(16) __half g_k[1048576];      // permuted head-dim
__device__ __align__(16) __half g_v[1048576];
__device__ __align__(16) __half g_y[4194304];

// ---------------------------------------------------------------------------
// helpers
// ---------------------------------------------------------------------------
__device__ __forceinline__ uint32_t smem_u32(const void* p) {
    return (uint32_t)__cvta_generic_to_shared(p);
}
__device__ __forceinline__ void ldmx4(uint32_t* r, uint32_t addr) {
    asm volatile("ldmatrix.sync.aligned.m8n8.x4.shared.b16 {%0,%1,%2,%3}, [%4];"
        : "=r"(r[0]), "=r"(r[1]), "=r"(r[2]), "=r"(r[3]) : "r"(addr));
}
__device__ __forceinline__ void ldmx4t(uint32_t* r, uint32_t addr) {
    asm volatile("ldmatrix.sync.aligned.m8n8.x4.trans.shared.b16 {%0,%1,%2,%3}, [%4];"
        : "=r"(r[0]), "=r"(r[1]), "=r"(r[2]), "=r"(r[3]) : "r"(addr));
}
__device__ __forceinline__ void mma_f16(float* c, const uint32_t* a, const uint32_t* b) {
    asm volatile(
        "mma.sync.aligned.m16n8k16.row.col.f32.f16.f16.f32 "
        "{%0,%1,%2,%3}, {%4,%5,%6,%7}, {%8,%9}, {%0,%1,%2,%3};\n"
        : "+f"(c[0]), "+f"(c[1]), "+f"(c[2]), "+f"(c[3])
        : "r"(a[0]), "r"(a[1]), "r"(a[2]), "r"(a[3]), "r"(b[0]), "r"(b[1]));
}
__device__ __forceinline__ float ex2(float x) {
    float r;
    asm("ex2.approx.f32 %0, %1;" : "=f"(r) : "f"(x));
    return r;
}
__device__ __forceinline__ void store_h16(__half* H, int idx, float a, float b) {
    __half2 hv = __floats2half2_rn(a, b);
    *(__half2*)(H + idx) = hv;
}
__device__ __forceinline__ uint32_t pack_f16x2(float a, float b) {
    __half2 h = __floats2half2_rn(a, b);
    return *(uint32_t*)&h;
}
__device__ __forceinline__ uint2 cvt4_f16(float4 v) {
    __half2 h0 = __floats2half2_rn(v.x, v.y);
    __half2 h1 = __floats2half2_rn(v.z, v.w);
    uint2 r; r.x = *(uint32_t*)&h0; r.y = *(uint32_t*)&h1;
    return r;
}
__device__ __forceinline__ void cpa16(uint32_t dst, const void* src) {
    asm volatile("cp.async.cg.shared.global [%0], [%1], 16;\n" :: "r"(dst), "l"(src));
}

#define SOFTMAX_SCALE (0.125f * 1.44269504088896f)  // 1/sqrt(64) * log2(e)

// ---------------------------------------------------------------------------
// Single merged conversion kernel (fp32 -> fp16, weights permuted for rope).
// blocks [0,4096): x | [4096,5632): wqkv | [5632,6656): wo
// ---------------------------------------------------------------------------
__global__ void cvt_all(const float* __restrict__ x,
                        const float* __restrict__ Wq,
                        const float* __restrict__ Wk,
                        const float* __restrict__ Wv,
                        const float* __restrict__ Wo)
{
    int blk = blockIdx.x;
    if (blk < 4096) {
        int i = blk * 256 + threadIdx.x;                 // < 1048576
        ((uint2*)g_x)[i] = cvt4_f16(((const float4*)x)[i]);
    } else if (blk < 5632) {
        int i = (blk - 4096) * 256 + threadIdx.x;        // < 393216
        int k  = i / 384;
        int n4 = (i % 384) * 4;                          // output col, %4 == 0
        float4 v;
        if (n4 < 1024) {                                 // Q: permuted gather
            int h = n4 >> 6, ch = n4 & 63, j = ch >> 1;
            const float* wr = Wq + k * 1024 + h * 64;
            v.x = wr[j];      v.y = wr[j + 32];
            v.z = wr[j + 1];  v.w = wr[j + 33];
        } else if (n4 < 1280) {                          // K: permuted gather
            int m = n4 - 1024;
            int h = m >> 6, ch = m & 63, j = ch >> 1;
            const float* wr = Wk + k * 256 + h * 64;
            v.x = wr[j];      v.y = wr[j + 32];
            v.z = wr[j + 1];  v.w = wr[j + 33];
        } else {                                         // V: straight
            v = *(const float4*)(Wv + k * 256 + n4 - 1280);
        }
        *(uint2*)(g_wqkv + k * 1536 + n4) = cvt4_f16(v);
    } else {
        int i = (blk - 5632) * 256 + threadIdx.x;        // < 262144
        ((uint2*)g_wo)[i] = cvt4_f16(((const float4*)Wo)[i]);
    }
}

// ---------------------------------------------------------------------------
// fp16 GEMM (fp32 accum), 3-stage cp.async ring (ONE sync/slab), 2 CTAs/SM.
// MODE 0: tile 128x192, grid 8x32 = 256 CTAs (SINGLE wave). A=g_x, B=g_wqkv.
//         Epilogue: rope-pair math per adjacent col pair (permuted layout),
//         scale on Q; writes g_q/g_k (permuted) and g_v fp16.
// MODE 1: tile 128x128, grid 8x32 = 256 CTAs. A=g_y, B=g_wo; fp32 -> Cout.
// Warp layout 4x2; warp tile 32x(96|64); frags 2m x (12|8)n, 1 MMA each.
// ---------------------------------------------------------------------------
template<int MODE>
__global__ void __launch_bounds__(256, 2) gemm_fp16(
    const float* __restrict__ cosb,
    const float* __restrict__ sinb,
    float* __restrict__ Cout)
{
    constexpr int NT     = (MODE == 0) ? 192 : 128;   // tile N
    constexpr int NWARP  = NT / 2;                     // per-warp N span (wn in 0..1)
    constexpr int NF     = NWARP / 8;                  // n-frags per warp (12|8)
    constexpr int BPITCH = NT + 8;                     // smem B pitch in halves
    constexpr int STAGE  = 128 * 40 * 2 + 32 * BPITCH * 2;  // bytes
    constexpr int BCH    = 32 * (NT / 8);              // B 16B-chunks per stage
    constexpr int ITERS  = (512 + BCH) / 256;
    const int ldn = (MODE == 0) ? 1536 : 1024;

    extern __shared__ __align__(16) __half sm[];
    const uint32_t sbase = smem_u32(sm);

    const __half* A = (MODE == 0) ? g_x : g_y;
    const __half* B = (MODE == 0) ? g_wqkv : g_wo;

    const int tid  = threadIdx.x;
    const int lane = tid & 31;
    const int warp = tid >> 5;
    const int wm   = warp >> 1;
    const int wn   = warp & 1;
    const int brow = blockIdx.y * 128;
    const int bcol = blockIdx.x * NT;
    const int t4   = lane & 3;

    float c[2][NF][4];
    #pragma unroll
    for (int mt = 0; mt < 2; mt++)
        #pragma unroll
        for (int nt = 0; nt < NF; nt++)
            #pragma unroll
            for (int i = 0; i < 4; i++) c[mt][nt][i] = 0.f;

    auto stage = [&](int ki, int buf) {
        int kb = ki * 32;
        uint32_t base = sbase + (uint32_t)(buf * STAGE);
        #pragma unroll
        for (int i = 0; i < ITERS; i++) {
            int u = tid + i * 256;
            if (u < 512) {
                int ar = u >> 2, ac8 = (u & 3) << 3;
                cpa16(base + (uint32_t)(ar * 40 + ac8) * 2u,
                      A + (brow + ar) * 1024 + kb + ac8);
            } else {
                int v = u - 512;
                int br2 = v / (NT / 8), bc8 = (v % (NT / 8)) * 8;
                cpa16(base + 10240u + (uint32_t)(br2 * BPITCH + bc8) * 2u,
                      B + (kb + br2) * ldn + bcol + bc8);
            }
        }
        asm volatile("cp.async.commit_group;\n" ::: "memory");
    };

    stage(0, 0);
    stage(1, 1);

    for (int ki = 0; ki < 32; ki++) {
        int buf = ki % 3;
        if (ki == 31) {
            asm volatile("cp.async.wait_group 0;\n" ::: "memory");
        } else {
            asm volatile("cp.async.wait_group 1;\n" ::: "memory");
        }
        __syncthreads();

        uint32_t bA = sbase + (uint32_t)(buf * STAGE);
        uint32_t bB = bA + 10240u;

        #pragma unroll
        for (int ks = 0; ks < 2; ks++) {
            uint32_t a[2][4];
            #pragma unroll
            for (int mt = 0; mt < 2; mt++) {
                uint32_t off = 2u * ((uint32_t)(wm * 32 + mt * 16 + (lane & 15)) * 40
                                     + ks * 16 + ((lane >> 4) << 3));
                ldmx4(a[mt], bA + off);
            }
            #pragma unroll
            for (int npp = 0; npp < NF / 2; npp++) {
                uint32_t b4[4];
                uint32_t off = 2u * ((uint32_t)(ks * 16 + (lane & 15)) * BPITCH
                                     + wn * NWARP + npp * 16 + ((lane >> 4) << 3));
                ldmx4t(b4, bB + off);
                #pragma unroll
                for (int sub = 0; sub < 2; sub++) {
                    mma_f16(c[0][npp * 2 + sub], a[0], &b4[sub * 2]);
                    mma_f16(c[1][npp * 2 + sub], a[1], &b4[sub * 2]);
                }
            }
        }

        if (ki + 2 < 32) stage(ki + 2, (ki + 2) % 3);
    }

    if (MODE == 1) {
        #pragma unroll
        for (int mt = 0; mt < 2; mt++) {
            int r0 = brow + wm * 32 + mt * 16 + (lane >> 2);
            #pragma unroll
            for (int nt = 0; nt < NF; nt++) {
                int cc = bcol + wn * NWARP + nt * 8 + (t4 << 1);
                float2 v0; v0.x = c[mt][nt][0]; v0.y = c[mt][nt][1];
                float2 v1; v1.x = c[mt][nt][2]; v1.y = c[mt][nt][3];
                *(float2*)(Cout + r0 * 1024 + cc)       = v0;
                *(float2*)(Cout + (r0 + 8) * 1024 + cc) = v1;
            }
        }
    } else {
        // permuted-rope epilogue: each frag pair (cc, cc+1) = (d=j, d=j+32)
        #pragma unroll
        for (int mt = 0; mt < 2; mt++) {
            int r0 = brow + wm * 32 + mt * 16 + (lane >> 2);
            int r1 = r0 + 8;
            int b0 = r0 >> 11, t0 = r0 & 2047;
            int b1 = r1 >> 11, t1 = r1 & 2047;
            #pragma unroll
            for (int nt = 0; nt < NF; nt++) {
                int cc = bcol + wn * NWARP + nt * 8 + (t4 << 1);
                if (cc < 1280) {                   // Q or K: rope on pair
                    bool isq = (cc < 1024);
                    int m  = isq ? cc : cc - 1024;
                    int h  = m >> 6, ch = m & 63, j = ch >> 1;
                    int nh = isq ? 16 : 4;
                    float sc = isq ? SOFTMAX_SCALE : 1.f;
                    __half* H = isq ? g_q : g_k;
                    float cs0 = cosb[t0 * 32 + j], sn0 = sinb[t0 * 32 + j];
                    float cs1 = cosb[t1 * 32 + j], sn1 = sinb[t1 * 32 + j];
                    float x1 = c[mt][nt][0], x2 = c[mt][nt][1];
                    store_h16(H, ((b0 * nh + h) * 2048 + t0) * 64 + ch,
                              (x1 * cs0 - x2 * sn0) * sc, (x2 * cs0 + x1 * sn0) * sc);
                    x1 = c[mt][nt][2]; x2 = c[mt][nt][3];
                    store_h16(H, ((b1 * nh + h) * 2048 + t1) * 64 + ch,
                              (x1 * cs1 - x2 * sn1) * sc, (x2 * cs1 + x1 * sn1) * sc);
                } else {                            // V: straight
                    int m = cc - 1280;
                    int h = m >> 6, d = m & 63;
                    store_h16(g_v, ((b0 * 4 + h) * 2048 + t0) * 64 + d,
                              c[mt][nt][0], c[mt][nt][1]);
                    store_h16(g_v, ((b1 * 4 + h) * 2048 + t1) * 64 + d,
                              c[mt][nt][2], c[mt][nt][3]);
                }
            }
        }
    }
}

// ---------------------------------------------------------------------------
// MMA flash attention: all fp16 x1 (QK 1 MMA, PV 1 MMA per frag), fp32 accum.
// XOR-swizzled 64x64 tiles (8 KB each); stage = K + V = 16 KB.
// 3-stage ring, ONE __syncthreads per tile, 4 CTAs/SM.
// Block = 128 (4 warps), 64 q rows per CTA. grid = (32, 32), heavy first.
// ---------------------------------------------------------------------------
__global__ void __launch_bounds__(128, 4) attn_kernel()
{
    extern __shared__ __align__(16) __half smem[];
    const uint32_t sbase = smem_u32(smem);

    const int tid  = threadIdx.x;
    const int lane = tid & 31;
    const int warp = tid >> 5;
    const int g    = lane >> 2;
    const int t4   = lane & 3;
    const int bh   = blockIdx.y;
    const int b    = bh >> 4, hh = bh & 15;
    const int kh   = hh >> 2;
    const int qt   = (int)gridDim.x - 1 - (int)blockIdx.x;   // heavy first

    const int r0 = qt * 64 + warp * 16 + g;
    const int r1 = r0 + 8;
    const int warp_min_row = qt * 64 + warp * 16;

    uint32_t qf[4][4];
    {
        const __half* q0 = g_q + (bh * 2048 + r0) * 64;
        const __half* q1 = g_q + (bh * 2048 + r1) * 64;
        #pragma unroll
        for (int ks = 0; ks < 4; ks++) {
            int cb = ks * 16 + (t4 << 1);
            qf[ks][0] = *(const uint32_t*)(q0 + cb);
            qf[ks][1] = *(const uint32_t*)(q1 + cb);
            qf[ks][2] = *(const uint32_t*)(q0 + cb + 8);
            qf[ks][3] = *(const uint32_t*)(q1 + cb + 8);
        }
    }

    float o[8][4];
    #pragma unroll
    for (int nt = 0; nt < 8; nt++)
        #pragma unroll
        for (int i = 0; i < 4; i++) o[nt][i] = 0.f;
    float m0 = -1e30f, m1 = -1e30f, l0 = 0.f, l1 = 0.f;

    const __half* srcK = g_k + ((b * 4 + kh) * 2048) * 64;
    const __half* srcV = g_v + ((b * 4 + kh) * 2048) * 64;

    const int ntiles = qt + 1;

    auto stage = [&](int kt, int buf) {
        uint32_t base = sbase + (uint32_t)buf * 16384u;
        #pragma unroll
        for (int i = 0; i < 4; i++) {
            int u = tid + i * 128;
            int row = u >> 3, ch = u & 7;
            uint32_t sw = (uint32_t)(row * 128) + (uint32_t)((ch ^ (row & 7)) << 4);
            cpa16(base +          sw, srcK + kt * 4096 + u * 8);
            cpa16(base + 8192u  + sw, srcV + kt * 4096 + u * 8);
        }
        asm volatile("cp.async.commit_group;\n" ::: "memory");
    };

    stage(0, 0);
    if (ntiles > 1) stage(1, 1);

    for (int kt = 0; kt < ntiles; kt++) {
        int buf = kt % 3;
        if (kt == ntiles - 1) {
            asm volatile("cp.async.wait_group 0;\n" ::: "memory");
        } else {
            asm volatile("cp.async.wait_group 1;\n" ::: "memory");
        }
        __syncthreads();

        {
            const uint32_t bK = sbase + (uint32_t)buf * 16384u;
            const uint32_t bV = bK + 8192u;

            float s[8][4];
            #pragma unroll
            for (int nt = 0; nt < 8; nt++)
                #pragma unroll
                for (int i = 0; i < 4; i++) s[nt][i] = 0.f;

            #pragma unroll
            for (int ks = 0; ks < 4; ks++) {
                uint32_t kb[4][4];
                #pragma unroll
                for (int pr = 0; pr < 4; pr++) {
                    int n_idx = pr * 16 + (lane & 7) + ((lane >> 4) << 3);
                    int chv   = 2 * ks + ((lane >> 3) & 1);
                    uint32_t off = (uint32_t)(n_idx * 128)
                                 + (uint32_t)((chv ^ (n_idx & 7)) << 4);
                    ldmx4(kb[pr], bK + off);
                }
                #pragma unroll
                for (int pr = 0; pr < 4; pr++)
                    #pragma unroll
                    for (int sub = 0; sub < 2; sub++)
                        mma_f16(s[pr * 2 + sub], qf[ks], &kb[pr][sub * 2]);
            }

            if (kt * 64 + 63 > warp_min_row) {
                #pragma unroll
                for (int nt = 0; nt < 8; nt++) {
                    int c0 = kt * 64 + nt * 8 + (t4 << 1);
                    if (c0     > r0) s[nt][0] = -1e30f;
                    if (c0 + 1 > r0) s[nt][1] = -1e30f;
                    if (c0     > r1) s[nt][2] = -1e30f;
                    if (c0 + 1 > r1) s[nt][3] = -1e30f;
                }
            }

            float t0 = -1e30f, t1 = -1e30f;
            #pragma unroll
            for (int nt = 0; nt < 8; nt++) {
                t0 = fmaxf(t0, fmaxf(s[nt][0], s[nt][1]));
                t1 = fmaxf(t1, fmaxf(s[nt][2], s[nt][3]));
            }
            t0 = fmaxf(t0, __shfl_xor_sync(0xffffffffu, t0, 1));
            t0 = fmaxf(t0, __shfl_xor_sync(0xffffffffu, t0, 2));
            t1 = fmaxf(t1, __shfl_xor_sync(0xffffffffu, t1, 1));
            t1 = fmaxf(t1, __shfl_xor_sync(0xffffffffu, t1, 2));

            float m0n = fmaxf(m0, t0), m1n = fmaxf(m1, t1);
            float c0f = ex2(m0 - m0n), c1f = ex2(m1 - m1n);
            m0 = m0n; m1 = m1n;

            float sum0 = 0.f, sum1 = 0.f;
            #pragma unroll
            for (int nt = 0; nt < 8; nt++) {
                float p0 = ex2(s[nt][0] - m0);
                float p1 = ex2(s[nt][1] - m0);
                float p2 = ex2(s[nt][2] - m1);
                float p3 = ex2(s[nt][3] - m1);
                sum0 += p0 + p1; sum1 += p2 + p3;
                s[nt][0] = p0; s[nt][1] = p1; s[nt][2] = p2; s[nt][3] = p3;
            }
            l0 = l0 * c0f + sum0;
            l1 = l1 * c1f + sum1;
            #pragma unroll
            for (int nt = 0; nt < 8; nt++) {
                o[nt][0] *= c0f; o[nt][1] *= c0f;
                o[nt][2] *= c1f; o[nt][3] *= c1f;
            }

            #pragma unroll
            for (int ks = 0; ks < 4; ks++) {
                uint32_t aP[4];
                aP[0] = pack_f16x2(s[2*ks][0],   s[2*ks][1]);
                aP[1] = pack_f16x2(s[2*ks][2],   s[2*ks][3]);
                aP[2] = pack_f16x2(s[2*ks+1][0], s[2*ks+1][1]);
                aP[3] = pack_f16x2(s[2*ks+1][2], s[2*ks+1][3]);

                #pragma unroll
                for (int dp = 0; dp < 4; dp++) {
                    uint32_t vf[4];
                    int row  = 16 * ks + (lane & 15);
                    int chv  = dp * 2 + (lane >> 4);
                    uint32_t off = (uint32_t)(row * 128)
                                 + (uint32_t)((chv ^ (row & 7)) << 4);
                    ldmx4t(vf, bV + off);
                    mma_f16(o[dp * 2 + 0], aP, &vf[0]);
                    mma_f16(o[dp * 2 + 1], aP, &vf[2]);
                }
            }
        }

        if (kt + 2 < ntiles) stage(kt + 2, (kt + 2) % 3);
    }

    l0 += __shfl_xor_sync(0xffffffffu, l0, 1);
    l0 += __shfl_xor_sync(0xffffffffu, l0, 2);
    l1 += __shfl_xor_sync(0xffffffffu, l1, 1);
    l1 += __shfl_xor_sync(0xffffffffu, l1, 2);
    float inv0 = 1.f / l0, inv1 = 1.f / l1;

    int y0 = (b * 2048 + r0) * 1024 + hh * 64;
    int y1 = (b * 2048 + r1) * 1024 + hh * 64;
    #pragma unroll
    for (int nt = 0; nt < 8; nt++) {
        int d = nt * 8 + (t4 << 1);
        store_h16(g_y, y0 + d, o[nt][0] * inv0, o[nt][1] * inv0);
        store_h16(g_y, y1 + d, o[nt][2] * inv1, o[nt][3] * inv1);
    }
}

// ---------------------------------------------------------------------------
// Launch: x, cos, sin, Wq, Wk, Wv, Wo. out = f32 [B,T,C].
// ---------------------------------------------------------------------------
extern "C" void kernel_launch(void* const* d_in, const int* in_sizes, int n_in,
                              void* d_out, int out_size)
{
    const float* x    = (const float*)d_in[0];
    const float* cosb = (const float*)d_in[1];
    const float* sinb = (const float*)d_in[2];
    const float* Wq   = (const float*)d_in[3];
    const float* Wk   = (const float*)d_in[4];
    const float* Wv   = (const float*)d_in[5];
    const float* Wo   = (const float*)d_in[6];
    float* out = (float*)d_out;

    static bool attr_set = false;
    if (!attr_set) {
        cudaFuncSetAttribute(attn_kernel,
                             cudaFuncAttributeMaxDynamicSharedMemorySize, 49152);
        cudaFuncSetAttribute(gemm_fp16<0>,
                             cudaFuncAttributeMaxDynamicSharedMemorySize, 69120);
        cudaFuncSetAttribute(gemm_fp16<1>,
                             cudaFuncAttributeMaxDynamicSharedMemorySize, 56832);
        attr_set = true;
    }

    // 0. one merged fp32 -> fp16 conversion (weights permuted for rope pairs)
    cvt_all<<<6656, 256>>>(x, Wq, Wk, Wv, Wo);

    // 1. fused QKV projection + RoPE + scale (fp16, tile 128x192, ONE wave)
    gemm_fp16<0><<<dim3(8, 32), 256, 69120>>>(cosb, sinb, nullptr);

    // 2. causal flash attention (fp16 x1; 3-stage ring, 4 CTAs/SM)
    attn_kernel<<<dim3(32, 32), 128, 49152>>>();

    // 3. output projection (fp16, tile 128x128, single wave)
    gemm_fp16<1><<<dim3(8, 32), 256, 56832>>>(nullptr, nullptr, out);
}